// round 3
// baseline (speedup 1.0000x reference)
#include <cuda_runtime.h>
#include <math.h>

// Problem sizes
constexpr int NS = 1024;   // sequence length
constexpr int NB = 64;     // batch
constexpr int NE = 512;    // embed dim
constexpr int NH = 512;    // hidden
constexpr int NH3 = 3 * NH;
constexpr int NV = 32000;  // vocab
constexpr int NCD = 48;    // CTAs per direction in recurrent kernel
constexpr int REC_THREADS = 256;
constexpr int REC_SMEM_FLOATS = 16384 /*W*/ + 32768 /*h*/ + 2048 /*pacc*/;
constexpr int REC_SMEM_BYTES = REC_SMEM_FLOATS * 4;  // 204800

// ----------------------------------------------------------------------------
// Device scratch (static; no runtime allocation allowed)
// ----------------------------------------------------------------------------
__device__ float g_Wp0[(size_t)NV * NH3];      // LN'd input projection table, fwd  (~196MB)
__device__ float g_Wp1[(size_t)NV * NH3];      // LN'd input projection table, bwd
__device__ float g_gru[(size_t)NS * NB * 2 * NH];  // concat GRU outputs (~256MB)
__device__ float g_hp[2][NB * NH3];            // per-step raw h-projection
__device__ float g_h[2][NB * NH];              // hidden state per direction
__device__ float g_stats[2][2][NB * 3 * 2];    // [parity][dir][b*6 + gate*2 + {sum,sumsq}]
__device__ unsigned g_cnt[2];
__device__ unsigned g_gen[2];

// ----------------------------------------------------------------------------
// Init: zero h and stats
// ----------------------------------------------------------------------------
__global__ void init_k() {
    int i = blockIdx.x * blockDim.x + threadIdx.x;
    if (i < 2 * NB * NH) ((float*)g_h)[i] = 0.f;
    if (i < 2 * 2 * NB * 3 * 2) ((float*)g_stats)[i] = 0.f;
}

// ----------------------------------------------------------------------------
// SGEMM: C[M,N] = A[M,K] * Bw[N,K]^T   (A,Bw,C row-major)
// EPI=1: C = tanh(C + bias[n])
// M%128==0, N%128==0, K%8==0 assumed.
// ----------------------------------------------------------------------------
template <int EPI>
__global__ void __launch_bounds__(256) sgemm_nt(
    const float* __restrict__ A, const float* __restrict__ Bw,
    float* __restrict__ C, int M, int N, int K, const float* __restrict__ bias)
{
    __shared__ float As[8][128];
    __shared__ float Bs[8][128];
    int tid = threadIdx.x;
    int lrow = tid >> 1;
    int lcol = (tid & 1) * 4;
    int tr = (tid >> 4) << 3;
    int tc = (tid & 15) << 3;
    const float* Ab = A + (size_t)blockIdx.y * 128 * K;
    const float* Bb = Bw + (size_t)blockIdx.x * 128 * K;

    float acc[8][8];
#pragma unroll
    for (int i = 0; i < 8; i++)
#pragma unroll
        for (int j = 0; j < 8; j++) acc[i][j] = 0.f;

    for (int k0 = 0; k0 < K; k0 += 8) {
        float4 av = *(const float4*)(Ab + (size_t)lrow * K + k0 + lcol);
        float4 bv = *(const float4*)(Bb + (size_t)lrow * K + k0 + lcol);
        As[lcol + 0][lrow] = av.x; As[lcol + 1][lrow] = av.y;
        As[lcol + 2][lrow] = av.z; As[lcol + 3][lrow] = av.w;
        Bs[lcol + 0][lrow] = bv.x; Bs[lcol + 1][lrow] = bv.y;
        Bs[lcol + 2][lrow] = bv.z; Bs[lcol + 3][lrow] = bv.w;
        __syncthreads();
#pragma unroll
        for (int k = 0; k < 8; k++) {
            float4 a0 = *(const float4*)&As[k][tr];
            float4 a1 = *(const float4*)&As[k][tr + 4];
            float4 b0 = *(const float4*)&Bs[k][tc];
            float4 b1 = *(const float4*)&Bs[k][tc + 4];
            float ra[8] = {a0.x, a0.y, a0.z, a0.w, a1.x, a1.y, a1.z, a1.w};
            float rb[8] = {b0.x, b0.y, b0.z, b0.w, b1.x, b1.y, b1.z, b1.w};
#pragma unroll
            for (int i = 0; i < 8; i++)
#pragma unroll
                for (int j = 0; j < 8; j++) acc[i][j] += ra[i] * rb[j];
        }
        __syncthreads();
    }

#pragma unroll
    for (int i = 0; i < 8; i++) {
        size_t crow = (size_t)(blockIdx.y * 128 + tr + i) * N + blockIdx.x * 128 + tc;
#pragma unroll
        for (int j = 0; j < 8; j += 4) {
            float4 v;
            v.x = acc[i][j]; v.y = acc[i][j + 1]; v.z = acc[i][j + 2]; v.w = acc[i][j + 3];
            if (EPI) {
                int nb = blockIdx.x * 128 + tc + j;
                v.x = tanhf(v.x + bias[nb]);
                v.y = tanhf(v.y + bias[nb + 1]);
                v.z = tanhf(v.z + bias[nb + 2]);
                v.w = tanhf(v.w + bias[nb + 3]);
            }
            *(float4*)(C + crow + j) = v;
        }
    }
}

// ----------------------------------------------------------------------------
// LayerNorm over vocab projection table rows (per gate), in place.
// Row index: [dir][tok][gate]. Token 0 is the padding row -> treat x as 0.
// out = (x - mu) * rsqrt(var + 1e-5) * g + be + b_ih
// ----------------------------------------------------------------------------
__global__ void ln_k(const float* __restrict__ gA, const float* __restrict__ beA,
                     const float* __restrict__ bA, const float* __restrict__ gB,
                     const float* __restrict__ beB, const float* __restrict__ bB)
{
    int row = blockIdx.x;               // 0 .. 2*NV*3-1
    int dir = row >= NV * 3;
    int rem = dir ? row - NV * 3 : row;
    int tok = rem / 3;
    int gate = rem - tok * 3;
    float* p = (dir ? g_Wp1 : g_Wp0) + (size_t)tok * NH3 + gate * NH;
    const float* gg = (dir ? gB : gA) + gate * NH;
    const float* be = (dir ? beB : beA) + gate * NH;
    const float* bi = (dir ? bB : bA) + gate * NH;
    int tid = threadIdx.x;              // 128 threads
    float4 v = ((float4*)p)[tid];
    if (tok == 0) { v.x = 0.f; v.y = 0.f; v.z = 0.f; v.w = 0.f; }
    float sum = v.x + v.y + v.z + v.w;
    float sq = v.x * v.x + v.y * v.y + v.z * v.z + v.w * v.w;
#pragma unroll
    for (int o = 16; o; o >>= 1) {
        sum += __shfl_xor_sync(0xffffffffu, sum, o);
        sq  += __shfl_xor_sync(0xffffffffu, sq, o);
    }
    __shared__ float ss[4], sc[4];
    int w = tid >> 5;
    if ((tid & 31) == 0) { ss[w] = sum; sc[w] = sq; }
    __syncthreads();
    sum = ss[0] + ss[1] + ss[2] + ss[3];
    sq  = sc[0] + sc[1] + sc[2] + sc[3];
    float mu = sum * (1.f / NH);
    float var = sq * (1.f / NH) - mu * mu;
    float rs = rsqrtf(var + 1e-5f);
    int j = tid * 4;
    v.x = (v.x - mu) * rs * gg[j]     + be[j]     + bi[j];
    v.y = (v.y - mu) * rs * gg[j + 1] + be[j + 1] + bi[j + 1];
    v.z = (v.z - mu) * rs * gg[j + 2] + be[j + 2] + bi[j + 2];
    v.w = (v.w - mu) * rs * gg[j + 3] + be[j + 3] + bi[j + 3];
    ((float4*)p)[tid] = v;
}

// ----------------------------------------------------------------------------
// Per-direction grid barrier (NCD CTAs per direction, all co-resident).
// ----------------------------------------------------------------------------
__device__ __forceinline__ void dirbar(int dir) {
    __threadfence();
    __syncthreads();
    if (threadIdx.x == 0) {
        unsigned g = atomicAdd(&g_gen[dir], 0u);
        if (atomicAdd(&g_cnt[dir], 1u) == NCD - 1) {
            atomicExch(&g_cnt[dir], 0u);
            __threadfence();
            atomicExch(&g_gen[dir], g + 1u);
        } else {
            while (atomicAdd(&g_gen[dir], 0u) == g) __nanosleep(128);
        }
        __threadfence();
    }
    __syncthreads();
}

// ----------------------------------------------------------------------------
// Persistent bidirectional GRU recurrence.
// Grid: 2*NCD CTAs (dir = blockIdx.x / NCD). CTA owns 32 contiguous hp columns.
// Shared: W_hh slice [32 cols x 512 K] resident for whole kernel (64KB),
//         h staged per step (128KB), cross-warp partial buffer (8KB).
// ----------------------------------------------------------------------------
__global__ void __launch_bounds__(REC_THREADS, 1) gru_rec(
    const int* __restrict__ src,
    const float* __restrict__ Whh_f, const float* __restrict__ Whh_b,
    const float* __restrict__ ghh_f, const float* __restrict__ behh_f,
    const float* __restrict__ bhh_f, const float* __restrict__ ghh_b,
    const float* __restrict__ behh_b, const float* __restrict__ bhh_b,
    float* __restrict__ dout)
{
    extern __shared__ float sm[];
    float4* wsv = (float4*)sm;               // 4096 float4  (W slice, [k4][c])
    float4* hsv = (float4*)(sm + 16384);     // 8192 float4  (h, [b][k4])
    float*  pacc = sm + 16384 + 32768;       // 2048 floats

    int dir = blockIdx.x / NCD;
    int cid = blockIdx.x - dir * NCD;
    int tid = threadIdx.x;
    int lane = tid & 31, wid = tid >> 5;

    const float* Whh  = dir ? Whh_b  : Whh_f;
    const float* ghh  = dir ? ghh_b  : ghh_f;
    const float* behh = dir ? behh_b : behh_f;
    const float* bhh  = dir ? bhh_b  : bhh_f;
    const float* Wp   = dir ? g_Wp1  : g_Wp0;
    float* hglob = g_h[dir];
    float* hpg = g_hp[dir];
    int gate = cid >> 4;                     // (cid*32)/512

    // Preload W_hh slice: rows [cid*32, cid*32+32), all 512 K, layout [k4][c].
    for (int idx = tid; idx < 4096; idx += REC_THREADS) {
        int k4 = idx >> 5, c = idx & 31;
        wsv[idx] = *(const float4*)(Whh + (size_t)(cid * 32 + c) * NH + k4 * 4);
    }

    int kh = wid >> 2;          // k-half: warps 0-3 -> [0,256), 4-7 -> [256,512)
    int bg = (wid & 3) * 16;    // batch group base
    int kb4 = kh * 64;

    for (int t = 0; t < NS; t++) {
        int s = dir ? (NS - 1 - t) : t;
        int par = t & 1;

        __syncthreads();
        // Stage h into shared (coalesced float4)
        for (int idx = tid; idx < 8192; idx += REC_THREADS)
            hsv[idx] = ((const float4*)hglob)[idx];
        __syncthreads();

        // Phase 1: hp[b][c] = sum_k h[b][k] * Whh[c][k] (c = cid*32 + lane)
        float acc[16];
#pragma unroll
        for (int i = 0; i < 16; i++) acc[i] = 0.f;
#pragma unroll 4
        for (int k4 = kb4; k4 < kb4 + 64; k4++) {
            float4 wv = wsv[(k4 << 5) + lane];
#pragma unroll
            for (int i = 0; i < 16; i++) {
                float4 hv = hsv[((bg + i) << 7) + k4];   // broadcast within warp
                acc[i] += wv.x * hv.x;
                acc[i] += wv.y * hv.y;
                acc[i] += wv.z * hv.z;
                acc[i] += wv.w * hv.w;
            }
        }
        if (kh) {
#pragma unroll
            for (int i = 0; i < 16; i++) pacc[((bg + i) << 5) + lane] = acc[i];
        }
        __syncthreads();
        if (!kh) {
#pragma unroll
            for (int i = 0; i < 16; i++) {
                float v = acc[i] + pacc[((bg + i) << 5) + lane];
                acc[i] = v;
                hpg[(bg + i) * NH3 + cid * 32 + lane] = v;
            }
            // per-(b,gate) partial LN stats
#pragma unroll
            for (int i = 0; i < 16; i++) {
                float sv = acc[i], sq = acc[i] * acc[i];
#pragma unroll
                for (int o = 16; o; o >>= 1) {
                    sv += __shfl_xor_sync(0xffffffffu, sv, o);
                    sq += __shfl_xor_sync(0xffffffffu, sq, o);
                }
                if (lane == 0) {
                    float* st = &g_stats[par][dir][(bg + i) * 6 + gate * 2];
                    atomicAdd(st, sv);
                    atomicAdd(st + 1, sq);
                }
            }
        }
        dirbar(dir);

        // Phase 2: LN(hp), gates, h update, write y
        const int* srow = src + s * NB;
        for (int e = cid * REC_THREADS + tid; e < NB * NH; e += NCD * REC_THREADS) {
            int b = e >> 9, j = e & (NH - 1);
            const float* st = &g_stats[par][dir][b * 6];
            float mu0 = st[0] * (1.f / NH);
            float rs0 = rsqrtf(st[1] * (1.f / NH) - mu0 * mu0 + 1e-5f);
            float mu1 = st[2] * (1.f / NH);
            float rs1 = rsqrtf(st[3] * (1.f / NH) - mu1 * mu1 + 1e-5f);
            float mu2 = st[4] * (1.f / NH);
            float rs2 = rsqrtf(st[5] * (1.f / NH) - mu2 * mu2 + 1e-5f);
            int base = b * NH3 + j;
            float hr = (hpg[base]          - mu0) * rs0 * ghh[j]          + behh[j]          + bhh[j];
            float hz = (hpg[base + NH]     - mu1) * rs1 * ghh[NH + j]     + behh[NH + j]     + bhh[NH + j];
            float hn = (hpg[base + 2 * NH] - mu2) * rs2 * ghh[2 * NH + j] + behh[2 * NH + j] + bhh[2 * NH + j];
            int tok = srow[b];
            const float* xrow = Wp + (size_t)tok * NH3;
            float xr = xrow[j], xz = xrow[NH + j], xn = xrow[2 * NH + j];
            float r = 1.f / (1.f + __expf(-(xr + hr)));
            float z = 1.f / (1.f + __expf(-(xz + hz)));
            float n = tanhf(xn + r * hn);
            float ho = hglob[e];
            float hnew = (1.f - z) * n + z * ho;
            hglob[e] = hnew;
            g_gru[((size_t)s * NB + b) * (2 * NH) + dir * NH + j] = hnew;
            if (t == NS - 1)
                dout[(size_t)NS * NB * NH + (size_t)dir * NB * NH + e] = hnew;
        }
        // zero the opposite-parity stats for this direction (used next step)
        int zi = cid * REC_THREADS + tid;
        if (zi < NB * 3 * 2) g_stats[par ^ 1][dir][zi] = 0.f;
        dirbar(dir);
    }
}

// ----------------------------------------------------------------------------
// Launch
// ----------------------------------------------------------------------------
extern "C" void kernel_launch(void* const* d_in, const int* in_sizes, int n_in,
                              void* d_out, int out_size) {
    (void)in_sizes; (void)n_in; (void)out_size;
    const int*   src    = (const int*)  d_in[0];
    const float* emb    = (const float*)d_in[1];
    const float* W_ih_f = (const float*)d_in[2];
    const float* W_hh_f = (const float*)d_in[3];
    const float* b_ih_f = (const float*)d_in[4];
    const float* bhh_f  = (const float*)d_in[5];
    const float* gih_f  = (const float*)d_in[6];
    const float* beih_f = (const float*)d_in[7];
    const float* ghh_f  = (const float*)d_in[8];
    const float* behh_f = (const float*)d_in[9];
    const float* W_ih_b = (const float*)d_in[10];
    const float* W_hh_b = (const float*)d_in[11];
    const float* b_ih_b = (const float*)d_in[12];
    const float* bhh_b  = (const float*)d_in[13];
    const float* gih_b  = (const float*)d_in[14];
    const float* beih_b = (const float*)d_in[15];
    const float* ghh_b  = (const float*)d_in[16];
    const float* behh_b = (const float*)d_in[17];
    const float* W_out  = (const float*)d_in[18];
    const float* b_out  = (const float*)d_in[19];
    float* out = (float*)d_out;

    void *pWp0, *pWp1, *pGru;
    cudaGetSymbolAddress(&pWp0, g_Wp0);
    cudaGetSymbolAddress(&pWp1, g_Wp1);
    cudaGetSymbolAddress(&pGru, g_gru);
    cudaFuncSetAttribute(gru_rec, cudaFuncAttributeMaxDynamicSharedMemorySize,
                         REC_SMEM_BYTES);

    init_k<<<256, 256>>>();

    // Vocab-level input projection: Wp = emb @ W_ih^T  (32000 x 1536, K=512)
    sgemm_nt<0><<<dim3(NH3 / 128, NV / 128), 256>>>(
        emb, W_ih_f, (float*)pWp0, NV, NH3, NE, nullptr);
    sgemm_nt<0><<<dim3(NH3 / 128, NV / 128), 256>>>(
        emb, W_ih_b, (float*)pWp1, NV, NH3, NE, nullptr);

    // Per-gate LayerNorm + scale/shift + input bias, in place (token 0 -> zero x)
    ln_k<<<2 * NV * 3, 128>>>(gih_f, beih_f, b_ih_f, gih_b, beih_b, b_ih_b);

    // Persistent bidirectional recurrence
    gru_rec<<<2 * NCD, REC_THREADS, REC_SMEM_BYTES>>>(
        src, W_hh_f, W_hh_b, ghh_f, behh_f, bhh_f, ghh_b, behh_b, bhh_b, out);

    // Output projection with tanh epilogue: out = tanh(gru_out @ W_out^T + b_out)
    sgemm_nt<1><<<dim3(NH / 128, (NS * NB) / 128), 256>>>(
        (const float*)pGru, W_out, out, NS * NB, NH, 2 * NH, b_out);
}

// round 4
// speedup vs baseline: 1.0546x; 1.0546x over previous
#include <cuda_runtime.h>
#include <math.h>

// Problem sizes
constexpr int NS = 1024;   // sequence length
constexpr int NB = 64;     // batch
constexpr int NE = 512;    // embed dim
constexpr int NH = 512;    // hidden
constexpr int NH3 = 3 * NH;
constexpr int NV = 32000;  // vocab
constexpr int NCD = 48;    // CTAs per direction in recurrent kernel
constexpr int REC_THREADS = 256;
constexpr int REC_SMEM_FLOATS = 16384 /*W*/ + 32768 /*h*/ + 2048 /*pacc*/;
constexpr int REC_SMEM_BYTES = REC_SMEM_FLOATS * 4;  // 204800

// ----------------------------------------------------------------------------
// Packed fp32x2 helpers (Blackwell; full fp32 precision, 2 MACs / instruction)
// ----------------------------------------------------------------------------
__device__ __forceinline__ unsigned long long splat2(float x) {
    unsigned long long r;
    asm("mov.b64 %0, {%1, %1};" : "=l"(r) : "f"(x));
    return r;
}
__device__ __forceinline__ void ffma2(unsigned long long& d,
                                      unsigned long long a,
                                      unsigned long long b) {
    asm("fma.rn.f32x2 %0, %1, %2, %0;" : "+l"(d) : "l"(a), "l"(b));
}
__device__ __forceinline__ float2 un2(unsigned long long v) {
    float2 f;
    asm("mov.b64 {%0, %1}, %2;" : "=f"(f.x), "=f"(f.y) : "l"(v));
    return f;
}

// ----------------------------------------------------------------------------
// Device scratch (static; no runtime allocation allowed)
// ----------------------------------------------------------------------------
__device__ float g_Wp0[(size_t)NV * NH3];      // LN'd input projection table, fwd
__device__ float g_Wp1[(size_t)NV * NH3];      // LN'd input projection table, bwd
__device__ float g_gru[(size_t)NS * NB * 2 * NH];  // concat GRU outputs
__device__ float g_hp[2][NB * NH3];            // per-step raw h-projection
__device__ float g_h[2][NB * NH];              // hidden state per direction
__device__ float g_stats[2][2][NB * 3 * 2];    // [parity][dir][b*6 + gate*2 + {sum,sumsq}]
__device__ unsigned g_cnt[2];
__device__ unsigned g_gen[2];

// ----------------------------------------------------------------------------
// Init: zero h and stats
// ----------------------------------------------------------------------------
__global__ void init_k() {
    int i = blockIdx.x * blockDim.x + threadIdx.x;
    if (i < 2 * NB * NH) ((float*)g_h)[i] = 0.f;
    if (i < 2 * 2 * NB * 3 * 2) ((float*)g_stats)[i] = 0.f;
}

// ----------------------------------------------------------------------------
// SGEMM: C[M,N] = A[M,K] * Bw[N,K]^T   (A,Bw,C row-major)
// FFMA2 column-packed accumulators, double-buffered smem (1 sync/chunk).
// EPI=1: C = tanh(C + bias[n]). M%128==0, N%128==0, K%8==0 assumed.
// ----------------------------------------------------------------------------
template <int EPI>
__global__ void __launch_bounds__(256) sgemm_nt(
    const float* __restrict__ A, const float* __restrict__ Bw,
    float* __restrict__ C, int M, int N, int K, const float* __restrict__ bias)
{
    __shared__ __align__(16) float As[2][8][128];
    __shared__ __align__(16) float Bs[2][8][128];
    int tid = threadIdx.x;
    int lrow = tid >> 1;
    int lcol = (tid & 1) * 4;
    int tr = (tid >> 4) << 3;
    int tc = (tid & 15) << 3;
    const float* Ab = A + (size_t)blockIdx.y * 128 * K + (size_t)lrow * K + lcol;
    const float* Bb = Bw + (size_t)blockIdx.x * 128 * K + (size_t)lrow * K + lcol;

    unsigned long long acc2[8][4];
#pragma unroll
    for (int i = 0; i < 8; i++)
#pragma unroll
        for (int j = 0; j < 4; j++) acc2[i][j] = 0ull;

    // Preload chunk 0 into buffer 0
    {
        float4 av = *(const float4*)Ab;
        float4 bv = *(const float4*)Bb;
        As[0][lcol + 0][lrow] = av.x; As[0][lcol + 1][lrow] = av.y;
        As[0][lcol + 2][lrow] = av.z; As[0][lcol + 3][lrow] = av.w;
        Bs[0][lcol + 0][lrow] = bv.x; Bs[0][lcol + 1][lrow] = bv.y;
        Bs[0][lcol + 2][lrow] = bv.z; Bs[0][lcol + 3][lrow] = bv.w;
    }
    __syncthreads();

    int nk = K >> 3;
    for (int kc = 0; kc < nk; kc++) {
        int cur = kc & 1;
        float4 av2, bv2;
        bool more = (kc + 1 < nk);
        if (more) {
            av2 = *(const float4*)(Ab + (kc + 1) * 8);
            bv2 = *(const float4*)(Bb + (kc + 1) * 8);
        }
#pragma unroll
        for (int k = 0; k < 8; k++) {
            float4 a0 = *(const float4*)&As[cur][k][tr];
            float4 a1 = *(const float4*)&As[cur][k][tr + 4];
            ulonglong2 b0 = *(const ulonglong2*)&Bs[cur][k][tc];
            ulonglong2 b1 = *(const ulonglong2*)&Bs[cur][k][tc + 4];
            float ra[8] = {a0.x, a0.y, a0.z, a0.w, a1.x, a1.y, a1.z, a1.w};
            unsigned long long pb[4] = {b0.x, b0.y, b1.x, b1.y};
#pragma unroll
            for (int i = 0; i < 8; i++) {
                unsigned long long sa = splat2(ra[i]);
#pragma unroll
                for (int j = 0; j < 4; j++) ffma2(acc2[i][j], sa, pb[j]);
            }
        }
        if (more) {
            int nxt = cur ^ 1;
            As[nxt][lcol + 0][lrow] = av2.x; As[nxt][lcol + 1][lrow] = av2.y;
            As[nxt][lcol + 2][lrow] = av2.z; As[nxt][lcol + 3][lrow] = av2.w;
            Bs[nxt][lcol + 0][lrow] = bv2.x; Bs[nxt][lcol + 1][lrow] = bv2.y;
            Bs[nxt][lcol + 2][lrow] = bv2.z; Bs[nxt][lcol + 3][lrow] = bv2.w;
        }
        __syncthreads();
    }

#pragma unroll
    for (int i = 0; i < 8; i++) {
        size_t crow = (size_t)(blockIdx.y * 128 + tr + i) * N + blockIdx.x * 128 + tc;
        float cv[8];
#pragma unroll
        for (int j = 0; j < 4; j++) {
            float2 p = un2(acc2[i][j]);
            cv[2 * j] = p.x; cv[2 * j + 1] = p.y;
        }
#pragma unroll
        for (int j = 0; j < 8; j += 4) {
            float4 v;
            v.x = cv[j]; v.y = cv[j + 1]; v.z = cv[j + 2]; v.w = cv[j + 3];
            if (EPI) {
                int nb = blockIdx.x * 128 + tc + j;
                v.x = tanhf(v.x + bias[nb]);
                v.y = tanhf(v.y + bias[nb + 1]);
                v.z = tanhf(v.z + bias[nb + 2]);
                v.w = tanhf(v.w + bias[nb + 3]);
            }
            *(float4*)(C + crow + j) = v;
        }
    }
}

// ----------------------------------------------------------------------------
// LayerNorm over vocab projection table rows (per gate), in place.
// ----------------------------------------------------------------------------
__global__ void ln_k(const float* __restrict__ gA, const float* __restrict__ beA,
                     const float* __restrict__ bA, const float* __restrict__ gB,
                     const float* __restrict__ beB, const float* __restrict__ bB)
{
    int row = blockIdx.x;               // 0 .. 2*NV*3-1
    int dir = row >= NV * 3;
    int rem = dir ? row - NV * 3 : row;
    int tok = rem / 3;
    int gate = rem - tok * 3;
    float* p = (dir ? g_Wp1 : g_Wp0) + (size_t)tok * NH3 + gate * NH;
    const float* gg = (dir ? gB : gA) + gate * NH;
    const float* be = (dir ? beB : beA) + gate * NH;
    const float* bi = (dir ? bB : bA) + gate * NH;
    int tid = threadIdx.x;              // 128 threads
    float4 v = ((float4*)p)[tid];
    if (tok == 0) { v.x = 0.f; v.y = 0.f; v.z = 0.f; v.w = 0.f; }
    float sum = v.x + v.y + v.z + v.w;
    float sq = v.x * v.x + v.y * v.y + v.z * v.z + v.w * v.w;
#pragma unroll
    for (int o = 16; o; o >>= 1) {
        sum += __shfl_xor_sync(0xffffffffu, sum, o);
        sq  += __shfl_xor_sync(0xffffffffu, sq, o);
    }
    __shared__ float ss[4], sc[4];
    int w = tid >> 5;
    if ((tid & 31) == 0) { ss[w] = sum; sc[w] = sq; }
    __syncthreads();
    sum = ss[0] + ss[1] + ss[2] + ss[3];
    sq  = sc[0] + sc[1] + sc[2] + sc[3];
    float mu = sum * (1.f / NH);
    float var = sq * (1.f / NH) - mu * mu;
    float rs = rsqrtf(var + 1e-5f);
    int j = tid * 4;
    v.x = (v.x - mu) * rs * gg[j]     + be[j]     + bi[j];
    v.y = (v.y - mu) * rs * gg[j + 1] + be[j + 1] + bi[j + 1];
    v.z = (v.z - mu) * rs * gg[j + 2] + be[j + 2] + bi[j + 2];
    v.w = (v.w - mu) * rs * gg[j + 3] + be[j + 3] + bi[j + 3];
    ((float4*)p)[tid] = v;
}

// ----------------------------------------------------------------------------
// Per-direction grid barrier: volatile-load polling (no RMW storm).
// ----------------------------------------------------------------------------
__device__ __forceinline__ void dirbar(int dir) {
    __threadfence();
    __syncthreads();
    if (threadIdx.x == 0) {
        volatile unsigned* genp = &g_gen[dir];
        unsigned g = *genp;
        if (atomicAdd(&g_cnt[dir], 1u) == NCD - 1) {
            atomicExch(&g_cnt[dir], 0u);
            __threadfence();
            *genp = g + 1u;
        } else {
            while (*genp == g) __nanosleep(32);
        }
        __threadfence();
    }
    __syncthreads();
}

// ----------------------------------------------------------------------------
// Persistent bidirectional GRU recurrence (FFMA2 phase-1).
// ----------------------------------------------------------------------------
__global__ void __launch_bounds__(REC_THREADS, 1) gru_rec(
    const int* __restrict__ src,
    const float* __restrict__ Whh_f, const float* __restrict__ Whh_b,
    const float* __restrict__ ghh_f, const float* __restrict__ behh_f,
    const float* __restrict__ bhh_f, const float* __restrict__ ghh_b,
    const float* __restrict__ behh_b, const float* __restrict__ bhh_b,
    float* __restrict__ dout)
{
    extern __shared__ __align__(16) float sm[];
    float4* wsv = (float4*)sm;               // 4096 float4  (W slice, [k4][c])
    float4* hsv = (float4*)(sm + 16384);     // 8192 float4  (h, [b][k4])
    float*  pacc = sm + 16384 + 32768;       // 2048 floats
    const ulonglong2* wsv2 = (const ulonglong2*)sm;
    const ulonglong2* hsv2 = (const ulonglong2*)(sm + 16384);

    int dir = blockIdx.x / NCD;
    int cid = blockIdx.x - dir * NCD;
    int tid = threadIdx.x;
    int lane = tid & 31, wid = tid >> 5;

    const float* Whh  = dir ? Whh_b  : Whh_f;
    const float* ghh  = dir ? ghh_b  : ghh_f;
    const float* behh = dir ? behh_b : behh_f;
    const float* bhh  = dir ? bhh_b  : bhh_f;
    const float* Wp   = dir ? g_Wp1  : g_Wp0;
    float* hglob = g_h[dir];
    float* hpg = g_hp[dir];
    int gate = cid >> 4;                     // (cid*32)/512

    // Preload W_hh slice: rows [cid*32, cid*32+32), all 512 K, layout [k4][c].
    for (int idx = tid; idx < 4096; idx += REC_THREADS) {
        int k4 = idx >> 5, c = idx & 31;
        wsv[idx] = *(const float4*)(Whh + (size_t)(cid * 32 + c) * NH + k4 * 4);
    }

    int kh = wid >> 2;          // k-half: warps 0-3 -> [0,256), 4-7 -> [256,512)
    int bg = (wid & 3) * 16;    // batch group base
    int kb4 = kh * 64;

    for (int t = 0; t < NS; t++) {
        int s = dir ? (NS - 1 - t) : t;
        int par = t & 1;

        __syncthreads();
        // Stage h into shared (coalesced float4)
        for (int idx = tid; idx < 8192; idx += REC_THREADS)
            hsv[idx] = ((const float4*)hglob)[idx];
        __syncthreads();

        // Phase 1: hp[b][c] = sum_k h[b][k] * Whh[c][k], FFMA2 (k-pair packed)
        unsigned long long acc2[16];
#pragma unroll
        for (int i = 0; i < 16; i++) acc2[i] = 0ull;
#pragma unroll 4
        for (int k4 = kb4; k4 < kb4 + 64; k4++) {
            ulonglong2 wv = wsv2[(k4 << 5) + lane];
#pragma unroll
            for (int i = 0; i < 16; i++) {
                ulonglong2 hv = hsv2[((bg + i) << 7) + k4];  // broadcast in warp
                ffma2(acc2[i], wv.x, hv.x);
                ffma2(acc2[i], wv.y, hv.y);
            }
        }
        float acc[16];
#pragma unroll
        for (int i = 0; i < 16; i++) {
            float2 p = un2(acc2[i]);
            acc[i] = p.x + p.y;
        }
        if (kh) {
#pragma unroll
            for (int i = 0; i < 16; i++) pacc[((bg + i) << 5) + lane] = acc[i];
        }
        __syncthreads();
        if (!kh) {
#pragma unroll
            for (int i = 0; i < 16; i++) {
                float v = acc[i] + pacc[((bg + i) << 5) + lane];
                acc[i] = v;
                hpg[(bg + i) * NH3 + cid * 32 + lane] = v;
            }
            // per-(b,gate) partial LN stats
#pragma unroll
            for (int i = 0; i < 16; i++) {
                float sv = acc[i], sq = acc[i] * acc[i];
#pragma unroll
                for (int o = 16; o; o >>= 1) {
                    sv += __shfl_xor_sync(0xffffffffu, sv, o);
                    sq += __shfl_xor_sync(0xffffffffu, sq, o);
                }
                if (lane == 0) {
                    float* st = &g_stats[par][dir][(bg + i) * 6 + gate * 2];
                    atomicAdd(st, sv);
                    atomicAdd(st + 1, sq);
                }
            }
        }
        dirbar(dir);

        // Phase 2: LN(hp), gates, h update, write y
        const int* srow = src + s * NB;
        for (int e = cid * REC_THREADS + tid; e < NB * NH; e += NCD * REC_THREADS) {
            int b = e >> 9, j = e & (NH - 1);
            const float* st = &g_stats[par][dir][b * 6];
            float mu0 = st[0] * (1.f / NH);
            float rs0 = rsqrtf(st[1] * (1.f / NH) - mu0 * mu0 + 1e-5f);
            float mu1 = st[2] * (1.f / NH);
            float rs1 = rsqrtf(st[3] * (1.f / NH) - mu1 * mu1 + 1e-5f);
            float mu2 = st[4] * (1.f / NH);
            float rs2 = rsqrtf(st[5] * (1.f / NH) - mu2 * mu2 + 1e-5f);
            int base = b * NH3 + j;
            float hr = (hpg[base]          - mu0) * rs0 * ghh[j]          + behh[j]          + bhh[j];
            float hz = (hpg[base + NH]     - mu1) * rs1 * ghh[NH + j]     + behh[NH + j]     + bhh[NH + j];
            float hn = (hpg[base + 2 * NH] - mu2) * rs2 * ghh[2 * NH + j] + behh[2 * NH + j] + bhh[2 * NH + j];
            int tok = srow[b];
            const float* xrow = Wp + (size_t)tok * NH3;
            float xr = xrow[j], xz = xrow[NH + j], xn = xrow[2 * NH + j];
            float r = 1.f / (1.f + __expf(-(xr + hr)));
            float z = 1.f / (1.f + __expf(-(xz + hz)));
            float n = tanhf(xn + r * hn);
            float ho = hglob[e];
            float hnew = (1.f - z) * n + z * ho;
            hglob[e] = hnew;
            g_gru[((size_t)s * NB + b) * (2 * NH) + dir * NH + j] = hnew;
            if (t == NS - 1)
                dout[(size_t)NS * NB * NH + (size_t)dir * NB * NH + e] = hnew;
        }
        // zero the opposite-parity stats for this direction (used next step)
        int zi = cid * REC_THREADS + tid;
        if (zi < NB * 3 * 2) g_stats[par ^ 1][dir][zi] = 0.f;
        dirbar(dir);
    }
}

// ----------------------------------------------------------------------------
// Launch
// ----------------------------------------------------------------------------
extern "C" void kernel_launch(void* const* d_in, const int* in_sizes, int n_in,
                              void* d_out, int out_size) {
    (void)in_sizes; (void)n_in; (void)out_size;
    const int*   src    = (const int*)  d_in[0];
    const float* emb    = (const float*)d_in[1];
    const float* W_ih_f = (const float*)d_in[2];
    const float* W_hh_f = (const float*)d_in[3];
    const float* b_ih_f = (const float*)d_in[4];
    const float* bhh_f  = (const float*)d_in[5];
    const float* gih_f  = (const float*)d_in[6];
    const float* beih_f = (const float*)d_in[7];
    const float* ghh_f  = (const float*)d_in[8];
    const float* behh_f = (const float*)d_in[9];
    const float* W_ih_b = (const float*)d_in[10];
    const float* W_hh_b = (const float*)d_in[11];
    const float* b_ih_b = (const float*)d_in[12];
    const float* bhh_b  = (const float*)d_in[13];
    const float* gih_b  = (const float*)d_in[14];
    const float* beih_b = (const float*)d_in[15];
    const float* ghh_b  = (const float*)d_in[16];
    const float* behh_b = (const float*)d_in[17];
    const float* W_out  = (const float*)d_in[18];
    const float* b_out  = (const float*)d_in[19];
    float* out = (float*)d_out;

    void *pWp0, *pWp1, *pGru;
    cudaGetSymbolAddress(&pWp0, g_Wp0);
    cudaGetSymbolAddress(&pWp1, g_Wp1);
    cudaGetSymbolAddress(&pGru, g_gru);
    cudaFuncSetAttribute(gru_rec, cudaFuncAttributeMaxDynamicSharedMemorySize,
                         REC_SMEM_BYTES);

    init_k<<<256, 256>>>();

    // Vocab-level input projection: Wp = emb @ W_ih^T  (32000 x 1536, K=512)
    sgemm_nt<0><<<dim3(NH3 / 128, NV / 128), 256>>>(
        emb, W_ih_f, (float*)pWp0, NV, NH3, NE, nullptr);
    sgemm_nt<0><<<dim3(NH3 / 128, NV / 128), 256>>>(
        emb, W_ih_b, (float*)pWp1, NV, NH3, NE, nullptr);

    // Per-gate LayerNorm + scale/shift + input bias, in place (token 0 -> zero x)
    ln_k<<<2 * NV * 3, 128>>>(gih_f, beih_f, b_ih_f, gih_b, beih_b, b_ih_b);

    // Persistent bidirectional recurrence
    gru_rec<<<2 * NCD, REC_THREADS, REC_SMEM_BYTES>>>(
        src, W_hh_f, W_hh_b, ghh_f, behh_f, bhh_f, ghh_b, behh_b, bhh_b, out);

    // Output projection with tanh epilogue: out = tanh(gru_out @ W_out^T + b_out)
    sgemm_nt<1><<<dim3(NH / 128, (NS * NB) / 128), 256>>>(
        (const float*)pGru, W_out, out, NS * NB, NH, 2 * NH, b_out);
}

// round 5
// speedup vs baseline: 1.2070x; 1.1445x over previous
#include <cuda_runtime.h>
#include <math.h>

// Problem sizes
constexpr int NS = 1024;   // sequence length
constexpr int NB = 64;     // batch
constexpr int NE = 512;    // embed dim
constexpr int NH = 512;    // hidden
constexpr int NH3 = 3 * NH;
constexpr int NV = 32000;  // vocab
constexpr int NCD = 64;    // CTAs per direction (each owns 8 j-cols x 3 gates)
constexpr int JS = 8;      // j columns per CTA
constexpr int NROW = 24;   // W rows per CTA (3 gates x JS)
constexpr int REC_THREADS = 256;
// smem: W 24x512 fl (12288) | h padded 64x129 fl4 (33024 fl) | pacc 64*25 | hp 64*25
constexpr int SM_W = 0;
constexpr int SM_H = 12288;            // float index (16B aligned: 12288*4=49152)
constexpr int SM_PACC = SM_H + 33024;  // 45312
constexpr int SM_HP = SM_PACC + 1600;  // 46912
constexpr int REC_SMEM_BYTES = (SM_HP + 1600) * 4;  // 194048

// ----------------------------------------------------------------------------
// Packed fp32x2 helpers (full fp32 precision, 2 MACs / instruction)
// ----------------------------------------------------------------------------
__device__ __forceinline__ unsigned long long splat2(float x) {
    unsigned long long r;
    asm("mov.b64 %0, {%1, %1};" : "=l"(r) : "f"(x));
    return r;
}
__device__ __forceinline__ void ffma2(unsigned long long& d,
                                      unsigned long long a,
                                      unsigned long long b) {
    asm("fma.rn.f32x2 %0, %1, %2, %0;" : "+l"(d) : "l"(a), "l"(b));
}
__device__ __forceinline__ float2 un2(unsigned long long v) {
    float2 f;
    asm("mov.b64 {%0, %1}, %2;" : "=f"(f.x), "=f"(f.y) : "l"(v));
    return f;
}

// ----------------------------------------------------------------------------
// Device scratch
// ----------------------------------------------------------------------------
__device__ float g_Wp0[(size_t)NV * NH3];
__device__ float g_Wp1[(size_t)NV * NH3];
__device__ float g_gru[(size_t)NS * NB * 2 * NH];
__device__ float g_h[2][NB * NH];
__device__ float g_stats[2][2][NB * 3 * 2];  // [parity][dir][b*6 + gate*2 + {sum,sq}]
__device__ unsigned g_cnt[2];
__device__ unsigned g_gen[2];

// ----------------------------------------------------------------------------
// SGEMM: C[M,N] = A[M,K] * Bw[N,K]^T, FFMA2, double-buffered.
// EPI=1: C = tanh(C + bias[n]).
// ----------------------------------------------------------------------------
template <int EPI>
__global__ void __launch_bounds__(256) sgemm_nt(
    const float* __restrict__ A, const float* __restrict__ Bw,
    float* __restrict__ C, int M, int N, int K, const float* __restrict__ bias)
{
    __shared__ __align__(16) float As[2][8][128];
    __shared__ __align__(16) float Bs[2][8][128];
    int tid = threadIdx.x;
    int lrow = tid >> 1;
    int lcol = (tid & 1) * 4;
    int tr = (tid >> 4) << 3;
    int tc = (tid & 15) << 3;
    const float* Ab = A + (size_t)blockIdx.y * 128 * K + (size_t)lrow * K + lcol;
    const float* Bb = Bw + (size_t)blockIdx.x * 128 * K + (size_t)lrow * K + lcol;

    unsigned long long acc2[8][4];
#pragma unroll
    for (int i = 0; i < 8; i++)
#pragma unroll
        for (int j = 0; j < 4; j++) acc2[i][j] = 0ull;

    {
        float4 av = *(const float4*)Ab;
        float4 bv = *(const float4*)Bb;
        As[0][lcol + 0][lrow] = av.x; As[0][lcol + 1][lrow] = av.y;
        As[0][lcol + 2][lrow] = av.z; As[0][lcol + 3][lrow] = av.w;
        Bs[0][lcol + 0][lrow] = bv.x; Bs[0][lcol + 1][lrow] = bv.y;
        Bs[0][lcol + 2][lrow] = bv.z; Bs[0][lcol + 3][lrow] = bv.w;
    }
    __syncthreads();

    int nk = K >> 3;
    for (int kc = 0; kc < nk; kc++) {
        int cur = kc & 1;
        float4 av2, bv2;
        bool more = (kc + 1 < nk);
        if (more) {
            av2 = *(const float4*)(Ab + (kc + 1) * 8);
            bv2 = *(const float4*)(Bb + (kc + 1) * 8);
        }
#pragma unroll
        for (int k = 0; k < 8; k++) {
            float4 a0 = *(const float4*)&As[cur][k][tr];
            float4 a1 = *(const float4*)&As[cur][k][tr + 4];
            ulonglong2 b0 = *(const ulonglong2*)&Bs[cur][k][tc];
            ulonglong2 b1 = *(const ulonglong2*)&Bs[cur][k][tc + 4];
            float ra[8] = {a0.x, a0.y, a0.z, a0.w, a1.x, a1.y, a1.z, a1.w};
            unsigned long long pb[4] = {b0.x, b0.y, b1.x, b1.y};
#pragma unroll
            for (int i = 0; i < 8; i++) {
                unsigned long long sa = splat2(ra[i]);
#pragma unroll
                for (int j = 0; j < 4; j++) ffma2(acc2[i][j], sa, pb[j]);
            }
        }
        if (more) {
            int nxt = cur ^ 1;
            As[nxt][lcol + 0][lrow] = av2.x; As[nxt][lcol + 1][lrow] = av2.y;
            As[nxt][lcol + 2][lrow] = av2.z; As[nxt][lcol + 3][lrow] = av2.w;
            Bs[nxt][lcol + 0][lrow] = bv2.x; Bs[nxt][lcol + 1][lrow] = bv2.y;
            Bs[nxt][lcol + 2][lrow] = bv2.z; Bs[nxt][lcol + 3][lrow] = bv2.w;
        }
        __syncthreads();
    }

#pragma unroll
    for (int i = 0; i < 8; i++) {
        size_t crow = (size_t)(blockIdx.y * 128 + tr + i) * N + blockIdx.x * 128 + tc;
        float cv[8];
#pragma unroll
        for (int j = 0; j < 4; j++) {
            float2 p = un2(acc2[i][j]);
            cv[2 * j] = p.x; cv[2 * j + 1] = p.y;
        }
#pragma unroll
        for (int j = 0; j < 8; j += 4) {
            float4 v;
            v.x = cv[j]; v.y = cv[j + 1]; v.z = cv[j + 2]; v.w = cv[j + 3];
            if (EPI) {
                int nb = blockIdx.x * 128 + tc + j;
                v.x = tanhf(v.x + bias[nb]);
                v.y = tanhf(v.y + bias[nb + 1]);
                v.z = tanhf(v.z + bias[nb + 2]);
                v.w = tanhf(v.w + bias[nb + 3]);
            }
            *(float4*)(C + crow + j) = v;
        }
    }
}

// ----------------------------------------------------------------------------
// LayerNorm over vocab projection rows (per gate), in place + init duties
// (zero h and stats in the first 513 blocks).
// ----------------------------------------------------------------------------
__global__ void ln_k(const float* __restrict__ gA, const float* __restrict__ beA,
                     const float* __restrict__ bA, const float* __restrict__ gB,
                     const float* __restrict__ beB, const float* __restrict__ bB)
{
    int row = blockIdx.x;               // 0 .. 2*NV*3-1
    int tid = threadIdx.x;              // 128 threads
    // fused init
    if (row < 512) {
        ((float*)g_h)[row * 128 + tid] = 0.f;
    } else if (row == 512) {
        for (int q = 0; q < 12; q++) ((float*)g_stats)[q * 128 + tid] = 0.f;
    }
    int dir = row >= NV * 3;
    int rem = dir ? row - NV * 3 : row;
    int tok = rem / 3;
    int gate = rem - tok * 3;
    float* p = (dir ? g_Wp1 : g_Wp0) + (size_t)tok * NH3 + gate * NH;
    const float* gg = (dir ? gB : gA) + gate * NH;
    const float* be = (dir ? beB : beA) + gate * NH;
    const float* bi = (dir ? bB : bA) + gate * NH;
    float4 v = ((float4*)p)[tid];
    if (tok == 0) { v.x = 0.f; v.y = 0.f; v.z = 0.f; v.w = 0.f; }
    float sum = v.x + v.y + v.z + v.w;
    float sq = v.x * v.x + v.y * v.y + v.z * v.z + v.w * v.w;
#pragma unroll
    for (int o = 16; o; o >>= 1) {
        sum += __shfl_xor_sync(0xffffffffu, sum, o);
        sq  += __shfl_xor_sync(0xffffffffu, sq, o);
    }
    __shared__ float ss[4], sc[4];
    int w = tid >> 5;
    if ((tid & 31) == 0) { ss[w] = sum; sc[w] = sq; }
    __syncthreads();
    sum = ss[0] + ss[1] + ss[2] + ss[3];
    sq  = sc[0] + sc[1] + sc[2] + sc[3];
    float mu = sum * (1.f / NH);
    float var = sq * (1.f / NH) - mu * mu;
    float rs = rsqrtf(var + 1e-5f);
    int j = tid * 4;
    v.x = (v.x - mu) * rs * gg[j]     + be[j]     + bi[j];
    v.y = (v.y - mu) * rs * gg[j + 1] + be[j + 1] + bi[j + 1];
    v.z = (v.z - mu) * rs * gg[j + 2] + be[j + 2] + bi[j + 2];
    v.w = (v.w - mu) * rs * gg[j + 3] + be[j + 3] + bi[j + 3];
    ((float4*)p)[tid] = v;
}

// ----------------------------------------------------------------------------
// Per-direction grid barrier (NCD CTAs per direction, all co-resident).
// ----------------------------------------------------------------------------
__device__ __forceinline__ void dirbar(int dir) {
    __threadfence();
    __syncthreads();
    if (threadIdx.x == 0) {
        volatile unsigned* genp = &g_gen[dir];
        unsigned g = *genp;
        if (atomicAdd(&g_cnt[dir], 1u) == NCD - 1) {
            atomicExch(&g_cnt[dir], 0u);
            __threadfence();
            *genp = g + 1u;
        } else {
            while (*genp == g) { }
        }
        __threadfence();
    }
    __syncthreads();
}

// ----------------------------------------------------------------------------
// Persistent bidirectional GRU recurrence, j-slice ownership.
// Grid: 2*NCD CTAs. CTA owns j in [cid*8, cid*8+8) for ALL 3 gates.
// hp stays in shared memory; only LN stats cross CTAs.
// ----------------------------------------------------------------------------
__global__ void __launch_bounds__(REC_THREADS, 1) gru_rec(
    const int* __restrict__ src,
    const float* __restrict__ Whh_f, const float* __restrict__ Whh_b,
    const float* __restrict__ ghh_f, const float* __restrict__ behh_f,
    const float* __restrict__ bhh_f, const float* __restrict__ ghh_b,
    const float* __restrict__ behh_b, const float* __restrict__ bhh_b,
    float* __restrict__ dout)
{
    extern __shared__ __align__(16) float sm[];
    float* wsm = sm + SM_W;                  // [24][512]
    float4* hsm4 = (float4*)(sm + SM_H);     // [64][129] padded rows
    float* hsm = sm + SM_H;                  // float view: h[b][k] at b*516+k
    float* pacc = sm + SM_PACC;              // [64][25]
    float* hps = sm + SM_HP;                 // [64][25] hp[b][row]

    int dir = blockIdx.x / NCD;
    int cid = blockIdx.x - dir * NCD;
    int tid = threadIdx.x;
    int lane = tid & 31, wid = tid >> 5;
    int jbase = cid * JS;

    const float* Whh  = dir ? Whh_b  : Whh_f;
    const float* ghh  = dir ? ghh_b  : ghh_f;
    const float* behh = dir ? behh_b : behh_f;
    const float* bhh  = dir ? bhh_b  : bhh_f;
    const float* Wp   = dir ? g_Wp1  : g_Wp0;
    float* hglob = g_h[dir];

    // Preload W rows: row r -> (gate=r>>3, jj=r&7) -> Whh row gate*512+jbase+jj
    for (int idx = tid; idx < NROW * NH; idx += REC_THREADS) {
        int r = idx >> 9, k = idx & (NH - 1);
        int grow = (r >> 3) * NH + jbase + (r & 7);
        wsm[r * NH + k] = Whh[(size_t)grow * NH + k];
    }

    // phase-1 mapping
    int kh = wid >> 2;            // k-half
    int rgrp = wid & 3;           // row group of 6
    int rbase = rgrp * 6;
    int kb4 = kh * 64;            // k4 range [kb4, kb4+64)
    int b0 = lane, b1 = lane + 32;

    // phase-2 mapping + per-thread constants
    int pb = tid >> 2;            // batch
    int jj0 = (tid & 3) * 2;      // local j offset (2 per thread)
    float cg[3][2], cbe[3][2], cbb[3][2];
#pragma unroll
    for (int g = 0; g < 3; g++)
#pragma unroll
        for (int d = 0; d < 2; d++) {
            int j = g * NH + jbase + jj0 + d;
            cg[g][d] = ghh[j]; cbe[g][d] = behh[j]; cbb[g][d] = bhh[j];
        }

    for (int t = 0; t < NS; t++) {
        int s = dir ? (NS - 1 - t) : t;
        int par = t & 1;

        __syncthreads();
        // Stage h into padded shared rows
        for (int idx = tid; idx < NB * 128; idx += REC_THREADS) {
            int b = idx >> 7, k4 = idx & 127;
            hsm4[b * 129 + k4] = ((const float4*)hglob)[idx];
        }
        __syncthreads();

        // Prefetch x gather (DRAM) for phase 2 — overlaps phase-1 compute
        int tok = __ldg(src + s * NB + pb);
        const float* xrow = Wp + (size_t)tok * NH3;
        float xv[3][2];
#pragma unroll
        for (int g = 0; g < 3; g++)
#pragma unroll
            for (int d = 0; d < 2; d++)
                xv[g][d] = __ldg(xrow + g * NH + jbase + jj0 + d);

        // Phase 1: hp[b][r] = sum_k h[b][k] * W[r][k]  (FFMA2, k-pair packed)
        unsigned long long acc2[6][2];
#pragma unroll
        for (int r = 0; r < 6; r++) { acc2[r][0] = 0ull; acc2[r][1] = 0ull; }
#pragma unroll 4
        for (int k4 = kb4; k4 < kb4 + 64; k4++) {
            ulonglong2 h0 = *(const ulonglong2*)&hsm4[b0 * 129 + k4];
            ulonglong2 h1 = *(const ulonglong2*)&hsm4[b1 * 129 + k4];
#pragma unroll
            for (int r = 0; r < 6; r++) {
                ulonglong2 wv = *(const ulonglong2*)&wsm[(rbase + r) * NH + k4 * 4];
                ffma2(acc2[r][0], wv.x, h0.x);
                ffma2(acc2[r][0], wv.y, h0.y);
                ffma2(acc2[r][1], wv.x, h1.x);
                ffma2(acc2[r][1], wv.y, h1.y);
            }
        }
        float accf[6][2];
#pragma unroll
        for (int r = 0; r < 6; r++)
#pragma unroll
            for (int p = 0; p < 2; p++) {
                float2 u = un2(acc2[r][p]);
                accf[r][p] = u.x + u.y;
            }
        if (kh) {
#pragma unroll
            for (int r = 0; r < 6; r++) {
                pacc[b0 * 25 + rbase + r] = accf[r][0];
                pacc[b1 * 25 + rbase + r] = accf[r][1];
            }
        }
        __syncthreads();
        if (!kh) {
#pragma unroll
            for (int r = 0; r < 6; r++) {
                hps[b0 * 25 + rbase + r] = accf[r][0] + pacc[b0 * 25 + rbase + r];
                hps[b1 * 25 + rbase + r] = accf[r][1] + pacc[b1 * 25 + rbase + r];
            }
        }
        __syncthreads();

        // Partial LN stats for this CTA's 8 j per (b, gate): one atomic pair each
        if (tid < 192) {
            int g = tid >> 6, b = tid & 63;
            float sv = 0.f, sq = 0.f;
#pragma unroll
            for (int q = 0; q < 8; q++) {
                float v = hps[b * 25 + g * 8 + q];
                sv += v; sq += v * v;
            }
            float* st = &g_stats[par][dir][b * 6 + g * 2];
            atomicAdd(st, sv);
            atomicAdd(st + 1, sq);
        }
        dirbar(dir);

        // Phase 2: LN + gates + h update for this CTA's (pb, 2 j) elements
        {
            const float* st = &g_stats[par][dir][pb * 6];
            float mu0 = st[0] * (1.f / NH);
            float rs0 = rsqrtf(st[1] * (1.f / NH) - mu0 * mu0 + 1e-5f);
            float mu1 = st[2] * (1.f / NH);
            float rs1 = rsqrtf(st[3] * (1.f / NH) - mu1 * mu1 + 1e-5f);
            float mu2 = st[4] * (1.f / NH);
            float rs2 = rsqrtf(st[5] * (1.f / NH) - mu2 * mu2 + 1e-5f);
#pragma unroll
            for (int d = 0; d < 2; d++) {
                int jj = jj0 + d;
                int j = jbase + jj;
                float hr = (hps[pb * 25 + jj]      - mu0) * rs0 * cg[0][d] + cbe[0][d] + cbb[0][d];
                float hz = (hps[pb * 25 + 8 + jj]  - mu1) * rs1 * cg[1][d] + cbe[1][d] + cbb[1][d];
                float hn = (hps[pb * 25 + 16 + jj] - mu2) * rs2 * cg[2][d] + cbe[2][d] + cbb[2][d];
                float r = 1.f / (1.f + __expf(-(xv[0][d] + hr)));
                float z = 1.f / (1.f + __expf(-(xv[1][d] + hz)));
                float n = tanhf(xv[2][d] + r * hn);
                float ho = hsm[pb * 516 + j];
                float hnew = (1.f - z) * n + z * ho;
                hglob[pb * NH + j] = hnew;
                g_gru[((size_t)s * NB + pb) * (2 * NH) + dir * NH + j] = hnew;
                if (t == NS - 1)
                    dout[(size_t)NS * NB * NH + (size_t)dir * NB * NH + pb * NH + j] = hnew;
            }
        }
        // zero opposite-parity stats (CTAs 0,1 of each dir)
        if (cid < 2) {
            int zi = cid * REC_THREADS + tid;
            if (zi < NB * 6) g_stats[par ^ 1][dir][zi] = 0.f;
        }
        dirbar(dir);
    }
}

// ----------------------------------------------------------------------------
// Launch
// ----------------------------------------------------------------------------
extern "C" void kernel_launch(void* const* d_in, const int* in_sizes, int n_in,
                              void* d_out, int out_size) {
    (void)in_sizes; (void)n_in; (void)out_size;
    const int*   src    = (const int*)  d_in[0];
    const float* emb    = (const float*)d_in[1];
    const float* W_ih_f = (const float*)d_in[2];
    const float* W_hh_f = (const float*)d_in[3];
    const float* b_ih_f = (const float*)d_in[4];
    const float* bhh_f  = (const float*)d_in[5];
    const float* gih_f  = (const float*)d_in[6];
    const float* beih_f = (const float*)d_in[7];
    const float* ghh_f  = (const float*)d_in[8];
    const float* behh_f = (const float*)d_in[9];
    const float* W_ih_b = (const float*)d_in[10];
    const float* W_hh_b = (const float*)d_in[11];
    const float* b_ih_b = (const float*)d_in[12];
    const float* bhh_b  = (const float*)d_in[13];
    const float* gih_b  = (const float*)d_in[14];
    const float* beih_b = (const float*)d_in[15];
    const float* ghh_b  = (const float*)d_in[16];
    const float* behh_b = (const float*)d_in[17];
    const float* W_out  = (const float*)d_in[18];
    const float* b_out  = (const float*)d_in[19];
    float* out = (float*)d_out;

    void *pWp0, *pWp1, *pGru;
    cudaGetSymbolAddress(&pWp0, g_Wp0);
    cudaGetSymbolAddress(&pWp1, g_Wp1);
    cudaGetSymbolAddress(&pGru, g_gru);
    cudaFuncSetAttribute(gru_rec, cudaFuncAttributeMaxDynamicSharedMemorySize,
                         REC_SMEM_BYTES);

    // Vocab-level input projection: Wp = emb @ W_ih^T  (32000 x 1536, K=512)
    sgemm_nt<0><<<dim3(NH3 / 128, NV / 128), 256>>>(
        emb, W_ih_f, (float*)pWp0, NV, NH3, NE, nullptr);
    sgemm_nt<0><<<dim3(NH3 / 128, NV / 128), 256>>>(
        emb, W_ih_b, (float*)pWp1, NV, NH3, NE, nullptr);

    // Per-gate LayerNorm + input bias, in place + zero h/stats
    ln_k<<<2 * NV * 3, 128>>>(gih_f, beih_f, b_ih_f, gih_b, beih_b, b_ih_b);

    // Persistent bidirectional recurrence
    gru_rec<<<2 * NCD, REC_THREADS, REC_SMEM_BYTES>>>(
        src, W_hh_f, W_hh_b, ghh_f, behh_f, bhh_f, ghh_b, behh_b, bhh_b, out);

    // Output projection with tanh epilogue
    sgemm_nt<1><<<dim3(NH / 128, (NS * NB) / 128), 256>>>(
        (const float*)pGru, W_out, out, NS * NB, NH, 2 * NH, b_out);
}

// round 6
// speedup vs baseline: 1.5129x; 1.2535x over previous
#include <cuda_runtime.h>
#include <math.h>

// Problem sizes
constexpr int NS = 1024;   // sequence length
constexpr int NB = 64;     // batch
constexpr int NE = 512;    // embed dim
constexpr int NH = 512;    // hidden
constexpr int NH3 = 3 * NH;
constexpr int NV = 32000;  // vocab
constexpr int NCD = 64;    // CTAs per direction (each owns 8 j-cols x 3 gates)
constexpr int JS = 8;      // j columns per CTA
constexpr int NROW = 24;   // W rows per CTA (3 gates x JS)
constexpr int REC_THREADS = 512;
// smem floats: W 24x512 | h padded 64x129 fl4 | pacc 3x64x25 | hps 64x25
constexpr int SM_W = 0;
constexpr int SM_H = 12288;
constexpr int SM_PACC = SM_H + 33024;   // 45312
constexpr int SM_HPS = SM_PACC + 4800;  // 50112
constexpr int REC_SMEM_BYTES = (SM_HPS + 1600) * 4;  // 206848

// ----------------------------------------------------------------------------
// Packed fp32x2 helpers (full fp32 precision, 2 MACs / instruction)
// ----------------------------------------------------------------------------
__device__ __forceinline__ unsigned long long splat2(float x) {
    unsigned long long r;
    asm("mov.b64 %0, {%1, %1};" : "=l"(r) : "f"(x));
    return r;
}
__device__ __forceinline__ void ffma2(unsigned long long& d,
                                      unsigned long long a,
                                      unsigned long long b) {
    asm("fma.rn.f32x2 %0, %1, %2, %0;" : "+l"(d) : "l"(a), "l"(b));
}
__device__ __forceinline__ float2 un2(unsigned long long v) {
    float2 f;
    asm("mov.b64 {%0, %1}, %2;" : "=f"(f.x), "=f"(f.y) : "l"(v));
    return f;
}

// ----------------------------------------------------------------------------
// Device scratch
// ----------------------------------------------------------------------------
__device__ float g_Wp0[(size_t)NV * NH3];
__device__ float g_Wp1[(size_t)NV * NH3];
__device__ float g_gru[(size_t)NS * NB * 2 * NH];
__device__ float g_h[2][NB * NH];
__device__ float g_stats[2][2][NB * 3 * 2];  // [parity][dir][b*6 + gate*2 + {sum,sq}]
__device__ unsigned g_ctrS[2];
__device__ unsigned g_ctrH[2];

// ----------------------------------------------------------------------------
// Acquire/release grid barrier primitives (monotonic counters, no fences)
// ----------------------------------------------------------------------------
__device__ __forceinline__ void bar_arrive(unsigned* c) {
    __syncthreads();
    if (threadIdx.x == 0)
        asm volatile("red.release.gpu.global.add.u32 [%0], 1;" :: "l"(c) : "memory");
}
__device__ __forceinline__ void bar_wait(unsigned* c, unsigned tgt) {
    if (threadIdx.x == 0) {
        unsigned v;
        do {
            asm volatile("ld.acquire.gpu.global.u32 %0, [%1];" : "=r"(v) : "l"(c) : "memory");
        } while (v < tgt);
    }
    __syncthreads();
}

// ----------------------------------------------------------------------------
// SGEMM: C[M,N] = A[M,K] * Bw[N,K]^T, FFMA2, double-buffered.
// EPI=1: C = tanh(C + bias[n]).
// ----------------------------------------------------------------------------
template <int EPI>
__global__ void __launch_bounds__(256) sgemm_nt(
    const float* __restrict__ A, const float* __restrict__ Bw,
    float* __restrict__ C, int M, int N, int K, const float* __restrict__ bias)
{
    __shared__ __align__(16) float As[2][8][128];
    __shared__ __align__(16) float Bs[2][8][128];
    int tid = threadIdx.x;
    int lrow = tid >> 1;
    int lcol = (tid & 1) * 4;
    int tr = (tid >> 4) << 3;
    int tc = (tid & 15) << 3;
    const float* Ab = A + (size_t)blockIdx.y * 128 * K + (size_t)lrow * K + lcol;
    const float* Bb = Bw + (size_t)blockIdx.x * 128 * K + (size_t)lrow * K + lcol;

    unsigned long long acc2[8][4];
#pragma unroll
    for (int i = 0; i < 8; i++)
#pragma unroll
        for (int j = 0; j < 4; j++) acc2[i][j] = 0ull;

    {
        float4 av = *(const float4*)Ab;
        float4 bv = *(const float4*)Bb;
        As[0][lcol + 0][lrow] = av.x; As[0][lcol + 1][lrow] = av.y;
        As[0][lcol + 2][lrow] = av.z; As[0][lcol + 3][lrow] = av.w;
        Bs[0][lcol + 0][lrow] = bv.x; Bs[0][lcol + 1][lrow] = bv.y;
        Bs[0][lcol + 2][lrow] = bv.z; Bs[0][lcol + 3][lrow] = bv.w;
    }
    __syncthreads();

    int nk = K >> 3;
    for (int kc = 0; kc < nk; kc++) {
        int cur = kc & 1;
        float4 av2, bv2;
        bool more = (kc + 1 < nk);
        if (more) {
            av2 = *(const float4*)(Ab + (kc + 1) * 8);
            bv2 = *(const float4*)(Bb + (kc + 1) * 8);
        }
#pragma unroll
        for (int k = 0; k < 8; k++) {
            float4 a0 = *(const float4*)&As[cur][k][tr];
            float4 a1 = *(const float4*)&As[cur][k][tr + 4];
            ulonglong2 b0 = *(const ulonglong2*)&Bs[cur][k][tc];
            ulonglong2 b1 = *(const ulonglong2*)&Bs[cur][k][tc + 4];
            float ra[8] = {a0.x, a0.y, a0.z, a0.w, a1.x, a1.y, a1.z, a1.w};
            unsigned long long pb[4] = {b0.x, b0.y, b1.x, b1.y};
#pragma unroll
            for (int i = 0; i < 8; i++) {
                unsigned long long sa = splat2(ra[i]);
#pragma unroll
                for (int j = 0; j < 4; j++) ffma2(acc2[i][j], sa, pb[j]);
            }
        }
        if (more) {
            int nxt = cur ^ 1;
            As[nxt][lcol + 0][lrow] = av2.x; As[nxt][lcol + 1][lrow] = av2.y;
            As[nxt][lcol + 2][lrow] = av2.z; As[nxt][lcol + 3][lrow] = av2.w;
            Bs[nxt][lcol + 0][lrow] = bv2.x; Bs[nxt][lcol + 1][lrow] = bv2.y;
            Bs[nxt][lcol + 2][lrow] = bv2.z; Bs[nxt][lcol + 3][lrow] = bv2.w;
        }
        __syncthreads();
    }

#pragma unroll
    for (int i = 0; i < 8; i++) {
        size_t crow = (size_t)(blockIdx.y * 128 + tr + i) * N + blockIdx.x * 128 + tc;
        float cv[8];
#pragma unroll
        for (int j = 0; j < 4; j++) {
            float2 p = un2(acc2[i][j]);
            cv[2 * j] = p.x; cv[2 * j + 1] = p.y;
        }
#pragma unroll
        for (int j = 0; j < 8; j += 4) {
            float4 v;
            v.x = cv[j]; v.y = cv[j + 1]; v.z = cv[j + 2]; v.w = cv[j + 3];
            if (EPI) {
                int nb = blockIdx.x * 128 + tc + j;
                v.x = tanhf(v.x + bias[nb]);
                v.y = tanhf(v.y + bias[nb + 1]);
                v.z = tanhf(v.z + bias[nb + 2]);
                v.w = tanhf(v.w + bias[nb + 3]);
            }
            *(float4*)(C + crow + j) = v;
        }
    }
}

// ----------------------------------------------------------------------------
// LayerNorm over vocab projection rows (per gate), in place.
// Fused init duties: zero h, stats, and barrier counters.
// ----------------------------------------------------------------------------
__global__ void ln_k(const float* __restrict__ gA, const float* __restrict__ beA,
                     const float* __restrict__ bA, const float* __restrict__ gB,
                     const float* __restrict__ beB, const float* __restrict__ bB)
{
    int row = blockIdx.x;               // 0 .. 2*NV*3-1
    int tid = threadIdx.x;              // 128 threads
    // fused init
    if (row < 512) {
        ((float*)g_h)[row * 128 + tid] = 0.f;
    } else if (row == 512) {
        for (int q = 0; q < 12; q++) ((float*)g_stats)[q * 128 + tid] = 0.f;
        if (tid < 2) { g_ctrS[tid] = 0u; g_ctrH[tid] = 0u; }
    }
    int dir = row >= NV * 3;
    int rem = dir ? row - NV * 3 : row;
    int tok = rem / 3;
    int gate = rem - tok * 3;
    float* p = (dir ? g_Wp1 : g_Wp0) + (size_t)tok * NH3 + gate * NH;
    const float* gg = (dir ? gB : gA) + gate * NH;
    const float* be = (dir ? beB : beA) + gate * NH;
    const float* bi = (dir ? bB : bA) + gate * NH;
    float4 v = ((float4*)p)[tid];
    if (tok == 0) { v.x = 0.f; v.y = 0.f; v.z = 0.f; v.w = 0.f; }
    float sum = v.x + v.y + v.z + v.w;
    float sq = v.x * v.x + v.y * v.y + v.z * v.z + v.w * v.w;
#pragma unroll
    for (int o = 16; o; o >>= 1) {
        sum += __shfl_xor_sync(0xffffffffu, sum, o);
        sq  += __shfl_xor_sync(0xffffffffu, sq, o);
    }
    __shared__ float ss[4], sc[4];
    int w = tid >> 5;
    if ((tid & 31) == 0) { ss[w] = sum; sc[w] = sq; }
    __syncthreads();
    sum = ss[0] + ss[1] + ss[2] + ss[3];
    sq  = sc[0] + sc[1] + sc[2] + sc[3];
    float mu = sum * (1.f / NH);
    float var = sq * (1.f / NH) - mu * mu;
    float rs = rsqrtf(var + 1e-5f);
    int j = tid * 4;
    v.x = (v.x - mu) * rs * gg[j]     + be[j]     + bi[j];
    v.y = (v.y - mu) * rs * gg[j + 1] + be[j + 1] + bi[j + 1];
    v.z = (v.z - mu) * rs * gg[j + 2] + be[j + 2] + bi[j + 2];
    v.w = (v.w - mu) * rs * gg[j + 3] + be[j + 3] + bi[j + 3];
    ((float4*)p)[tid] = v;
}

// ----------------------------------------------------------------------------
// Persistent bidirectional GRU recurrence, j-slice ownership, 512 threads.
// CTA owns j in [cid*8, cid*8+8) for ALL 3 gates; hp stays in smem.
// Sync via monotonic acquire/release counters (2 waits/step).
// ----------------------------------------------------------------------------
__global__ void __launch_bounds__(REC_THREADS, 1) gru_rec(
    const int* __restrict__ src,
    const float* __restrict__ Whh_f, const float* __restrict__ Whh_b,
    const float* __restrict__ ghh_f, const float* __restrict__ behh_f,
    const float* __restrict__ bhh_f, const float* __restrict__ ghh_b,
    const float* __restrict__ behh_b, const float* __restrict__ bhh_b,
    float* __restrict__ dout)
{
    extern __shared__ __align__(16) float sm[];
    float* wsm = sm + SM_W;                  // [24][512]
    float4* hsm4 = (float4*)(sm + SM_H);     // [64][129] padded rows
    float* hsm = sm + SM_H;                  // float view: h[b][k] at b*516+k
    float* pacc = sm + SM_PACC;              // [3][64][25]
    float* hps = sm + SM_HPS;                // [64][25] hp[b][row]

    int dir = blockIdx.x / NCD;
    int cid = blockIdx.x - dir * NCD;
    int tid = threadIdx.x;
    int lane = tid & 31, wid = tid >> 5;
    int jbase = cid * JS;

    const float* Whh  = dir ? Whh_b  : Whh_f;
    const float* ghh  = dir ? ghh_b  : ghh_f;
    const float* behh = dir ? behh_b : behh_f;
    const float* bhh  = dir ? bhh_b  : bhh_f;
    const float* Wp   = dir ? g_Wp1  : g_Wp0;
    float* hglob = g_h[dir];
    unsigned* ctrS = &g_ctrS[dir];
    unsigned* ctrH = &g_ctrH[dir];

    // Preload W rows: row r -> (gate=r>>3, jj=r&7) -> Whh row gate*512+jbase+jj
    for (int idx = tid; idx < NROW * NH; idx += REC_THREADS) {
        int r = idx >> 9, k = idx & (NH - 1);
        int grow = (r >> 3) * NH + jbase + (r & 7);
        wsm[r * NH + k] = Whh[(size_t)grow * NH + k];
    }

    // phase-1 mapping: 16 warps = 4 k-quarters x 4 row-groups-of-6
    int kq = wid >> 2;            // k quarter
    int rgrp = wid & 3;           // row group of 6
    int rbase = rgrp * 6;
    int kb4 = kq * 32;            // k4 range [kb4, kb4+32)
    int b0 = lane, b1 = lane + 32;

    // phase-2 mapping + per-thread constants (1 j per thread)
    int pb = tid >> 3;            // batch
    int jl = tid & 7;             // local j
    float cg[3], cbe[3], cbb[3];
#pragma unroll
    for (int g = 0; g < 3; g++) {
        int j = g * NH + jbase + jl;
        cg[g] = ghh[j]; cbe[g] = behh[j]; cbb[g] = bhh[j];
    }

    // Prefetch x for step 0
    float xv[3];
    {
        int s0 = dir ? (NS - 1) : 0;
        int tok = __ldg(src + s0 * NB + pb);
        const float* xrow = Wp + (size_t)tok * NH3;
#pragma unroll
        for (int g = 0; g < 3; g++) xv[g] = __ldg(xrow + g * NH + jbase + jl);
    }

    for (int t = 0; t < NS; t++) {
        int s = dir ? (NS - 1 - t) : t;
        int par = t & 1;

        // Wait for all h(t) writes (t=0: hglob zeroed by ln_k)
        if (t > 0) bar_wait(ctrH, (unsigned)(NCD * t));
        // Stage h into padded shared rows
        for (int idx = tid; idx < NB * 128; idx += REC_THREADS) {
            int b = idx >> 7, k4 = idx & 127;
            hsm4[b * 129 + k4] = ((const float4*)hglob)[idx];
        }
        __syncthreads();

        // Phase 1: hp[b][r] = sum_k h[b][k] * W[r][k]  (FFMA2, k-pair packed)
        unsigned long long acc2[6][2];
#pragma unroll
        for (int r = 0; r < 6; r++) { acc2[r][0] = 0ull; acc2[r][1] = 0ull; }
#pragma unroll 4
        for (int k4 = kb4; k4 < kb4 + 32; k4++) {
            ulonglong2 h0 = *(const ulonglong2*)&hsm4[b0 * 129 + k4];
            ulonglong2 h1 = *(const ulonglong2*)&hsm4[b1 * 129 + k4];
#pragma unroll
            for (int r = 0; r < 6; r++) {
                ulonglong2 wv = *(const ulonglong2*)&wsm[(rbase + r) * NH + k4 * 4];
                ffma2(acc2[r][0], wv.x, h0.x);
                ffma2(acc2[r][0], wv.y, h0.y);
                ffma2(acc2[r][1], wv.x, h1.x);
                ffma2(acc2[r][1], wv.y, h1.y);
            }
        }
        float accf[6][2];
#pragma unroll
        for (int r = 0; r < 6; r++)
#pragma unroll
            for (int p = 0; p < 2; p++) {
                float2 u = un2(acc2[r][p]);
                accf[r][p] = u.x + u.y;
            }
        if (kq) {
            float* pq = pacc + (kq - 1) * 1600;
#pragma unroll
            for (int r = 0; r < 6; r++) {
                pq[b0 * 25 + rbase + r] = accf[r][0];
                pq[b1 * 25 + rbase + r] = accf[r][1];
            }
        }
        __syncthreads();
        if (!kq) {
#pragma unroll
            for (int r = 0; r < 6; r++) {
                float v0 = accf[r][0], v1 = accf[r][1];
#pragma unroll
                for (int q = 0; q < 3; q++) {
                    v0 += pacc[q * 1600 + b0 * 25 + rbase + r];
                    v1 += pacc[q * 1600 + b1 * 25 + rbase + r];
                }
                hps[b0 * 25 + rbase + r] = v0;
                hps[b1 * 25 + rbase + r] = v1;
            }
        }
        __syncthreads();

        // Partial LN stats for this CTA's 8 j per (b, gate)
        if (tid < 192) {
            int g = tid >> 6, b = tid & 63;
            float sv = 0.f, sq = 0.f;
#pragma unroll
            for (int q = 0; q < 8; q++) {
                float v = hps[b * 25 + g * 8 + q];
                sv += v; sq += v * v;
            }
            float* st = &g_stats[par][dir][b * 6 + g * 2];
            atomicAdd(st, sv);
            atomicAdd(st + 1, sq);
        }
        bar_arrive(ctrS);

        // Prefetch x(t+1) — DRAM latency hidden under the stats wait
        float xn[3];
        if (t + 1 < NS) {
            int sn = dir ? (NS - 2 - t) : (t + 1);
            int tok = __ldg(src + sn * NB + pb);
            const float* xrow = Wp + (size_t)tok * NH3;
#pragma unroll
            for (int g = 0; g < 3; g++) xn[g] = __ldg(xrow + g * NH + jbase + jl);
        }

        bar_wait(ctrS, (unsigned)(NCD * (t + 1)));

        // Phase 2: LN + gates + h update for (pb, jl)
        float hnew;
        {
            const float* st = &g_stats[par][dir][pb * 6];
            float mu0 = st[0] * (1.f / NH);
            float rs0 = rsqrtf(st[1] * (1.f / NH) - mu0 * mu0 + 1e-5f);
            float mu1 = st[2] * (1.f / NH);
            float rs1 = rsqrtf(st[3] * (1.f / NH) - mu1 * mu1 + 1e-5f);
            float mu2 = st[4] * (1.f / NH);
            float rs2 = rsqrtf(st[5] * (1.f / NH) - mu2 * mu2 + 1e-5f);
            int j = jbase + jl;
            float hr = (hps[pb * 25 + jl]      - mu0) * rs0 * cg[0] + cbe[0] + cbb[0];
            float hz = (hps[pb * 25 + 8 + jl]  - mu1) * rs1 * cg[1] + cbe[1] + cbb[1];
            float hn = (hps[pb * 25 + 16 + jl] - mu2) * rs2 * cg[2] + cbe[2] + cbb[2];
            float r = 1.f / (1.f + __expf(-(xv[0] + hr)));
            float z = 1.f / (1.f + __expf(-(xv[1] + hz)));
            float n = tanhf(xv[2] + r * hn);
            float ho = hsm[pb * 516 + j];
            hnew = (1.f - z) * n + z * ho;
            hglob[pb * NH + j] = hnew;
        }
        // zero opposite-parity stats for next step (first CTA of each dir)
        if (cid == 0 && tid < NB * 6) g_stats[par ^ 1][dir][tid] = 0.f;
        bar_arrive(ctrH);

        // Off-critical-path stores
        {
            int j = jbase + jl;
            g_gru[((size_t)s * NB + pb) * (2 * NH) + dir * NH + j] = hnew;
            if (t == NS - 1)
                dout[(size_t)NS * NB * NH + (size_t)dir * NB * NH + pb * NH + j] = hnew;
        }
        xv[0] = xn[0]; xv[1] = xn[1]; xv[2] = xn[2];
    }
}

// ----------------------------------------------------------------------------
// Launch
// ----------------------------------------------------------------------------
extern "C" void kernel_launch(void* const* d_in, const int* in_sizes, int n_in,
                              void* d_out, int out_size) {
    (void)in_sizes; (void)n_in; (void)out_size;
    const int*   src    = (const int*)  d_in[0];
    const float* emb    = (const float*)d_in[1];
    const float* W_ih_f = (const float*)d_in[2];
    const float* W_hh_f = (const float*)d_in[3];
    const float* b_ih_f = (const float*)d_in[4];
    const float* bhh_f  = (const float*)d_in[5];
    const float* gih_f  = (const float*)d_in[6];
    const float* beih_f = (const float*)d_in[7];
    const float* ghh_f  = (const float*)d_in[8];
    const float* behh_f = (const float*)d_in[9];
    const float* W_ih_b = (const float*)d_in[10];
    const float* W_hh_b = (const float*)d_in[11];
    const float* b_ih_b = (const float*)d_in[12];
    const float* bhh_b  = (const float*)d_in[13];
    const float* gih_b  = (const float*)d_in[14];
    const float* beih_b = (const float*)d_in[15];
    const float* ghh_b  = (const float*)d_in[16];
    const float* behh_b = (const float*)d_in[17];
    const float* W_out  = (const float*)d_in[18];
    const float* b_out  = (const float*)d_in[19];
    float* out = (float*)d_out;

    void *pWp0, *pWp1, *pGru;
    cudaGetSymbolAddress(&pWp0, g_Wp0);
    cudaGetSymbolAddress(&pWp1, g_Wp1);
    cudaGetSymbolAddress(&pGru, g_gru);
    cudaFuncSetAttribute(gru_rec, cudaFuncAttributeMaxDynamicSharedMemorySize,
                         REC_SMEM_BYTES);

    // Vocab-level input projection: Wp = emb @ W_ih^T  (32000 x 1536, K=512)
    sgemm_nt<0><<<dim3(NH3 / 128, NV / 128), 256>>>(
        emb, W_ih_f, (float*)pWp0, NV, NH3, NE, nullptr);
    sgemm_nt<0><<<dim3(NH3 / 128, NV / 128), 256>>>(
        emb, W_ih_b, (float*)pWp1, NV, NH3, NE, nullptr);

    // Per-gate LayerNorm + input bias, in place + zero h/stats/counters
    ln_k<<<2 * NV * 3, 128>>>(gih_f, beih_f, b_ih_f, gih_b, beih_b, b_ih_b);

    // Persistent bidirectional recurrence
    gru_rec<<<2 * NCD, REC_THREADS, REC_SMEM_BYTES>>>(
        src, W_hh_f, W_hh_b, ghh_f, behh_f, bhh_f, ghh_b, behh_b, bhh_b, out);

    // Output projection with tanh epilogue
    sgemm_nt<1><<<dim3(NH / 128, (NS * NB) / 128), 256>>>(
        (const float*)pGru, W_out, out, NS * NB, NH, 2 * NH, b_out);
}

// round 8
// speedup vs baseline: 1.6482x; 1.0894x over previous
#include <cuda_runtime.h>
#include <math.h>

// Problem sizes
constexpr int NS = 1024;   // sequence length
constexpr int NB = 64;     // batch
constexpr int NE = 512;    // embed dim
constexpr int NH = 512;    // hidden
constexpr int NH3 = 3 * NH;
constexpr int NV = 32000;  // vocab
// Recurrence decomposition: 4 independent groups = 2 dirs x 2 batch-halves.
// Each group: 32 CTAs x 32 batches; CTA owns 16 j-cols x 3 gates (48 W rows).
constexpr int NCG = 32;    // CTAs per group
constexpr int NGB = 32;    // batches per group
constexpr int JS = 16;     // j columns per CTA
constexpr int NROW = 48;   // W rows per CTA
constexpr int REC_THREADS = 512;
// smem floats: W 48x512 | h padded 32x129 fl4 | pacc [3][32][49] | hps [32][49]
constexpr int SM_W = 0;
constexpr int SM_H = NROW * NH;          // 24576
constexpr int SM_PACC = SM_H + 16512;    // 41088
constexpr int SM_HPS = SM_PACC + 4704;   // 45792
constexpr int REC_SMEM_BYTES = (SM_HPS + 1568) * 4;  // 189440

// ----------------------------------------------------------------------------
// Packed fp32x2 helpers (full fp32 precision, 2 MACs / instruction)
// ----------------------------------------------------------------------------
__device__ __forceinline__ unsigned long long splat2(float x) {
    unsigned long long r;
    asm("mov.b64 %0, {%1, %1};" : "=l"(r) : "f"(x));
    return r;
}
__device__ __forceinline__ void ffma2(unsigned long long& d,
                                      unsigned long long a,
                                      unsigned long long b) {
    asm("fma.rn.f32x2 %0, %1, %2, %0;" : "+l"(d) : "l"(a), "l"(b));
}
__device__ __forceinline__ float2 un2(unsigned long long v) {
    float2 f;
    asm("mov.b64 {%0, %1}, %2;" : "=f"(f.x), "=f"(f.y) : "l"(v));
    return f;
}

// ----------------------------------------------------------------------------
// Device scratch
// ----------------------------------------------------------------------------
__device__ float g_Wp0[(size_t)NV * NH3];
__device__ float g_Wp1[(size_t)NV * NH3];
__device__ float g_gru[(size_t)NS * NB * 2 * NH];
__device__ float g_h[2][NB * NH];
__device__ float g_stats[2][4][NGB * 3 * 2];  // [parity][group][b*6 + gate*2 + {sum,sq}]
__device__ unsigned g_ctrS[4];
__device__ unsigned g_ctrH[4];

// ----------------------------------------------------------------------------
// Acquire/release grid barrier primitives (monotonic counters)
// ----------------------------------------------------------------------------
__device__ __forceinline__ void bar_arrive(unsigned* c) {
    __syncthreads();
    if (threadIdx.x == 0)
        asm volatile("red.release.gpu.global.add.u32 [%0], 1;" :: "l"(c) : "memory");
}
__device__ __forceinline__ void bar_wait(unsigned* c, unsigned tgt) {
    if (threadIdx.x == 0) {
        unsigned v;
        do {
            asm volatile("ld.acquire.gpu.global.u32 %0, [%1];" : "=r"(v) : "l"(c) : "memory");
        } while (v < tgt);
    }
    __syncthreads();
}

// ----------------------------------------------------------------------------
// SGEMM: C[M,N] = A[M,K] * Bw[N,K]^T, FFMA2, double-buffered.
// EPI=1: C = tanh(C + bias[n]).
// ----------------------------------------------------------------------------
template <int EPI>
__global__ void __launch_bounds__(256) sgemm_nt(
    const float* __restrict__ A, const float* __restrict__ Bw,
    float* __restrict__ C, int M, int N, int K, const float* __restrict__ bias)
{
    __shared__ __align__(16) float As[2][8][128];
    __shared__ __align__(16) float Bs[2][8][128];
    int tid = threadIdx.x;
    int lrow = tid >> 1;
    int lcol = (tid & 1) * 4;
    int tr = (tid >> 4) << 3;
    int tc = (tid & 15) << 3;
    const float* Ab = A + (size_t)blockIdx.y * 128 * K + (size_t)lrow * K + lcol;
    const float* Bb = Bw + (size_t)blockIdx.x * 128 * K + (size_t)lrow * K + lcol;

    unsigned long long acc2[8][4];
#pragma unroll
    for (int i = 0; i < 8; i++)
#pragma unroll
        for (int j = 0; j < 4; j++) acc2[i][j] = 0ull;

    {
        float4 av = *(const float4*)Ab;
        float4 bv = *(const float4*)Bb;
        As[0][lcol + 0][lrow] = av.x; As[0][lcol + 1][lrow] = av.y;
        As[0][lcol + 2][lrow] = av.z; As[0][lcol + 3][lrow] = av.w;
        Bs[0][lcol + 0][lrow] = bv.x; Bs[0][lcol + 1][lrow] = bv.y;
        Bs[0][lcol + 2][lrow] = bv.z; Bs[0][lcol + 3][lrow] = bv.w;
    }
    __syncthreads();

    int nk = K >> 3;
    for (int kc = 0; kc < nk; kc++) {
        int cur = kc & 1;
        float4 av2, bv2;
        bool more = (kc + 1 < nk);
        if (more) {
            av2 = *(const float4*)(Ab + (kc + 1) * 8);
            bv2 = *(const float4*)(Bb + (kc + 1) * 8);
        }
#pragma unroll
        for (int k = 0; k < 8; k++) {
            float4 a0 = *(const float4*)&As[cur][k][tr];
            float4 a1 = *(const float4*)&As[cur][k][tr + 4];
            ulonglong2 b0 = *(const ulonglong2*)&Bs[cur][k][tc];
            ulonglong2 b1 = *(const ulonglong2*)&Bs[cur][k][tc + 4];
            float ra[8] = {a0.x, a0.y, a0.z, a0.w, a1.x, a1.y, a1.z, a1.w};
            unsigned long long pb[4] = {b0.x, b0.y, b1.x, b1.y};
#pragma unroll
            for (int i = 0; i < 8; i++) {
                unsigned long long sa = splat2(ra[i]);
#pragma unroll
                for (int j = 0; j < 4; j++) ffma2(acc2[i][j], sa, pb[j]);
            }
        }
        if (more) {
            int nxt = cur ^ 1;
            As[nxt][lcol + 0][lrow] = av2.x; As[nxt][lcol + 1][lrow] = av2.y;
            As[nxt][lcol + 2][lrow] = av2.z; As[nxt][lcol + 3][lrow] = av2.w;
            Bs[nxt][lcol + 0][lrow] = bv2.x; Bs[nxt][lcol + 1][lrow] = bv2.y;
            Bs[nxt][lcol + 2][lrow] = bv2.z; Bs[nxt][lcol + 3][lrow] = bv2.w;
        }
        __syncthreads();
    }

#pragma unroll
    for (int i = 0; i < 8; i++) {
        size_t crow = (size_t)(blockIdx.y * 128 + tr + i) * N + blockIdx.x * 128 + tc;
        float cv[8];
#pragma unroll
        for (int j = 0; j < 4; j++) {
            float2 p = un2(acc2[i][j]);
            cv[2 * j] = p.x; cv[2 * j + 1] = p.y;
        }
#pragma unroll
        for (int j = 0; j < 8; j += 4) {
            float4 v;
            v.x = cv[j]; v.y = cv[j + 1]; v.z = cv[j + 2]; v.w = cv[j + 3];
            if (EPI) {
                int nb = blockIdx.x * 128 + tc + j;
                v.x = tanhf(v.x + bias[nb]);
                v.y = tanhf(v.y + bias[nb + 1]);
                v.z = tanhf(v.z + bias[nb + 2]);
                v.w = tanhf(v.w + bias[nb + 3]);
            }
            *(float4*)(C + crow + j) = v;
        }
    }
}

// ----------------------------------------------------------------------------
// LayerNorm over vocab projection rows (per gate), in place.
// Fused init: zero h, stats, barrier counters.
// ----------------------------------------------------------------------------
__global__ void ln_k(const float* __restrict__ gA, const float* __restrict__ beA,
                     const float* __restrict__ bA, const float* __restrict__ gB,
                     const float* __restrict__ beB, const float* __restrict__ bB)
{
    int row = blockIdx.x;               // 0 .. 2*NV*3-1
    int tid = threadIdx.x;              // 128 threads
    if (row < 512) {
        ((float*)g_h)[row * 128 + tid] = 0.f;
    } else if (row == 512) {
        for (int q = 0; q < 12; q++) ((float*)g_stats)[q * 128 + tid] = 0.f;
        if (tid < 4) { g_ctrS[tid] = 0u; g_ctrH[tid] = 0u; }
    }
    int dir = row >= NV * 3;
    int rem = dir ? row - NV * 3 : row;
    int tok = rem / 3;
    int gate = rem - tok * 3;
    float* p = (dir ? g_Wp1 : g_Wp0) + (size_t)tok * NH3 + gate * NH;
    const float* gg = (dir ? gB : gA) + gate * NH;
    const float* be = (dir ? beB : beA) + gate * NH;
    const float* bi = (dir ? bB : bA) + gate * NH;
    float4 v = ((float4*)p)[tid];
    if (tok == 0) { v.x = 0.f; v.y = 0.f; v.z = 0.f; v.w = 0.f; }
    float sum = v.x + v.y + v.z + v.w;
    float sq = v.x * v.x + v.y * v.y + v.z * v.z + v.w * v.w;
#pragma unroll
    for (int o = 16; o; o >>= 1) {
        sum += __shfl_xor_sync(0xffffffffu, sum, o);
        sq  += __shfl_xor_sync(0xffffffffu, sq, o);
    }
    __shared__ float ss[4], sc[4];
    int w = tid >> 5;
    if ((tid & 31) == 0) { ss[w] = sum; sc[w] = sq; }
    __syncthreads();
    sum = ss[0] + ss[1] + ss[2] + ss[3];
    sq  = sc[0] + sc[1] + sc[2] + sc[3];
    float mu = sum * (1.f / NH);
    float var = sq * (1.f / NH) - mu * mu;
    float rs = rsqrtf(var + 1e-5f);
    int j = tid * 4;
    v.x = (v.x - mu) * rs * gg[j]     + be[j]     + bi[j];
    v.y = (v.y - mu) * rs * gg[j + 1] + be[j + 1] + bi[j + 1];
    v.z = (v.z - mu) * rs * gg[j + 2] + be[j + 2] + bi[j + 2];
    v.w = (v.w - mu) * rs * gg[j + 3] + be[j + 3] + bi[j + 3];
    ((float4*)p)[tid] = v;
}

// ----------------------------------------------------------------------------
// Persistent GRU recurrence: 4 independent groups (dir x batch-half),
// 32 CTAs x 32 batches each. CTA owns 16 j for all 3 gates (48 W rows).
// hp stays in smem; only LN stats cross CTAs; 2 narrow barriers/step.
// ----------------------------------------------------------------------------
__global__ void __launch_bounds__(REC_THREADS, 1) gru_rec(
    const int* __restrict__ src,
    const float* __restrict__ Whh_f, const float* __restrict__ Whh_b,
    const float* __restrict__ ghh_f, const float* __restrict__ behh_f,
    const float* __restrict__ bhh_f, const float* __restrict__ ghh_b,
    const float* __restrict__ behh_b, const float* __restrict__ bhh_b,
    float* __restrict__ dout)
{
    extern __shared__ __align__(16) float sm[];
    float* wsm = sm + SM_W;                        // [48][512]
    float4* hsm4 = (float4*)(sm + SM_H);           // [32][129] padded
    float* hsm = sm + SM_H;                        // h[b][k] at b*516+k
    float* pacc = sm + SM_PACC;                    // [3][32][49]
    float* hps = sm + SM_HPS;                      // [32][49]

    int grp = blockIdx.x >> 5;         // 0..3
    int cid = blockIdx.x & 31;
    int dir = grp >> 1, bh = grp & 1;
    int tid = threadIdx.x;
    int lane = tid & 31, wid = tid >> 5;
    int jbase = cid * JS;

    const float* Whh  = dir ? Whh_b  : Whh_f;
    const float* ghh  = dir ? ghh_b  : ghh_f;
    const float* behh = dir ? behh_b : behh_f;
    const float* bhh  = dir ? bhh_b  : bhh_f;
    const float* Wp   = dir ? g_Wp1  : g_Wp0;
    float* hg = g_h[dir] + bh * NGB * NH;          // group's 32 batches
    const float4* hg4 = (const float4*)hg;
    unsigned* ctrS = &g_ctrS[grp];
    unsigned* ctrH = &g_ctrH[grp];

    // Preload W rows: r = gate*16 + jj  ->  Whh row gate*512 + jbase + jj
    for (int idx = tid; idx < NROW * NH; idx += REC_THREADS) {
        int r = idx >> 9, k = idx & (NH - 1);
        int grow = (r >> 4) * NH + jbase + (r & 15);
        wsm[r * NH + k] = Whh[(size_t)grow * NH + k];
    }

    // phase-1 mapping: 16 warps = 4 k-quarters x 4 row-groups-of-12
    int kq = wid >> 2;
    int rbase = (wid & 3) * 12;
    int kb4 = kq * 32;
    int qtid = tid & 127;              // thread index within quarter group

    // phase-2 mapping + constants (1 j per thread)
    int pb = tid >> 4;                 // local batch 0..31
    int jl = tid & 15;                 // local j 0..15
    float cg[3], cbe[3], cbb[3];
#pragma unroll
    for (int g = 0; g < 3; g++) {
        int j = g * NH + jbase + jl;
        cg[g] = ghh[j]; cbe[g] = behh[j]; cbb[g] = bhh[j];
    }

    // Prefetch x for step 0
    float xv[3];
    {
        int s0 = dir ? (NS - 1) : 0;
        int tok = __ldg(src + s0 * NB + bh * NGB + pb);
        const float* xrow = Wp + (size_t)tok * NH3;
#pragma unroll
        for (int g = 0; g < 3; g++) xv[g] = __ldg(xrow + g * NH + jbase + jl);
    }

    for (int t = 0; t < NS; t++) {
        int s = dir ? (NS - 1 - t) : t;
        int par = t & 1;

        if (t > 0) bar_wait(ctrH, (unsigned)(NCG * t));

        // Stage only this quarter's h-slice (32 b x 32 k4), then named barrier
#pragma unroll
        for (int i = 0; i < 8; i++) {
            int idx = qtid + i * 128;
            int k4l = idx & 31, b = idx >> 5;
            hsm4[b * 129 + kb4 + k4l] = hg4[b * 128 + kb4 + k4l];
        }
        asm volatile("bar.sync %0, %1;" :: "r"(kq + 1), "r"(128) : "memory");

        // Phase 1: hp[b][r] = sum_k h[b][k] * W[r][k]  (FFMA2)
        unsigned long long acc2[12];
#pragma unroll
        for (int r = 0; r < 12; r++) acc2[r] = 0ull;
#pragma unroll 4
        for (int k4 = kb4; k4 < kb4 + 32; k4++) {
            ulonglong2 hv = ((const ulonglong2*)hsm4)[lane * 129 + k4];
#pragma unroll
            for (int r = 0; r < 12; r++) {
                ulonglong2 wv = *(const ulonglong2*)&wsm[(rbase + r) * NH + k4 * 4];
                ffma2(acc2[r], wv.x, hv.x);
                ffma2(acc2[r], wv.y, hv.y);
            }
        }
        float accf[12];
#pragma unroll
        for (int r = 0; r < 12; r++) {
            float2 u = un2(acc2[r]);
            accf[r] = u.x + u.y;
        }
        if (kq) {
            float* pq = pacc + (kq - 1) * 1568;
#pragma unroll
            for (int r = 0; r < 12; r++) pq[lane * 49 + rbase + r] = accf[r];
        }
        __syncthreads();
        if (!kq) {
#pragma unroll
            for (int r = 0; r < 12; r++) {
                float v = accf[r];
#pragma unroll
                for (int q = 0; q < 3; q++) v += pacc[q * 1568 + lane * 49 + rbase + r];
                hps[lane * 49 + rbase + r] = v;
            }
        }
        __syncthreads();

        // Partial LN stats (16 j per (b,gate)); one atomic pair per (b,gate)
        if (tid < 96) {
            int g = tid >> 5, b = tid & 31;
            float sv = 0.f, sq = 0.f;
#pragma unroll
            for (int q = 0; q < 16; q++) {
                float v = hps[b * 49 + g * 16 + q];
                sv += v; sq += v * v;
            }
            float* st = &g_stats[par][grp][b * 6 + g * 2];
            atomicAdd(st, sv);
            atomicAdd(st + 1, sq);
        }
        bar_arrive(ctrS);

        // Prefetch x(t+1) under the stats wait
        float xn[3];
        if (t + 1 < NS) {
            int sn = dir ? (NS - 2 - t) : (t + 1);
            int tok = __ldg(src + sn * NB + bh * NGB + pb);
            const float* xrow = Wp + (size_t)tok * NH3;
#pragma unroll
            for (int g = 0; g < 3; g++) xn[g] = __ldg(xrow + g * NH + jbase + jl);
        }

        bar_wait(ctrS, (unsigned)(NCG * (t + 1)));

        // Phase 2: LN + gates + h update for (pb, jl)
        float hnew;
        {
            const float* st = &g_stats[par][grp][pb * 6];
            float mu0 = st[0] * (1.f / NH);
            float rs0 = rsqrtf(st[1] * (1.f / NH) - mu0 * mu0 + 1e-5f);
            float mu1 = st[2] * (1.f / NH);
            float rs1 = rsqrtf(st[3] * (1.f / NH) - mu1 * mu1 + 1e-5f);
            float mu2 = st[4] * (1.f / NH);
            float rs2 = rsqrtf(st[5] * (1.f / NH) - mu2 * mu2 + 1e-5f);
            int j = jbase + jl;
            float hr = (hps[pb * 49 + jl]      - mu0) * rs0 * cg[0] + cbe[0] + cbb[0];
            float hz = (hps[pb * 49 + 16 + jl] - mu1) * rs1 * cg[1] + cbe[1] + cbb[1];
            float hn = (hps[pb * 49 + 32 + jl] - mu2) * rs2 * cg[2] + cbe[2] + cbb[2];
            float r = 1.f / (1.f + __expf(-(xv[0] + hr)));
            float z = 1.f / (1.f + __expf(-(xv[1] + hz)));
            float n = tanhf(xv[2] + r * hn);
            float ho = hsm[pb * 516 + j];
            hnew = (1.f - z) * n + z * ho;
            hg[pb * NH + j] = hnew;
        }
        // distributed zero of opposite-parity stats (6 floats per CTA)
        if (tid < 6) g_stats[par ^ 1][grp][cid * 6 + tid] = 0.f;
        bar_arrive(ctrH);

        // Off-critical-path stores
        {
            int j = jbase + jl;
            int bglob = bh * NGB + pb;
            g_gru[((size_t)s * NB + bglob) * (2 * NH) + dir * NH + j] = hnew;
            if (t == NS - 1)
                dout[(size_t)NS * NB * NH + (size_t)dir * NB * NH + bglob * NH + j] = hnew;
        }
        xv[0] = xn[0]; xv[1] = xn[1]; xv[2] = xn[2];
    }
}

// ----------------------------------------------------------------------------
// Launch
// ----------------------------------------------------------------------------
extern "C" void kernel_launch(void* const* d_in, const int* in_sizes, int n_in,
                              void* d_out, int out_size) {
    (void)in_sizes; (void)n_in; (void)out_size;
    const int*   src    = (const int*)  d_in[0];
    const float* emb    = (const float*)d_in[1];
    const float* W_ih_f = (const float*)d_in[2];
    const float* W_hh_f = (const float*)d_in[3];
    const float* b_ih_f = (const float*)d_in[4];
    const float* bhh_f  = (const float*)d_in[5];
    const float* gih_f  = (const float*)d_in[6];
    const float* beih_f = (const float*)d_in[7];
    const float* ghh_f  = (const float*)d_in[8];
    const float* behh_f = (const float*)d_in[9];
    const float* W_ih_b = (const float*)d_in[10];
    const float* W_hh_b = (const float*)d_in[11];
    const float* b_ih_b = (const float*)d_in[12];
    const float* bhh_b  = (const float*)d_in[13];
    const float* gih_b  = (const float*)d_in[14];
    const float* beih_b = (const float*)d_in[15];
    const float* ghh_b  = (const float*)d_in[16];
    const float* behh_b = (const float*)d_in[17];
    const float* W_out  = (const float*)d_in[18];
    const float* b_out  = (const float*)d_in[19];
    float* out = (float*)d_out;

    void *pWp0, *pWp1, *pGru;
    cudaGetSymbolAddress(&pWp0, g_Wp0);
    cudaGetSymbolAddress(&pWp1, g_Wp1);
    cudaGetSymbolAddress(&pGru, g_gru);
    cudaFuncSetAttribute(gru_rec, cudaFuncAttributeMaxDynamicSharedMemorySize,
                         REC_SMEM_BYTES);

    // Vocab-level input projection: Wp = emb @ W_ih^T  (32000 x 1536, K=512)
    sgemm_nt<0><<<dim3(NH3 / 128, NV / 128), 256>>>(
        emb, W_ih_f, (float*)pWp0, NV, NH3, NE, nullptr);
    sgemm_nt<0><<<dim3(NH3 / 128, NV / 128), 256>>>(
        emb, W_ih_b, (float*)pWp1, NV, NH3, NE, nullptr);

    // Per-gate LayerNorm + input bias, in place + zero h/stats/counters
    ln_k<<<2 * NV * 3, 128>>>(gih_f, beih_f, b_ih_f, gih_b, beih_b, b_ih_b);

    // Persistent bidirectional recurrence (4 groups x 32 CTAs)
    gru_rec<<<128, REC_THREADS, REC_SMEM_BYTES>>>(
        src, W_hh_f, W_hh_b, ghh_f, behh_f, bhh_f, ghh_b, behh_b, bhh_b, out);

    // Output projection with tanh epilogue
    sgemm_nt<1><<<dim3(NH / 128, (NS * NB) / 128), 256>>>(
        (const float*)pGru, W_out, out, NS * NB, NH, 2 * NH, b_out);
}

// round 9
// speedup vs baseline: 1.6494x; 1.0007x over previous
#include <cuda_runtime.h>
#include <math.h>

// Problem sizes
constexpr int NS = 1024;   // sequence length
constexpr int NB = 64;     // batch
constexpr int NE = 512;    // embed dim
constexpr int NH = 512;    // hidden
constexpr int NH3 = 3 * NH;
constexpr int NV = 32000;  // vocab
// Recurrence decomposition: 4 independent groups = 2 dirs x 2 batch-halves.
// Each group: 32 CTAs x 32 batches; CTA owns 16 j-cols x 3 gates (48 W rows).
constexpr int NCG = 32;    // CTAs per group
constexpr int NGB = 32;    // batches per group
constexpr int JS = 16;     // j columns per CTA
constexpr int NROW = 48;   // W rows per CTA
constexpr int REC_THREADS = 512;
// smem floats: W 48x512 | h padded 32x129 fl4 | pacc [3][32][49] | hps [32][49]
constexpr int SM_W = 0;
constexpr int SM_H = NROW * NH;          // 24576
constexpr int SM_PACC = SM_H + 16512;    // 41088
constexpr int SM_HPS = SM_PACC + 4704;   // 45792
constexpr int REC_SMEM_BYTES = (SM_HPS + 1568) * 4;  // 189440

// ----------------------------------------------------------------------------
// Packed fp32x2 helpers (full fp32 precision, 2 MACs / instruction)
// ----------------------------------------------------------------------------
__device__ __forceinline__ unsigned long long splat2(float x) {
    unsigned long long r;
    asm("mov.b64 %0, {%1, %1};" : "=l"(r) : "f"(x));
    return r;
}
__device__ __forceinline__ void ffma2(unsigned long long& d,
                                      unsigned long long a,
                                      unsigned long long b) {
    asm("fma.rn.f32x2 %0, %1, %2, %0;" : "+l"(d) : "l"(a), "l"(b));
}
__device__ __forceinline__ float2 un2(unsigned long long v) {
    float2 f;
    asm("mov.b64 {%0, %1}, %2;" : "=f"(f.x), "=f"(f.y) : "l"(v));
    return f;
}

// ----------------------------------------------------------------------------
// Device scratch
// ----------------------------------------------------------------------------
__device__ float g_Wp0[(size_t)NV * NH3];
__device__ float g_Wp1[(size_t)NV * NH3];
__device__ float g_gru[(size_t)NS * NB * 2 * NH];
__device__ float g_h[2][NB * NH];
__device__ float g_stats[2][4][NGB * 3 * 2];  // [parity][group][b*6 + gate*2 + {sum,sq}]
__device__ unsigned g_ctrS[4];
__device__ unsigned g_ctrH[4];

// ----------------------------------------------------------------------------
// Acquire/release grid barrier primitives (monotonic counters)
// ----------------------------------------------------------------------------
__device__ __forceinline__ void bar_arrive(unsigned* c) {
    __syncthreads();
    if (threadIdx.x == 0)
        asm volatile("red.release.gpu.global.add.u32 [%0], 1;" :: "l"(c) : "memory");
}
__device__ __forceinline__ void bar_wait(unsigned* c, unsigned tgt) {
    if (threadIdx.x == 0) {
        unsigned v;
        do {
            asm volatile("ld.acquire.gpu.global.u32 %0, [%1];" : "=r"(v) : "l"(c) : "memory");
        } while (v < tgt);
    }
    __syncthreads();
}

// ----------------------------------------------------------------------------
// SGEMM: C[M,N] = A[M,K] * Bw[N,K]^T, FFMA2, double-buffered.
// EPI=1: C = tanh(C + bias[n]).
// ----------------------------------------------------------------------------
template <int EPI>
__global__ void __launch_bounds__(256) sgemm_nt(
    const float* __restrict__ A, const float* __restrict__ Bw,
    float* __restrict__ C, int M, int N, int K, const float* __restrict__ bias)
{
    __shared__ __align__(16) float As[2][8][128];
    __shared__ __align__(16) float Bs[2][8][128];
    int tid = threadIdx.x;
    int lrow = tid >> 1;
    int lcol = (tid & 1) * 4;
    int tr = (tid >> 4) << 3;
    int tc = (tid & 15) << 3;
    const float* Ab = A + (size_t)blockIdx.y * 128 * K + (size_t)lrow * K + lcol;
    const float* Bb = Bw + (size_t)blockIdx.x * 128 * K + (size_t)lrow * K + lcol;

    unsigned long long acc2[8][4];
#pragma unroll
    for (int i = 0; i < 8; i++)
#pragma unroll
        for (int j = 0; j < 4; j++) acc2[i][j] = 0ull;

    {
        float4 av = *(const float4*)Ab;
        float4 bv = *(const float4*)Bb;
        As[0][lcol + 0][lrow] = av.x; As[0][lcol + 1][lrow] = av.y;
        As[0][lcol + 2][lrow] = av.z; As[0][lcol + 3][lrow] = av.w;
        Bs[0][lcol + 0][lrow] = bv.x; Bs[0][lcol + 1][lrow] = bv.y;
        Bs[0][lcol + 2][lrow] = bv.z; Bs[0][lcol + 3][lrow] = bv.w;
    }
    __syncthreads();

    int nk = K >> 3;
    for (int kc = 0; kc < nk; kc++) {
        int cur = kc & 1;
        float4 av2, bv2;
        bool more = (kc + 1 < nk);
        if (more) {
            av2 = *(const float4*)(Ab + (kc + 1) * 8);
            bv2 = *(const float4*)(Bb + (kc + 1) * 8);
        }
#pragma unroll
        for (int k = 0; k < 8; k++) {
            float4 a0 = *(const float4*)&As[cur][k][tr];
            float4 a1 = *(const float4*)&As[cur][k][tr + 4];
            ulonglong2 b0 = *(const ulonglong2*)&Bs[cur][k][tc];
            ulonglong2 b1 = *(const ulonglong2*)&Bs[cur][k][tc + 4];
            float ra[8] = {a0.x, a0.y, a0.z, a0.w, a1.x, a1.y, a1.z, a1.w};
            unsigned long long pb[4] = {b0.x, b0.y, b1.x, b1.y};
#pragma unroll
            for (int i = 0; i < 8; i++) {
                unsigned long long sa = splat2(ra[i]);
#pragma unroll
                for (int j = 0; j < 4; j++) ffma2(acc2[i][j], sa, pb[j]);
            }
        }
        if (more) {
            int nxt = cur ^ 1;
            As[nxt][lcol + 0][lrow] = av2.x; As[nxt][lcol + 1][lrow] = av2.y;
            As[nxt][lcol + 2][lrow] = av2.z; As[nxt][lcol + 3][lrow] = av2.w;
            Bs[nxt][lcol + 0][lrow] = bv2.x; Bs[nxt][lcol + 1][lrow] = bv2.y;
            Bs[nxt][lcol + 2][lrow] = bv2.z; Bs[nxt][lcol + 3][lrow] = bv2.w;
        }
        __syncthreads();
    }

#pragma unroll
    for (int i = 0; i < 8; i++) {
        size_t crow = (size_t)(blockIdx.y * 128 + tr + i) * N + blockIdx.x * 128 + tc;
        float cv[8];
#pragma unroll
        for (int j = 0; j < 4; j++) {
            float2 p = un2(acc2[i][j]);
            cv[2 * j] = p.x; cv[2 * j + 1] = p.y;
        }
#pragma unroll
        for (int j = 0; j < 8; j += 4) {
            float4 v;
            v.x = cv[j]; v.y = cv[j + 1]; v.z = cv[j + 2]; v.w = cv[j + 3];
            if (EPI) {
                int nb = blockIdx.x * 128 + tc + j;
                v.x = tanhf(v.x + bias[nb]);
                v.y = tanhf(v.y + bias[nb + 1]);
                v.z = tanhf(v.z + bias[nb + 2]);
                v.w = tanhf(v.w + bias[nb + 3]);
            }
            *(float4*)(C + crow + j) = v;
        }
    }
}

// ----------------------------------------------------------------------------
// LayerNorm over vocab projection rows (per gate), in place.
// Fused init: zero h, stats, barrier counters.
// ----------------------------------------------------------------------------
__global__ void ln_k(const float* __restrict__ gA, const float* __restrict__ beA,
                     const float* __restrict__ bA, const float* __restrict__ gB,
                     const float* __restrict__ beB, const float* __restrict__ bB)
{
    int row = blockIdx.x;               // 0 .. 2*NV*3-1
    int tid = threadIdx.x;              // 128 threads
    if (row < 512) {
        ((float*)g_h)[row * 128 + tid] = 0.f;
    } else if (row == 512) {
        for (int q = 0; q < 12; q++) ((float*)g_stats)[q * 128 + tid] = 0.f;
        if (tid < 4) { g_ctrS[tid] = 0u; g_ctrH[tid] = 0u; }
    }
    int dir = row >= NV * 3;
    int rem = dir ? row - NV * 3 : row;
    int tok = rem / 3;
    int gate = rem - tok * 3;
    float* p = (dir ? g_Wp1 : g_Wp0) + (size_t)tok * NH3 + gate * NH;
    const float* gg = (dir ? gB : gA) + gate * NH;
    const float* be = (dir ? beB : beA) + gate * NH;
    const float* bi = (dir ? bB : bA) + gate * NH;
    float4 v = ((float4*)p)[tid];
    if (tok == 0) { v.x = 0.f; v.y = 0.f; v.z = 0.f; v.w = 0.f; }
    float sum = v.x + v.y + v.z + v.w;
    float sq = v.x * v.x + v.y * v.y + v.z * v.z + v.w * v.w;
#pragma unroll
    for (int o = 16; o; o >>= 1) {
        sum += __shfl_xor_sync(0xffffffffu, sum, o);
        sq  += __shfl_xor_sync(0xffffffffu, sq, o);
    }
    __shared__ float ss[4], sc[4];
    int w = tid >> 5;
    if ((tid & 31) == 0) { ss[w] = sum; sc[w] = sq; }
    __syncthreads();
    sum = ss[0] + ss[1] + ss[2] + ss[3];
    sq  = sc[0] + sc[1] + sc[2] + sc[3];
    float mu = sum * (1.f / NH);
    float var = sq * (1.f / NH) - mu * mu;
    float rs = rsqrtf(var + 1e-5f);
    int j = tid * 4;
    v.x = (v.x - mu) * rs * gg[j]     + be[j]     + bi[j];
    v.y = (v.y - mu) * rs * gg[j + 1] + be[j + 1] + bi[j + 1];
    v.z = (v.z - mu) * rs * gg[j + 2] + be[j + 2] + bi[j + 2];
    v.w = (v.w - mu) * rs * gg[j + 3] + be[j + 3] + bi[j + 3];
    ((float4*)p)[tid] = v;
}

// ----------------------------------------------------------------------------
// Persistent GRU recurrence: 4 independent groups (dir x batch-half),
// 32 CTAs x 32 batches each. CTA owns 16 j for all 3 gates (48 W rows).
// hp stays in smem; only LN stats cross CTAs; 2 narrow barriers/step.
// ----------------------------------------------------------------------------
__global__ void __launch_bounds__(REC_THREADS, 1) gru_rec(
    const int* __restrict__ src,
    const float* __restrict__ Whh_f, const float* __restrict__ Whh_b,
    const float* __restrict__ ghh_f, const float* __restrict__ behh_f,
    const float* __restrict__ bhh_f, const float* __restrict__ ghh_b,
    const float* __restrict__ behh_b, const float* __restrict__ bhh_b,
    float* __restrict__ dout)
{
    extern __shared__ __align__(16) float sm[];
    float* wsm = sm + SM_W;                        // [48][512]
    float4* hsm4 = (float4*)(sm + SM_H);           // [32][129] padded
    float* hsm = sm + SM_H;                        // h[b][k] at b*516+k
    float* pacc = sm + SM_PACC;                    // [3][32][49]
    float* hps = sm + SM_HPS;                      // [32][49]

    int grp = blockIdx.x >> 5;         // 0..3
    int cid = blockIdx.x & 31;
    int dir = grp >> 1, bh = grp & 1;
    int tid = threadIdx.x;
    int lane = tid & 31, wid = tid >> 5;
    int jbase = cid * JS;

    const float* Whh  = dir ? Whh_b  : Whh_f;
    const float* ghh  = dir ? ghh_b  : ghh_f;
    const float* behh = dir ? behh_b : behh_f;
    const float* bhh  = dir ? bhh_b  : bhh_f;
    const float* Wp   = dir ? g_Wp1  : g_Wp0;
    float* hg = g_h[dir] + bh * NGB * NH;          // group's 32 batches
    const float4* hg4 = (const float4*)hg;
    unsigned* ctrS = &g_ctrS[grp];
    unsigned* ctrH = &g_ctrH[grp];

    // Preload W rows: r = gate*16 + jj  ->  Whh row gate*512 + jbase + jj
    for (int idx = tid; idx < NROW * NH; idx += REC_THREADS) {
        int r = idx >> 9, k = idx & (NH - 1);
        int grow = (r >> 4) * NH + jbase + (r & 15);
        wsm[r * NH + k] = Whh[(size_t)grow * NH + k];
    }

    // phase-1 mapping: 16 warps = 4 k-quarters x 4 row-groups-of-12
    int kq = wid >> 2;
    int rbase = (wid & 3) * 12;
    int kb4 = kq * 32;
    int qtid = tid & 127;              // thread index within quarter group

    // phase-2 mapping + constants (1 j per thread)
    int pb = tid >> 4;                 // local batch 0..31
    int jl = tid & 15;                 // local j 0..15
    float cg[3], cbe[3], cbb[3];
#pragma unroll
    for (int g = 0; g < 3; g++) {
        int j = g * NH + jbase + jl;
        cg[g] = ghh[j]; cbe[g] = behh[j]; cbb[g] = bhh[j];
    }

    // Prefetch x for step 0
    float xv[3];
    {
        int s0 = dir ? (NS - 1) : 0;
        int tok = __ldg(src + s0 * NB + bh * NGB + pb);
        const float* xrow = Wp + (size_t)tok * NH3;
#pragma unroll
        for (int g = 0; g < 3; g++) xv[g] = __ldg(xrow + g * NH + jbase + jl);
    }

    for (int t = 0; t < NS; t++) {
        int s = dir ? (NS - 1 - t) : t;
        int par = t & 1;

        if (t > 0) bar_wait(ctrH, (unsigned)(NCG * t));

        // Stage only this quarter's h-slice (32 b x 32 k4), then named barrier
#pragma unroll
        for (int i = 0; i < 8; i++) {
            int idx = qtid + i * 128;
            int k4l = idx & 31, b = idx >> 5;
            hsm4[b * 129 + kb4 + k4l] = hg4[b * 128 + kb4 + k4l];
        }
        asm volatile("bar.sync %0, %1;" :: "r"(kq + 1), "r"(128) : "memory");

        // Phase 1: hp[b][r] = sum_k h[b][k] * W[r][k]  (FFMA2)
        unsigned long long acc2[12];
#pragma unroll
        for (int r = 0; r < 12; r++) acc2[r] = 0ull;
#pragma unroll 4
        for (int k4 = kb4; k4 < kb4 + 32; k4++) {
            ulonglong2 hv = ((const ulonglong2*)hsm4)[lane * 129 + k4];
#pragma unroll
            for (int r = 0; r < 12; r++) {
                ulonglong2 wv = *(const ulonglong2*)&wsm[(rbase + r) * NH + k4 * 4];
                ffma2(acc2[r], wv.x, hv.x);
                ffma2(acc2[r], wv.y, hv.y);
            }
        }
        float accf[12];
#pragma unroll
        for (int r = 0; r < 12; r++) {
            float2 u = un2(acc2[r]);
            accf[r] = u.x + u.y;
        }
        if (kq) {
            float* pq = pacc + (kq - 1) * 1568;
#pragma unroll
            for (int r = 0; r < 12; r++) pq[lane * 49 + rbase + r] = accf[r];
        }
        __syncthreads();
        if (!kq) {
#pragma unroll
            for (int r = 0; r < 12; r++) {
                float v = accf[r];
#pragma unroll
                for (int q = 0; q < 3; q++) v += pacc[q * 1568 + lane * 49 + rbase + r];
                hps[lane * 49 + rbase + r] = v;
            }
        }
        __syncthreads();

        // Partial LN stats (16 j per (b,gate)); one atomic pair per (b,gate)
        if (tid < 96) {
            int g = tid >> 5, b = tid & 31;
            float sv = 0.f, sq = 0.f;
#pragma unroll
            for (int q = 0; q < 16; q++) {
                float v = hps[b * 49 + g * 16 + q];
                sv += v; sq += v * v;
            }
            float* st = &g_stats[par][grp][b * 6 + g * 2];
            atomicAdd(st, sv);
            atomicAdd(st + 1, sq);
        }
        bar_arrive(ctrS);

        // Prefetch x(t+1) under the stats wait
        float xn[3];
        if (t + 1 < NS) {
            int sn = dir ? (NS - 2 - t) : (t + 1);
            int tok = __ldg(src + sn * NB + bh * NGB + pb);
            const float* xrow = Wp + (size_t)tok * NH3;
#pragma unroll
            for (int g = 0; g < 3; g++) xn[g] = __ldg(xrow + g * NH + jbase + jl);
        }

        bar_wait(ctrS, (unsigned)(NCG * (t + 1)));

        // Phase 2: LN + gates + h update for (pb, jl)
        float hnew;
        {
            const float* st = &g_stats[par][grp][pb * 6];
            float mu0 = st[0] * (1.f / NH);
            float rs0 = rsqrtf(st[1] * (1.f / NH) - mu0 * mu0 + 1e-5f);
            float mu1 = st[2] * (1.f / NH);
            float rs1 = rsqrtf(st[3] * (1.f / NH) - mu1 * mu1 + 1e-5f);
            float mu2 = st[4] * (1.f / NH);
            float rs2 = rsqrtf(st[5] * (1.f / NH) - mu2 * mu2 + 1e-5f);
            int j = jbase + jl;
            float hr = (hps[pb * 49 + jl]      - mu0) * rs0 * cg[0] + cbe[0] + cbb[0];
            float hz = (hps[pb * 49 + 16 + jl] - mu1) * rs1 * cg[1] + cbe[1] + cbb[1];
            float hn = (hps[pb * 49 + 32 + jl] - mu2) * rs2 * cg[2] + cbe[2] + cbb[2];
            float r = 1.f / (1.f + __expf(-(xv[0] + hr)));
            float z = 1.f / (1.f + __expf(-(xv[1] + hz)));
            float n = tanhf(xv[2] + r * hn);
            float ho = hsm[pb * 516 + j];
            hnew = (1.f - z) * n + z * ho;
            hg[pb * NH + j] = hnew;
        }
        // distributed zero of opposite-parity stats (6 floats per CTA)
        if (tid < 6) g_stats[par ^ 1][grp][cid * 6 + tid] = 0.f;
        bar_arrive(ctrH);

        // Off-critical-path stores
        {
            int j = jbase + jl;
            int bglob = bh * NGB + pb;
            g_gru[((size_t)s * NB + bglob) * (2 * NH) + dir * NH + j] = hnew;
            if (t == NS - 1)
                dout[(size_t)NS * NB * NH + (size_t)dir * NB * NH + bglob * NH + j] = hnew;
        }
        xv[0] = xn[0]; xv[1] = xn[1]; xv[2] = xn[2];
    }
}

// ----------------------------------------------------------------------------
// Launch
// ----------------------------------------------------------------------------
extern "C" void kernel_launch(void* const* d_in, const int* in_sizes, int n_in,
                              void* d_out, int out_size) {
    (void)in_sizes; (void)n_in; (void)out_size;
    const int*   src    = (const int*)  d_in[0];
    const float* emb    = (const float*)d_in[1];
    const float* W_ih_f = (const float*)d_in[2];
    const float* W_hh_f = (const float*)d_in[3];
    const float* b_ih_f = (const float*)d_in[4];
    const float* bhh_f  = (const float*)d_in[5];
    const float* gih_f  = (const float*)d_in[6];
    const float* beih_f = (const float*)d_in[7];
    const float* ghh_f  = (const float*)d_in[8];
    const float* behh_f = (const float*)d_in[9];
    const float* W_ih_b = (const float*)d_in[10];
    const float* W_hh_b = (const float*)d_in[11];
    const float* b_ih_b = (const float*)d_in[12];
    const float* bhh_b  = (const float*)d_in[13];
    const float* gih_b  = (const float*)d_in[14];
    const float* beih_b = (const float*)d_in[15];
    const float* ghh_b  = (const float*)d_in[16];
    const float* behh_b = (const float*)d_in[17];
    const float* W_out  = (const float*)d_in[18];
    const float* b_out  = (const float*)d_in[19];
    float* out = (float*)d_out;

    void *pWp0, *pWp1, *pGru;
    cudaGetSymbolAddress(&pWp0, g_Wp0);
    cudaGetSymbolAddress(&pWp1, g_Wp1);
    cudaGetSymbolAddress(&pGru, g_gru);
    cudaFuncSetAttribute(gru_rec, cudaFuncAttributeMaxDynamicSharedMemorySize,
                         REC_SMEM_BYTES);

    // Vocab-level input projection: Wp = emb @ W_ih^T  (32000 x 1536, K=512)
    sgemm_nt<0><<<dim3(NH3 / 128, NV / 128), 256>>>(
        emb, W_ih_f, (float*)pWp0, NV, NH3, NE, nullptr);
    sgemm_nt<0><<<dim3(NH3 / 128, NV / 128), 256>>>(
        emb, W_ih_b, (float*)pWp1, NV, NH3, NE, nullptr);

    // Per-gate LayerNorm + input bias, in place + zero h/stats/counters
    ln_k<<<2 * NV * 3, 128>>>(gih_f, beih_f, b_ih_f, gih_b, beih_b, b_ih_b);

    // Persistent bidirectional recurrence (4 groups x 32 CTAs)
    gru_rec<<<128, REC_THREADS, REC_SMEM_BYTES>>>(
        src, W_hh_f, W_hh_b, ghh_f, behh_f, bhh_f, ghh_b, behh_b, bhh_b, out);

    // Output projection with tanh epilogue
    sgemm_nt<1><<<dim3(NH / 128, (NS * NB) / 128), 256>>>(
        (const float*)pGru, W_out, out, NS * NB, NH, 2 * NH, b_out);
}

// round 11
// speedup vs baseline: 2.3141x; 1.4030x over previous
#include <cuda_runtime.h>
#include <cuda_bf16.h>
#include <math.h>
#include <stdint.h>

constexpr int NS = 1024, NB = 64, NE = 512, NH = 512, NH3 = 1536, NV = 32000;
constexpr int NCG = 32, NGB = 32, JS = 16, NROW = 48, REC_THREADS = 512;

// smem byte offsets (from 1024-aligned base)
constexpr int OFF_A   = 0;        // A tile: 64 rows x 512 bf16 (row stride 1024B) = 65536
constexpr int OFF_WHI = 65536;    // W_hi: 48 x 512 bf16 = 49152
constexpr int OFF_WLO = 114688;   // W_lo: 49152
constexpr int OFF_P   = 163840;   // partials [2][96][50] f32 = 38400
constexpr int OFF_HPS = 202240;   // hp [32][52] f32 = 6656
constexpr int REC_SMEM_BYTES = 208896 + 1024;

// ---------------- fp32x2 helpers (SGEMM) ----------------
__device__ __forceinline__ unsigned long long splat2(float x) {
    unsigned long long r; asm("mov.b64 %0, {%1, %1};" : "=l"(r) : "f"(x)); return r;
}
__device__ __forceinline__ void ffma2(unsigned long long& d, unsigned long long a,
                                      unsigned long long b) {
    asm("fma.rn.f32x2 %0, %1, %2, %0;" : "+l"(d) : "l"(a), "l"(b));
}
__device__ __forceinline__ float2 un2(unsigned long long v) {
    float2 f; asm("mov.b64 {%0, %1}, %2;" : "=f"(f.x), "=f"(f.y) : "l"(v)); return f;
}

// ---------------- warp mma / ldmatrix (base PTX, sm_80+) ----------------
__device__ __forceinline__ uint32_t smem_u32(const void* p) {
    uint32_t a;
    asm("{ .reg .u64 t; cvta.to.shared.u64 t, %1; cvt.u32.u64 %0, t; }" : "=r"(a) : "l"(p));
    return a;
}
__device__ __forceinline__ void ldsm4(uint32_t* r, uint32_t addr) {
    asm volatile("ldmatrix.sync.aligned.m8n8.x4.shared.b16 {%0,%1,%2,%3}, [%4];"
        : "=r"(r[0]), "=r"(r[1]), "=r"(r[2]), "=r"(r[3]) : "r"(addr));
}
__device__ __forceinline__ void ldsm2(uint32_t* r, uint32_t addr) {
    asm volatile("ldmatrix.sync.aligned.m8n8.x2.shared.b16 {%0,%1}, [%2];"
        : "=r"(r[0]), "=r"(r[1]) : "r"(addr));
}
__device__ __forceinline__ void mma16816(float* d, const uint32_t* a, const uint32_t* b) {
    asm volatile("mma.sync.aligned.m16n8k16.row.col.f32.bf16.bf16.f32 "
        "{%0,%1,%2,%3}, {%4,%5,%6,%7}, {%8,%9}, {%0,%1,%2,%3};"
        : "+f"(d[0]), "+f"(d[1]), "+f"(d[2]), "+f"(d[3])
        : "r"(a[0]), "r"(a[1]), "r"(a[2]), "r"(a[3]), "r"(b[0]), "r"(b[1]));
}
// swizzled byte offset within a bf16 tile (row stride 1024B, XOR on 16B units)
__device__ __forceinline__ uint32_t tile_off(int row, int k4) {
    return (uint32_t)(row * 1024 + ((k4 * 8) ^ ((row & 7) << 4)));
}
__device__ __forceinline__ void bsplit(float4 v, uint2& hi, uint2& lo) {
    __nv_bfloat16 a = __float2bfloat16_rn(v.x), b = __float2bfloat16_rn(v.y),
                  c = __float2bfloat16_rn(v.z), d = __float2bfloat16_rn(v.w);
    __nv_bfloat162 h0 = __halves2bfloat162(a, b), h1 = __halves2bfloat162(c, d);
    hi.x = *(uint32_t*)&h0; hi.y = *(uint32_t*)&h1;
    __nv_bfloat162 l0 = __floats2bfloat162_rn(v.x - __bfloat162float(a), v.y - __bfloat162float(b));
    __nv_bfloat162 l1 = __floats2bfloat162_rn(v.z - __bfloat162float(c), v.w - __bfloat162float(d));
    lo.x = *(uint32_t*)&l0; lo.y = *(uint32_t*)&l1;
}

// ---------------- device scratch ----------------
__device__ float g_Wp0[(size_t)NV * NH3];
__device__ float g_Wp1[(size_t)NV * NH3];
__device__ float g_gru[(size_t)NS * NB * 2 * NH];
__device__ float g_h[2][NB * NH];
__device__ float g_stats[2][4][NGB * 3 * 2];
__device__ unsigned g_ctrS[4];
__device__ unsigned g_ctrH[4];

__device__ __forceinline__ void bar_arrive(unsigned* c) {
    __syncthreads();
    if (threadIdx.x == 0)
        asm volatile("red.release.gpu.global.add.u32 [%0], 1;" :: "l"(c) : "memory");
}
__device__ __forceinline__ void bar_wait(unsigned* c, unsigned tgt) {
    if (threadIdx.x == 0) {
        unsigned v;
        do { asm volatile("ld.acquire.gpu.global.u32 %0, [%1];" : "=r"(v) : "l"(c) : "memory"); }
        while (v < tgt);
    }
    __syncthreads();
}

// ---------------- SGEMM (unchanged) ----------------
template <int EPI>
__global__ void __launch_bounds__(256) sgemm_nt(
    const float* __restrict__ A, const float* __restrict__ Bw,
    float* __restrict__ C, int M, int N, int K, const float* __restrict__ bias)
{
    __shared__ __align__(16) float As[2][8][128];
    __shared__ __align__(16) float Bs[2][8][128];
    int tid = threadIdx.x;
    int lrow = tid >> 1, lcol = (tid & 1) * 4;
    int tr = (tid >> 4) << 3, tc = (tid & 15) << 3;
    const float* Ab = A + (size_t)blockIdx.y * 128 * K + (size_t)lrow * K + lcol;
    const float* Bb = Bw + (size_t)blockIdx.x * 128 * K + (size_t)lrow * K + lcol;
    unsigned long long acc2[8][4];
#pragma unroll
    for (int i = 0; i < 8; i++)
#pragma unroll
        for (int j = 0; j < 4; j++) acc2[i][j] = 0ull;
    {
        float4 av = *(const float4*)Ab, bv = *(const float4*)Bb;
        As[0][lcol + 0][lrow] = av.x; As[0][lcol + 1][lrow] = av.y;
        As[0][lcol + 2][lrow] = av.z; As[0][lcol + 3][lrow] = av.w;
        Bs[0][lcol + 0][lrow] = bv.x; Bs[0][lcol + 1][lrow] = bv.y;
        Bs[0][lcol + 2][lrow] = bv.z; Bs[0][lcol + 3][lrow] = bv.w;
    }
    __syncthreads();
    int nk = K >> 3;
    for (int kc = 0; kc < nk; kc++) {
        int cur = kc & 1;
        float4 av2, bv2;
        bool more = (kc + 1 < nk);
        if (more) {
            av2 = *(const float4*)(Ab + (kc + 1) * 8);
            bv2 = *(const float4*)(Bb + (kc + 1) * 8);
        }
#pragma unroll
        for (int k = 0; k < 8; k++) {
            float4 a0 = *(const float4*)&As[cur][k][tr];
            float4 a1 = *(const float4*)&As[cur][k][tr + 4];
            ulonglong2 b0 = *(const ulonglong2*)&Bs[cur][k][tc];
            ulonglong2 b1 = *(const ulonglong2*)&Bs[cur][k][tc + 4];
            float ra[8] = {a0.x, a0.y, a0.z, a0.w, a1.x, a1.y, a1.z, a1.w};
            unsigned long long pb[4] = {b0.x, b0.y, b1.x, b1.y};
#pragma unroll
            for (int i = 0; i < 8; i++) {
                unsigned long long sa = splat2(ra[i]);
#pragma unroll
                for (int j = 0; j < 4; j++) ffma2(acc2[i][j], sa, pb[j]);
            }
        }
        if (more) {
            int nxt = cur ^ 1;
            As[nxt][lcol + 0][lrow] = av2.x; As[nxt][lcol + 1][lrow] = av2.y;
            As[nxt][lcol + 2][lrow] = av2.z; As[nxt][lcol + 3][lrow] = av2.w;
            Bs[nxt][lcol + 0][lrow] = bv2.x; Bs[nxt][lcol + 1][lrow] = bv2.y;
            Bs[nxt][lcol + 2][lrow] = bv2.z; Bs[nxt][lcol + 3][lrow] = bv2.w;
        }
        __syncthreads();
    }
#pragma unroll
    for (int i = 0; i < 8; i++) {
        size_t crow = (size_t)(blockIdx.y * 128 + tr + i) * N + blockIdx.x * 128 + tc;
        float cv[8];
#pragma unroll
        for (int j = 0; j < 4; j++) { float2 p = un2(acc2[i][j]); cv[2 * j] = p.x; cv[2 * j + 1] = p.y; }
#pragma unroll
        for (int j = 0; j < 8; j += 4) {
            float4 v; v.x = cv[j]; v.y = cv[j + 1]; v.z = cv[j + 2]; v.w = cv[j + 3];
            if (EPI) {
                int nb = blockIdx.x * 128 + tc + j;
                v.x = tanhf(v.x + bias[nb]);     v.y = tanhf(v.y + bias[nb + 1]);
                v.z = tanhf(v.z + bias[nb + 2]); v.w = tanhf(v.w + bias[nb + 3]);
            }
            *(float4*)(C + crow + j) = v;
        }
    }
}

// ---------------- LN over vocab table + init (unchanged) ----------------
__global__ void ln_k(const float* __restrict__ gA, const float* __restrict__ beA,
                     const float* __restrict__ bA, const float* __restrict__ gB,
                     const float* __restrict__ beB, const float* __restrict__ bB)
{
    int row = blockIdx.x, tid = threadIdx.x;
    if (row < 512) {
        ((float*)g_h)[row * 128 + tid] = 0.f;
    } else if (row == 512) {
        for (int q = 0; q < 12; q++) ((float*)g_stats)[q * 128 + tid] = 0.f;
        if (tid < 4) { g_ctrS[tid] = 0u; g_ctrH[tid] = 0u; }
    }
    int dir = row >= NV * 3;
    int rem = dir ? row - NV * 3 : row;
    int tok = rem / 3, gate = rem - tok * 3;
    float* p = (dir ? g_Wp1 : g_Wp0) + (size_t)tok * NH3 + gate * NH;
    const float* gg = (dir ? gB : gA) + gate * NH;
    const float* be = (dir ? beB : beA) + gate * NH;
    const float* bi = (dir ? bB : bA) + gate * NH;
    float4 v = ((float4*)p)[tid];
    if (tok == 0) { v.x = 0.f; v.y = 0.f; v.z = 0.f; v.w = 0.f; }
    float sum = v.x + v.y + v.z + v.w;
    float sq = v.x * v.x + v.y * v.y + v.z * v.z + v.w * v.w;
#pragma unroll
    for (int o = 16; o; o >>= 1) {
        sum += __shfl_xor_sync(0xffffffffu, sum, o);
        sq  += __shfl_xor_sync(0xffffffffu, sq, o);
    }
    __shared__ float ss[4], sc[4];
    int w = tid >> 5;
    if ((tid & 31) == 0) { ss[w] = sum; sc[w] = sq; }
    __syncthreads();
    sum = ss[0] + ss[1] + ss[2] + ss[3];
    sq  = sc[0] + sc[1] + sc[2] + sc[3];
    float mu = sum * (1.f / NH);
    float rs = rsqrtf(sq * (1.f / NH) - mu * mu + 1e-5f);
    int j = tid * 4;
    v.x = (v.x - mu) * rs * gg[j]     + be[j]     + bi[j];
    v.y = (v.y - mu) * rs * gg[j + 1] + be[j + 1] + bi[j + 1];
    v.z = (v.z - mu) * rs * gg[j + 2] + be[j + 2] + bi[j + 2];
    v.w = (v.w - mu) * rs * gg[j + 3] + be[j + 3] + bi[j + 3];
    ((float4*)p)[tid] = v;
}

// ----------------------------------------------------------------------------
// Persistent recurrence: phase-1 via warp-level bf16-split mma.sync.
// hp(32x48) = h_hi.W_hi + h_lo.W_hi + h_hi.W_lo (K=512, fp32 accum).
// 12 mma warps = 2 K-halves x (4 term1 blocks 2mt x 3nt + 2 term3 blocks).
// ----------------------------------------------------------------------------
__global__ void __launch_bounds__(REC_THREADS, 1) gru_rec(
    const int* __restrict__ src,
    const float* __restrict__ Whh_f, const float* __restrict__ Whh_b,
    const float* __restrict__ ghh_f, const float* __restrict__ behh_f,
    const float* __restrict__ bhh_f, const float* __restrict__ ghh_b,
    const float* __restrict__ behh_b, const float* __restrict__ bhh_b,
    float* __restrict__ dout)
{
    extern __shared__ __align__(16) char smraw[];
    uint32_t sb0 = smem_u32(smraw);
    uint32_t sb = (sb0 + 1023) & ~1023u;
    char* basep = smraw + (sb - sb0);
    float* Pbuf = (float*)(basep + OFF_P);     // [2][96][50]
    float* hpsp = (float*)(basep + OFF_HPS);   // [32][52]

    int grp = blockIdx.x >> 5, cid = blockIdx.x & 31;
    int dir = grp >> 1, bh = grp & 1;
    int tid = threadIdx.x, lane = tid & 31, wid = tid >> 5;
    int jbase = cid * JS;

    const float* Whh  = dir ? Whh_b  : Whh_f;
    const float* ghh  = dir ? ghh_b  : ghh_f;
    const float* behh = dir ? behh_b : behh_f;
    const float* bhh  = dir ? bhh_b  : bhh_f;
    const float* Wp   = dir ? g_Wp1  : g_Wp0;
    float* hg = g_h[dir] + bh * NGB * NH;
    const float4* hg4 = (const float4*)hg;
    unsigned* ctrS = &g_ctrS[grp];
    unsigned* ctrH = &g_ctrH[grp];

    // one-time: W -> bf16 hi/lo swizzled tiles; tile row r = gate*16 + jj
    for (int idx = tid; idx < NROW * 128; idx += REC_THREADS) {
        int r = idx >> 7, k4 = idx & 127;
        int grow = (r >> 4) * NH + jbase + (r & 15);
        float4 v = *(const float4*)(Whh + (size_t)grow * NH + k4 * 4);
        uint2 hi, lo; bsplit(v, hi, lo);
        uint32_t off = tile_off(r, k4);
        *(uint2*)(basep + OFF_WHI + off) = hi;
        *(uint2*)(basep + OFF_WLO + off) = lo;
    }

    // mma warp configuration (wid < 12)
    int kh = wid / 6;                    // K-half
    int sp = wid % 6;
    bool t3 = sp >= 4;                   // term3: h_hi x W_lo
    int mrowbase = t3 ? 0 : (sp >> 1) * 32;
    int ntb = t3 ? (sp - 4) * 24 : (sp & 1) * 24;
    int prow = t3 ? 64 : (sp >> 1) * 32;
    int khb = kh * 256;
    // per-lane ldmatrix address components
    int aRow0 = mrowbase + (lane & 7) + ((lane >> 3) & 1) * 8;
    int aKoff = (lane >> 4) * 8;
    uint32_t swzl = (uint32_t)((lane & 7) << 4);
    uint32_t aBase0 = sb + OFF_A + aRow0 * 1024;
    uint32_t wTile = sb + (t3 ? OFF_WLO : OFF_WHI);
    int bKoff = ((lane >> 3) & 1) * 8;
    uint32_t bBase[3];
#pragma unroll
    for (int nt = 0; nt < 3; nt++)
        bBase[nt] = wTile + (ntb + nt * 8 + (lane & 7)) * 1024;

    // phase-2 mapping + constants
    int pb = tid >> 4, jl = tid & 15;
    float cg[3], cbe[3], cbb[3];
#pragma unroll
    for (int g = 0; g < 3; g++) {
        int j = g * NH + jbase + jl;
        cg[g] = ghh[j]; cbe[g] = behh[j]; cbb[g] = bhh[j];
    }
    float xv[3];
    {
        int s0 = dir ? (NS - 1) : 0;
        int tok = __ldg(src + s0 * NB + bh * NGB + pb);
        const float* xrow = Wp + (size_t)tok * NH3;
#pragma unroll
        for (int g = 0; g < 3; g++) xv[g] = __ldg(xrow + g * NH + jbase + jl);
    }
    __syncthreads();   // W tiles ready

    for (int t = 0; t < NS; t++) {
        int s = dir ? (NS - 1 - t) : t;
        int par = t & 1;

        if (t > 0) bar_wait(ctrH, (unsigned)(NCG * t));

        // stage h -> A tile rows [hi(0:32); lo(32:64)], swizzled bf16
#pragma unroll
        for (int i = 0; i < 8; i++) {
            int idx = tid + i * REC_THREADS;
            int row = idx >> 7, k4 = idx & 127;
            float4 v = hg4[row * 128 + k4];
            uint2 hi, lo; bsplit(v, hi, lo);
            *(uint2*)(basep + OFF_A + tile_off(row, k4)) = hi;
            *(uint2*)(basep + OFF_A + tile_off(row + 32, k4)) = lo;
        }
        float ho = hg[pb * NH + jbase + jl];
        __syncthreads();

        // phase-1 mma: 6 acc tiles (2 m-tiles x 3 n-tiles) per warp, 16 k-chunks
        if (wid < 12) {
            float acc[2][3][4];
#pragma unroll
            for (int mt = 0; mt < 2; mt++)
#pragma unroll
                for (int nt = 0; nt < 3; nt++)
#pragma unroll
                    for (int q = 0; q < 4; q++) acc[mt][nt][q] = 0.f;
#pragma unroll 2
            for (int kc = 0; kc < 16; kc++) {
                int kb = khb + kc * 16;
                uint32_t a0[4], a1[4];
                uint32_t ad = aBase0 + ((uint32_t)((kb + aKoff) * 2) ^ swzl);
                ldsm4(a0, ad);
                ldsm4(a1, ad + 16 * 1024);
                uint32_t bf[3][2];
                uint32_t bko = (uint32_t)((kb + bKoff) * 2) ^ swzl;
#pragma unroll
                for (int nt = 0; nt < 3; nt++) ldsm2(bf[nt], bBase[nt] + bko);
#pragma unroll
                for (int nt = 0; nt < 3; nt++) {
                    mma16816(acc[0][nt], a0, bf[nt]);
                    mma16816(acc[1][nt], a1, bf[nt]);
                }
            }
            // write partials: P[kh][prow + mt*16 + r][ntb + nt*8 + c]
            float* P = Pbuf + kh * (96 * 50);
            int r0 = lane >> 2, c0 = (lane & 3) * 2;
#pragma unroll
            for (int mt = 0; mt < 2; mt++)
#pragma unroll
                for (int nt = 0; nt < 3; nt++) {
                    float* rp = P + (prow + mt * 16 + r0) * 50 + ntb + nt * 8 + c0;
                    *(float2*)rp = make_float2(acc[mt][nt][0], acc[mt][nt][1]);
                    *(float2*)(rp + 8 * 50) = make_float2(acc[mt][nt][2], acc[mt][nt][3]);
                }
        }
        __syncthreads();

        // combine partials -> hp[32][48] (stride 52)
#pragma unroll
        for (int i = 0; i < 3; i++) {
            int e = tid + i * REC_THREADS;
            int b = e / 48, r = e - b * 48;
            const float* P0 = Pbuf + b * 50 + r;
            const float* P1 = P0 + 96 * 50;
            float v = P0[0] + P0[32 * 50] + P0[64 * 50]
                    + P1[0] + P1[32 * 50] + P1[64 * 50];
            hpsp[b * 52 + r] = v;
        }
        __syncthreads();

        // LN partial stats (16 j per (b,gate))
        if (tid < 96) {
            int g = tid >> 5, b = tid & 31;
            float sv = 0.f, sq = 0.f;
#pragma unroll
            for (int q = 0; q < 16; q++) {
                float v = hpsp[b * 52 + g * 16 + q];
                sv += v; sq += v * v;
            }
            float* st = &g_stats[par][grp][b * 6 + g * 2];
            atomicAdd(st, sv);
            atomicAdd(st + 1, sq);
        }
        bar_arrive(ctrS);

        // prefetch x(t+1) under stats wait
        float xn[3];
        if (t + 1 < NS) {
            int sn = dir ? (NS - 2 - t) : (t + 1);
            int tok = __ldg(src + sn * NB + bh * NGB + pb);
            const float* xrow = Wp + (size_t)tok * NH3;
#pragma unroll
            for (int g = 0; g < 3; g++) xn[g] = __ldg(xrow + g * NH + jbase + jl);
        }

        bar_wait(ctrS, (unsigned)(NCG * (t + 1)));

        // phase 2: LN + gates + h update for (pb, jl)
        float hnew;
        {
            const float* st = &g_stats[par][grp][pb * 6];
            float mu0 = st[0] * (1.f / NH);
            float rs0 = rsqrtf(st[1] * (1.f / NH) - mu0 * mu0 + 1e-5f);
            float mu1 = st[2] * (1.f / NH);
            float rs1 = rsqrtf(st[3] * (1.f / NH) - mu1 * mu1 + 1e-5f);
            float mu2 = st[4] * (1.f / NH);
            float rs2 = rsqrtf(st[5] * (1.f / NH) - mu2 * mu2 + 1e-5f);
            float hr = (hpsp[pb * 52 + jl]      - mu0) * rs0 * cg[0] + cbe[0] + cbb[0];
            float hz = (hpsp[pb * 52 + 16 + jl] - mu1) * rs1 * cg[1] + cbe[1] + cbb[1];
            float hn = (hpsp[pb * 52 + 32 + jl] - mu2) * rs2 * cg[2] + cbe[2] + cbb[2];
            float r = 1.f / (1.f + __expf(-(xv[0] + hr)));
            float z = 1.f / (1.f + __expf(-(xv[1] + hz)));
            float n = tanhf(xv[2] + r * hn);
            hnew = (1.f - z) * n + z * ho;
            hg[pb * NH + jbase + jl] = hnew;
        }
        if (tid < 6) g_stats[par ^ 1][grp][cid * 6 + tid] = 0.f;
        bar_arrive(ctrH);

        {
            int j = jbase + jl;
            int bglob = bh * NGB + pb;
            g_gru[((size_t)s * NB + bglob) * (2 * NH) + dir * NH + j] = hnew;
            if (t == NS - 1)
                dout[(size_t)NS * NB * NH + (size_t)dir * NB * NH + bglob * NH + j] = hnew;
        }
        xv[0] = xn[0]; xv[1] = xn[1]; xv[2] = xn[2];
    }
}

// ---------------- launch ----------------
extern "C" void kernel_launch(void* const* d_in, const int* in_sizes, int n_in,
                              void* d_out, int out_size) {
    (void)in_sizes; (void)n_in; (void)out_size;
    const int*   src    = (const int*)  d_in[0];
    const float* emb    = (const float*)d_in[1];
    const float* W_ih_f = (const float*)d_in[2];
    const float* W_hh_f = (const float*)d_in[3];
    const float* b_ih_f = (const float*)d_in[4];
    const float* bhh_f  = (const float*)d_in[5];
    const float* gih_f  = (const float*)d_in[6];
    const float* beih_f = (const float*)d_in[7];
    const float* ghh_f  = (const float*)d_in[8];
    const float* behh_f = (const float*)d_in[9];
    const float* W_ih_b = (const float*)d_in[10];
    const float* W_hh_b = (const float*)d_in[11];
    const float* b_ih_b = (const float*)d_in[12];
    const float* bhh_b  = (const float*)d_in[13];
    const float* gih_b  = (const float*)d_in[14];
    const float* beih_b = (const float*)d_in[15];
    const float* ghh_b  = (const float*)d_in[16];
    const float* behh_b = (const float*)d_in[17];
    const float* W_out  = (const float*)d_in[18];
    const float* b_out  = (const float*)d_in[19];
    float* out = (float*)d_out;

    void *pWp0, *pWp1, *pGru;
    cudaGetSymbolAddress(&pWp0, g_Wp0);
    cudaGetSymbolAddress(&pWp1, g_Wp1);
    cudaGetSymbolAddress(&pGru, g_gru);
    cudaFuncSetAttribute(gru_rec, cudaFuncAttributeMaxDynamicSharedMemorySize,
                         REC_SMEM_BYTES);

    sgemm_nt<0><<<dim3(NH3 / 128, NV / 128), 256>>>(
        emb, W_ih_f, (float*)pWp0, NV, NH3, NE, nullptr);
    sgemm_nt<0><<<dim3(NH3 / 128, NV / 128), 256>>>(
        emb, W_ih_b, (float*)pWp1, NV, NH3, NE, nullptr);

    ln_k<<<2 * NV * 3, 128>>>(gih_f, beih_f, b_ih_f, gih_b, beih_b, b_ih_b);

    gru_rec<<<128, REC_THREADS, REC_SMEM_BYTES>>>(
        src, W_hh_f, W_hh_b, ghh_f, behh_f, bhh_f, ghh_b, behh_b, bhh_b, out);

    sgemm_nt<1><<<dim3(NH / 128, (NS * NB) / 128), 256>>>(
        (const float*)pGru, W_out, out, NS * NB, NH, 2 * NH, b_out);
}

// round 12
// speedup vs baseline: 3.0434x; 1.3151x over previous
#include <cuda_runtime.h>
#include <cuda_bf16.h>
#include <math.h>
#include <stdint.h>

constexpr int NS = 1024, NB = 64, NE = 512, NH = 512, NH3 = 1536, NV = 32000;
constexpr int NCG = 32, NGB = 32, JS = 16, NROW = 48, REC_THREADS = 512;

// gru_rec smem byte offsets (from 1024-aligned base)
constexpr int OFF_A   = 0;        // A tile: 64 x 512 bf16 (row stride 1024B)
constexpr int OFF_WHI = 65536;
constexpr int OFF_WLO = 114688;
constexpr int OFF_P   = 163840;   // partials [2][96][50] f32
constexpr int OFF_HPS = 202240;   // hp [32][52] f32
constexpr int REC_SMEM_BYTES = 208896 + 1024;

// hgemm smem: 4 tiles of [128 rows][64 k] bf16 (16KB each)
constexpr int HG_SMEM = 65536;

// ---------------- warp mma / ldmatrix (base PTX, sm_80+) ----------------
__device__ __forceinline__ uint32_t smem_u32(const void* p) {
    uint32_t a;
    asm("{ .reg .u64 t; cvta.to.shared.u64 t, %1; cvt.u32.u64 %0, t; }" : "=r"(a) : "l"(p));
    return a;
}
__device__ __forceinline__ void ldsm4(uint32_t* r, uint32_t addr) {
    asm volatile("ldmatrix.sync.aligned.m8n8.x4.shared.b16 {%0,%1,%2,%3}, [%4];"
        : "=r"(r[0]), "=r"(r[1]), "=r"(r[2]), "=r"(r[3]) : "r"(addr));
}
__device__ __forceinline__ void ldsm2(uint32_t* r, uint32_t addr) {
    asm volatile("ldmatrix.sync.aligned.m8n8.x2.shared.b16 {%0,%1}, [%2];"
        : "=r"(r[0]), "=r"(r[1]) : "r"(addr));
}
__device__ __forceinline__ void mma16816(float* d, const uint32_t* a, const uint32_t* b) {
    asm volatile("mma.sync.aligned.m16n8k16.row.col.f32.bf16.bf16.f32 "
        "{%0,%1,%2,%3}, {%4,%5,%6,%7}, {%8,%9}, {%0,%1,%2,%3};"
        : "+f"(d[0]), "+f"(d[1]), "+f"(d[2]), "+f"(d[3])
        : "r"(a[0]), "r"(a[1]), "r"(a[2]), "r"(a[3]), "r"(b[0]), "r"(b[1]));
}
// swizzled byte offset, row stride 1024B (gru tiles)
__device__ __forceinline__ uint32_t tile_off(int row, int k4) {
    return (uint32_t)(row * 1024 + ((k4 * 8) ^ ((row & 7) << 4)));
}
__device__ __forceinline__ void bsplit(float4 v, uint2& hi, uint2& lo) {
    __nv_bfloat16 a = __float2bfloat16_rn(v.x), b = __float2bfloat16_rn(v.y),
                  c = __float2bfloat16_rn(v.z), d = __float2bfloat16_rn(v.w);
    __nv_bfloat162 h0 = __halves2bfloat162(a, b), h1 = __halves2bfloat162(c, d);
    hi.x = *(uint32_t*)&h0; hi.y = *(uint32_t*)&h1;
    __nv_bfloat162 l0 = __floats2bfloat162_rn(v.x - __bfloat162float(a), v.y - __bfloat162float(b));
    __nv_bfloat162 l1 = __floats2bfloat162_rn(v.z - __bfloat162float(c), v.w - __bfloat162float(d));
    lo.x = *(uint32_t*)&l0; lo.y = *(uint32_t*)&l1;
}

// ---------------- device scratch ----------------
__device__ float g_Wp0[(size_t)NV * NH3];
__device__ float g_Wp1[(size_t)NV * NH3];
__device__ float g_gru[(size_t)NS * NB * 2 * NH];
__device__ float g_h[2][NB * NH];
__device__ float g_stats[2][4][NGB * 3 * 2];
__device__ unsigned g_ctrS[4];
__device__ unsigned g_ctrH[4];

__device__ __forceinline__ void bar_arrive(unsigned* c) {
    __syncthreads();
    if (threadIdx.x == 0)
        asm volatile("red.release.gpu.global.add.u32 [%0], 1;" :: "l"(c) : "memory");
}
__device__ __forceinline__ void bar_wait(unsigned* c, unsigned tgt) {
    if (threadIdx.x == 0) {
        unsigned v;
        do { asm volatile("ld.acquire.gpu.global.u32 %0, [%1];" : "=r"(v) : "l"(c) : "memory"); }
        while (v < tgt);
    }
    __syncthreads();
}

// ----------------------------------------------------------------------------
// hgemm_nt: C[M,N] = A[M,K] * Bw[N,K]^T via bf16-split mma.sync.
// 3-term: Ahi.Bhi + Alo.Bhi + Ahi.Blo (fp32 accum). EPI=1: C=tanh(C+bias).
// 128x128 tile, K-chunk 64, 8 warps each 32(m) x 64(n).
// ----------------------------------------------------------------------------
template <int EPI>
__global__ void __launch_bounds__(256, 2) hgemm_nt(
    const float* __restrict__ A, const float* __restrict__ Bw,
    float* __restrict__ C, int M, int N, int K, const float* __restrict__ bias)
{
    extern __shared__ __align__(1024) char hsm[];
    uint32_t sb = smem_u32(hsm);
    uint32_t sAhi = sb, sAlo = sb + 16384, sBhi = sb + 32768, sBlo = sb + 49152;

    int tid = threadIdx.x, lane = tid & 31, wid = tid >> 5;
    int wm = wid & 3, wn = wid >> 2;          // warp: rows wm*32, cols wn*64
    const float* Ab = A + (size_t)blockIdx.y * 128 * K;
    const float* Bb = Bw + (size_t)blockIdx.x * 128 * K;

    float acc[2][8][4];
#pragma unroll
    for (int mt = 0; mt < 2; mt++)
#pragma unroll
        for (int nt = 0; nt < 8; nt++)
#pragma unroll
            for (int q = 0; q < 4; q++) acc[mt][nt][q] = 0.f;

    // ldsm lane addressing
    int aRowL = (lane & 7) + ((lane >> 3) & 1) * 8;   // + (lane>>4)*k8
    int aK8 = (lane >> 4);
    int bRowL = ((lane >> 4) & 1) * 8 + (lane & 7);
    int bK8 = (lane >> 3) & 1;
    int rsub = tid >> 4, c4 = tid & 15;

    for (int kc = 0; kc < K; kc += 64) {
#pragma unroll
        for (int i = 0; i < 8; i++) {
            int row = rsub + i * 16;
            uint32_t off = (uint32_t)(row * 128 + ((c4 * 8) ^ ((row & 7) << 4)));
            float4 va = *(const float4*)(Ab + (size_t)row * K + kc + c4 * 4);
            uint2 hi, lo; bsplit(va, hi, lo);
            *(uint2*)(hsm + (sAhi - sb) + off) = hi;
            *(uint2*)(hsm + (sAlo - sb) + off) = lo;
            float4 vb = *(const float4*)(Bb + (size_t)row * K + kc + c4 * 4);
            bsplit(vb, hi, lo);
            *(uint2*)(hsm + (sBhi - sb) + off) = hi;
            *(uint2*)(hsm + (sBlo - sb) + off) = lo;
        }
        __syncthreads();
#pragma unroll
        for (int k16 = 0; k16 < 4; k16++) {
            int ku = k16 * 2;   // 16B-unit base within chunk
            uint32_t ah[2][4], al[2][4];
#pragma unroll
            for (int mt = 0; mt < 2; mt++) {
                int row = wm * 32 + mt * 16 + aRowL;
                uint32_t off = (uint32_t)(row * 128 + (((ku + aK8) * 16) ^ ((row & 7) << 4)));
                ldsm4(ah[mt], sAhi + off);
                ldsm4(al[mt], sAlo + off);
            }
#pragma unroll
            for (int ntp = 0; ntp < 4; ntp++) {
                int row = wn * 64 + ntp * 16 + bRowL;
                uint32_t off = (uint32_t)(row * 128 + (((ku + bK8) * 16) ^ ((row & 7) << 4)));
                uint32_t bh[4], bl[4];
                ldsm4(bh, sBhi + off);
                ldsm4(bl, sBlo + off);
#pragma unroll
                for (int h = 0; h < 2; h++) {
                    int nt = ntp * 2 + h;
#pragma unroll
                    for (int mt = 0; mt < 2; mt++) {
                        mma16816(acc[mt][nt], ah[mt], bh + h * 2);
                        mma16816(acc[mt][nt], al[mt], bh + h * 2);
                        mma16816(acc[mt][nt], ah[mt], bl + h * 2);
                    }
                }
            }
        }
        __syncthreads();
    }

    // epilogue
    int r0 = lane >> 2, c0 = (lane & 3) * 2;
#pragma unroll
    for (int mt = 0; mt < 2; mt++)
#pragma unroll
        for (int nt = 0; nt < 8; nt++) {
            int m = blockIdx.y * 128 + wm * 32 + mt * 16 + r0;
            int n = blockIdx.x * 128 + wn * 64 + nt * 8 + c0;
            float2 v0 = make_float2(acc[mt][nt][0], acc[mt][nt][1]);
            float2 v1 = make_float2(acc[mt][nt][2], acc[mt][nt][3]);
            if (EPI) {
                float b0 = bias[n], b1 = bias[n + 1];
                v0.x = tanhf(v0.x + b0); v0.y = tanhf(v0.y + b1);
                v1.x = tanhf(v1.x + b0); v1.y = tanhf(v1.y + b1);
            }
            *(float2*)(C + (size_t)m * N + n) = v0;
            *(float2*)(C + (size_t)(m + 8) * N + n) = v1;
        }
}

// ---------------- LN over vocab table + init (unchanged) ----------------
__global__ void ln_k(const float* __restrict__ gA, const float* __restrict__ beA,
                     const float* __restrict__ bA, const float* __restrict__ gB,
                     const float* __restrict__ beB, const float* __restrict__ bB)
{
    int row = blockIdx.x, tid = threadIdx.x;
    if (row < 512) {
        ((float*)g_h)[row * 128 + tid] = 0.f;
    } else if (row == 512) {
        for (int q = 0; q < 12; q++) ((float*)g_stats)[q * 128 + tid] = 0.f;
        if (tid < 4) { g_ctrS[tid] = 0u; g_ctrH[tid] = 0u; }
    }
    int dir = row >= NV * 3;
    int rem = dir ? row - NV * 3 : row;
    int tok = rem / 3, gate = rem - tok * 3;
    float* p = (dir ? g_Wp1 : g_Wp0) + (size_t)tok * NH3 + gate * NH;
    const float* gg = (dir ? gB : gA) + gate * NH;
    const float* be = (dir ? beB : beA) + gate * NH;
    const float* bi = (dir ? bB : bA) + gate * NH;
    float4 v = ((float4*)p)[tid];
    if (tok == 0) { v.x = 0.f; v.y = 0.f; v.z = 0.f; v.w = 0.f; }
    float sum = v.x + v.y + v.z + v.w;
    float sq = v.x * v.x + v.y * v.y + v.z * v.z + v.w * v.w;
#pragma unroll
    for (int o = 16; o; o >>= 1) {
        sum += __shfl_xor_sync(0xffffffffu, sum, o);
        sq  += __shfl_xor_sync(0xffffffffu, sq, o);
    }
    __shared__ float ss[4], sc[4];
    int w = tid >> 5;
    if ((tid & 31) == 0) { ss[w] = sum; sc[w] = sq; }
    __syncthreads();
    sum = ss[0] + ss[1] + ss[2] + ss[3];
    sq  = sc[0] + sc[1] + sc[2] + sc[3];
    float mu = sum * (1.f / NH);
    float rs = rsqrtf(sq * (1.f / NH) - mu * mu + 1e-5f);
    int j = tid * 4;
    v.x = (v.x - mu) * rs * gg[j]     + be[j]     + bi[j];
    v.y = (v.y - mu) * rs * gg[j + 1] + be[j + 1] + bi[j + 1];
    v.z = (v.z - mu) * rs * gg[j + 2] + be[j + 2] + bi[j + 2];
    v.w = (v.w - mu) * rs * gg[j + 3] + be[j + 3] + bi[j + 3];
    ((float4*)p)[tid] = v;
}

// ----------------------------------------------------------------------------
// Persistent recurrence (UNCHANGED from round 11 win)
// ----------------------------------------------------------------------------
__global__ void __launch_bounds__(REC_THREADS, 1) gru_rec(
    const int* __restrict__ src,
    const float* __restrict__ Whh_f, const float* __restrict__ Whh_b,
    const float* __restrict__ ghh_f, const float* __restrict__ behh_f,
    const float* __restrict__ bhh_f, const float* __restrict__ ghh_b,
    const float* __restrict__ behh_b, const float* __restrict__ bhh_b,
    float* __restrict__ dout)
{
    extern __shared__ __align__(16) char smraw[];
    uint32_t sb0 = smem_u32(smraw);
    uint32_t sb = (sb0 + 1023) & ~1023u;
    char* basep = smraw + (sb - sb0);
    float* Pbuf = (float*)(basep + OFF_P);
    float* hpsp = (float*)(basep + OFF_HPS);

    int grp = blockIdx.x >> 5, cid = blockIdx.x & 31;
    int dir = grp >> 1, bh = grp & 1;
    int tid = threadIdx.x, lane = tid & 31, wid = tid >> 5;
    int jbase = cid * JS;

    const float* Whh  = dir ? Whh_b  : Whh_f;
    const float* ghh  = dir ? ghh_b  : ghh_f;
    const float* behh = dir ? behh_b : behh_f;
    const float* bhh  = dir ? bhh_b  : bhh_f;
    const float* Wp   = dir ? g_Wp1  : g_Wp0;
    float* hg = g_h[dir] + bh * NGB * NH;
    const float4* hg4 = (const float4*)hg;
    unsigned* ctrS = &g_ctrS[grp];
    unsigned* ctrH = &g_ctrH[grp];

    for (int idx = tid; idx < NROW * 128; idx += REC_THREADS) {
        int r = idx >> 7, k4 = idx & 127;
        int grow = (r >> 4) * NH + jbase + (r & 15);
        float4 v = *(const float4*)(Whh + (size_t)grow * NH + k4 * 4);
        uint2 hi, lo; bsplit(v, hi, lo);
        uint32_t off = tile_off(r, k4);
        *(uint2*)(basep + OFF_WHI + off) = hi;
        *(uint2*)(basep + OFF_WLO + off) = lo;
    }

    int kh = wid / 6;
    int sp = wid % 6;
    bool t3 = sp >= 4;
    int mrowbase = t3 ? 0 : (sp >> 1) * 32;
    int ntb = t3 ? (sp - 4) * 24 : (sp & 1) * 24;
    int prow = t3 ? 64 : (sp >> 1) * 32;
    int khb = kh * 256;
    int aRow0 = mrowbase + (lane & 7) + ((lane >> 3) & 1) * 8;
    int aKoff = (lane >> 4) * 8;
    uint32_t swzl = (uint32_t)((lane & 7) << 4);
    uint32_t aBase0 = sb + OFF_A + aRow0 * 1024;
    uint32_t wTile = sb + (t3 ? OFF_WLO : OFF_WHI);
    int bKoff = ((lane >> 3) & 1) * 8;
    uint32_t bBase[3];
#pragma unroll
    for (int nt = 0; nt < 3; nt++)
        bBase[nt] = wTile + (ntb + nt * 8 + (lane & 7)) * 1024;

    int pb = tid >> 4, jl = tid & 15;
    float cg[3], cbe[3], cbb[3];
#pragma unroll
    for (int g = 0; g < 3; g++) {
        int j = g * NH + jbase + jl;
        cg[g] = ghh[j]; cbe[g] = behh[j]; cbb[g] = bhh[j];
    }
    float xv[3];
    {
        int s0 = dir ? (NS - 1) : 0;
        int tok = __ldg(src + s0 * NB + bh * NGB + pb);
        const float* xrow = Wp + (size_t)tok * NH3;
#pragma unroll
        for (int g = 0; g < 3; g++) xv[g] = __ldg(xrow + g * NH + jbase + jl);
    }
    __syncthreads();

    for (int t = 0; t < NS; t++) {
        int s = dir ? (NS - 1 - t) : t;
        int par = t & 1;

        if (t > 0) bar_wait(ctrH, (unsigned)(NCG * t));

#pragma unroll
        for (int i = 0; i < 8; i++) {
            int idx = tid + i * REC_THREADS;
            int row = idx >> 7, k4 = idx & 127;
            float4 v = hg4[row * 128 + k4];
            uint2 hi, lo; bsplit(v, hi, lo);
            *(uint2*)(basep + OFF_A + tile_off(row, k4)) = hi;
            *(uint2*)(basep + OFF_A + tile_off(row + 32, k4)) = lo;
        }
        float ho = hg[pb * NH + jbase + jl];
        __syncthreads();

        if (wid < 12) {
            float acc[2][3][4];
#pragma unroll
            for (int mt = 0; mt < 2; mt++)
#pragma unroll
                for (int nt = 0; nt < 3; nt++)
#pragma unroll
                    for (int q = 0; q < 4; q++) acc[mt][nt][q] = 0.f;
#pragma unroll 2
            for (int kc = 0; kc < 16; kc++) {
                int kb = khb + kc * 16;
                uint32_t a0[4], a1[4];
                uint32_t ad = aBase0 + ((uint32_t)((kb + aKoff) * 2) ^ swzl);
                ldsm4(a0, ad);
                ldsm4(a1, ad + 16 * 1024);
                uint32_t bf[3][2];
                uint32_t bko = (uint32_t)((kb + bKoff) * 2) ^ swzl;
#pragma unroll
                for (int nt = 0; nt < 3; nt++) ldsm2(bf[nt], bBase[nt] + bko);
#pragma unroll
                for (int nt = 0; nt < 3; nt++) {
                    mma16816(acc[0][nt], a0, bf[nt]);
                    mma16816(acc[1][nt], a1, bf[nt]);
                }
            }
            float* P = Pbuf + kh * (96 * 50);
            int r0 = lane >> 2, c0 = (lane & 3) * 2;
#pragma unroll
            for (int mt = 0; mt < 2; mt++)
#pragma unroll
                for (int nt = 0; nt < 3; nt++) {
                    float* rp = P + (prow + mt * 16 + r0) * 50 + ntb + nt * 8 + c0;
                    *(float2*)rp = make_float2(acc[mt][nt][0], acc[mt][nt][1]);
                    *(float2*)(rp + 8 * 50) = make_float2(acc[mt][nt][2], acc[mt][nt][3]);
                }
        }
        __syncthreads();

#pragma unroll
        for (int i = 0; i < 3; i++) {
            int e = tid + i * REC_THREADS;
            int b = e / 48, r = e - b * 48;
            const float* P0 = Pbuf + b * 50 + r;
            const float* P1 = P0 + 96 * 50;
            float v = P0[0] + P0[32 * 50] + P0[64 * 50]
                    + P1[0] + P1[32 * 50] + P1[64 * 50];
            hpsp[b * 52 + r] = v;
        }
        __syncthreads();

        if (tid < 96) {
            int g = tid >> 5, b = tid & 31;
            float sv = 0.f, sq = 0.f;
#pragma unroll
            for (int q = 0; q < 16; q++) {
                float v = hpsp[b * 52 + g * 16 + q];
                sv += v; sq += v * v;
            }
            float* st = &g_stats[par][grp][b * 6 + g * 2];
            atomicAdd(st, sv);
            atomicAdd(st + 1, sq);
        }
        bar_arrive(ctrS);

        float xn[3];
        if (t + 1 < NS) {
            int sn = dir ? (NS - 2 - t) : (t + 1);
            int tok = __ldg(src + sn * NB + bh * NGB + pb);
            const float* xrow = Wp + (size_t)tok * NH3;
#pragma unroll
            for (int g = 0; g < 3; g++) xn[g] = __ldg(xrow + g * NH + jbase + jl);
        }

        bar_wait(ctrS, (unsigned)(NCG * (t + 1)));

        float hnew;
        {
            const float* st = &g_stats[par][grp][pb * 6];
            float mu0 = st[0] * (1.f / NH);
            float rs0 = rsqrtf(st[1] * (1.f / NH) - mu0 * mu0 + 1e-5f);
            float mu1 = st[2] * (1.f / NH);
            float rs1 = rsqrtf(st[3] * (1.f / NH) - mu1 * mu1 + 1e-5f);
            float mu2 = st[4] * (1.f / NH);
            float rs2 = rsqrtf(st[5] * (1.f / NH) - mu2 * mu2 + 1e-5f);
            float hr = (hpsp[pb * 52 + jl]      - mu0) * rs0 * cg[0] + cbe[0] + cbb[0];
            float hz = (hpsp[pb * 52 + 16 + jl] - mu1) * rs1 * cg[1] + cbe[1] + cbb[1];
            float hn = (hpsp[pb * 52 + 32 + jl] - mu2) * rs2 * cg[2] + cbe[2] + cbb[2];
            float r = 1.f / (1.f + __expf(-(xv[0] + hr)));
            float z = 1.f / (1.f + __expf(-(xv[1] + hz)));
            float n = tanhf(xv[2] + r * hn);
            hnew = (1.f - z) * n + z * ho;
            hg[pb * NH + jbase + jl] = hnew;
        }
        if (tid < 6) g_stats[par ^ 1][grp][cid * 6 + tid] = 0.f;
        bar_arrive(ctrH);

        {
            int j = jbase + jl;
            int bglob = bh * NGB + pb;
            g_gru[((size_t)s * NB + bglob) * (2 * NH) + dir * NH + j] = hnew;
            if (t == NS - 1)
                dout[(size_t)NS * NB * NH + (size_t)dir * NB * NH + bglob * NH + j] = hnew;
        }
        xv[0] = xn[0]; xv[1] = xn[1]; xv[2] = xn[2];
    }
}

// ---------------- launch ----------------
extern "C" void kernel_launch(void* const* d_in, const int* in_sizes, int n_in,
                              void* d_out, int out_size) {
    (void)in_sizes; (void)n_in; (void)out_size;
    const int*   src    = (const int*)  d_in[0];
    const float* emb    = (const float*)d_in[1];
    const float* W_ih_f = (const float*)d_in[2];
    const float* W_hh_f = (const float*)d_in[3];
    const float* b_ih_f = (const float*)d_in[4];
    const float* bhh_f  = (const float*)d_in[5];
    const float* gih_f  = (const float*)d_in[6];
    const float* beih_f = (const float*)d_in[7];
    const float* ghh_f  = (const float*)d_in[8];
    const float* behh_f = (const float*)d_in[9];
    const float* W_ih_b = (const float*)d_in[10];
    const float* W_hh_b = (const float*)d_in[11];
    const float* b_ih_b = (const float*)d_in[12];
    const float* bhh_b  = (const float*)d_in[13];
    const float* gih_b  = (const float*)d_in[14];
    const float* beih_b = (const float*)d_in[15];
    const float* ghh_b  = (const float*)d_in[16];
    const float* behh_b = (const float*)d_in[17];
    const float* W_out  = (const float*)d_in[18];
    const float* b_out  = (const float*)d_in[19];
    float* out = (float*)d_out;

    void *pWp0, *pWp1, *pGru;
    cudaGetSymbolAddress(&pWp0, g_Wp0);
    cudaGetSymbolAddress(&pWp1, g_Wp1);
    cudaGetSymbolAddress(&pGru, g_gru);
    cudaFuncSetAttribute(gru_rec, cudaFuncAttributeMaxDynamicSharedMemorySize,
                         REC_SMEM_BYTES);
    cudaFuncSetAttribute(hgemm_nt<0>, cudaFuncAttributeMaxDynamicSharedMemorySize,
                         HG_SMEM);
    cudaFuncSetAttribute(hgemm_nt<1>, cudaFuncAttributeMaxDynamicSharedMemorySize,
                         HG_SMEM);

    // Vocab-level input projection: Wp = emb @ W_ih^T (bf16-split mma)
    hgemm_nt<0><<<dim3(NH3 / 128, NV / 128), 256, HG_SMEM>>>(
        emb, W_ih_f, (float*)pWp0, NV, NH3, NE, nullptr);
    hgemm_nt<0><<<dim3(NH3 / 128, NV / 128), 256, HG_SMEM>>>(
        emb, W_ih_b, (float*)pWp1, NV, NH3, NE, nullptr);

    ln_k<<<2 * NV * 3, 128>>>(gih_f, beih_f, b_ih_f, gih_b, beih_b, b_ih_b);

    gru_rec<<<128, REC_THREADS, REC_SMEM_BYTES>>>(
        src, W_hh_f, W_hh_b, ghh_f, behh_f, bhh_f, ghh_b, behh_b, bhh_b, out);

    // Output projection with tanh epilogue (bf16-split mma)
    hgemm_nt<1><<<dim3(NH / 128, (NS * NB) / 128), 256, HG_SMEM>>>(
        (const float*)pGru, W_out, out, NS * NB, NH, 2 * NH, b_out);
}

// round 13
// speedup vs baseline: 3.1346x; 1.0300x over previous
#include <cuda_runtime.h>
#include <cuda_bf16.h>
#include <math.h>
#include <stdint.h>

constexpr int NS = 1024, NB = 64, NE = 512, NH = 512, NH3 = 1536, NV = 32000;
constexpr int NCG = 32, NGB = 32, JS = 16, NROW = 48, REC_THREADS = 512;

// gru_rec smem byte offsets (from 1024-aligned base)
constexpr int OFF_A   = 0;        // A tile: 64 x 512 bf16 (row stride 1024B)
constexpr int OFF_WHI = 65536;
constexpr int OFF_WLO = 114688;
constexpr int OFF_P   = 163840;   // partials [2][96][50] f32
constexpr int OFF_HPS = 202240;   // hp [32][52] f32
constexpr int REC_SMEM_BYTES = 208896 + 1024;

// hgemm smem: 4 tiles of [128 rows][64 k] bf16 (16KB each)
constexpr int HG_SMEM = 65536;

// ---------------- warp mma / ldmatrix (base PTX, sm_80+) ----------------
__device__ __forceinline__ uint32_t smem_u32(const void* p) {
    uint32_t a;
    asm("{ .reg .u64 t; cvta.to.shared.u64 t, %1; cvt.u32.u64 %0, t; }" : "=r"(a) : "l"(p));
    return a;
}
__device__ __forceinline__ void ldsm4(uint32_t* r, uint32_t addr) {
    asm volatile("ldmatrix.sync.aligned.m8n8.x4.shared.b16 {%0,%1,%2,%3}, [%4];"
        : "=r"(r[0]), "=r"(r[1]), "=r"(r[2]), "=r"(r[3]) : "r"(addr));
}
__device__ __forceinline__ void ldsm2(uint32_t* r, uint32_t addr) {
    asm volatile("ldmatrix.sync.aligned.m8n8.x2.shared.b16 {%0,%1}, [%2];"
        : "=r"(r[0]), "=r"(r[1]) : "r"(addr));
}
__device__ __forceinline__ void mma16816(float* d, const uint32_t* a, const uint32_t* b) {
    asm volatile("mma.sync.aligned.m16n8k16.row.col.f32.bf16.bf16.f32 "
        "{%0,%1,%2,%3}, {%4,%5,%6,%7}, {%8,%9}, {%0,%1,%2,%3};"
        : "+f"(d[0]), "+f"(d[1]), "+f"(d[2]), "+f"(d[3])
        : "r"(a[0]), "r"(a[1]), "r"(a[2]), "r"(a[3]), "r"(b[0]), "r"(b[1]));
}
// swizzled byte offset, row stride 1024B (gru tiles), k4 = 8B unit
__device__ __forceinline__ uint32_t tile_off(int row, int k4) {
    return (uint32_t)(row * 1024 + ((k4 * 8) ^ ((row & 7) << 4)));
}
__device__ __forceinline__ void bsplit(float4 v, uint2& hi, uint2& lo) {
    __nv_bfloat16 a = __float2bfloat16_rn(v.x), b = __float2bfloat16_rn(v.y),
                  c = __float2bfloat16_rn(v.z), d = __float2bfloat16_rn(v.w);
    __nv_bfloat162 h0 = __halves2bfloat162(a, b), h1 = __halves2bfloat162(c, d);
    hi.x = *(uint32_t*)&h0; hi.y = *(uint32_t*)&h1;
    __nv_bfloat162 l0 = __floats2bfloat162_rn(v.x - __bfloat162float(a), v.y - __bfloat162float(b));
    __nv_bfloat162 l1 = __floats2bfloat162_rn(v.z - __bfloat162float(c), v.w - __bfloat162float(d));
    lo.x = *(uint32_t*)&l0; lo.y = *(uint32_t*)&l1;
}

// ---------------- device scratch ----------------
__device__ float g_Wp0[(size_t)NV * NH3];
__device__ float g_Wp1[(size_t)NV * NH3];
__device__ float g_gru[(size_t)NS * NB * 2 * NH];
__device__ __nv_bfloat16 g_hbf[4][2][NGB * NH];   // [group][hi/lo][b*512+k]
__device__ float g_stats[2][4][NGB * 3 * 2];
__device__ unsigned g_ctrS[4];
__device__ unsigned g_ctrH[4];

__device__ __forceinline__ void bar_arrive(unsigned* c) {
    __syncthreads();
    if (threadIdx.x == 0)
        asm volatile("red.release.gpu.global.add.u32 [%0], 1;" :: "l"(c) : "memory");
}
__device__ __forceinline__ void bar_wait(unsigned* c, unsigned tgt) {
    if (threadIdx.x == 0) {
        unsigned v;
        do { asm volatile("ld.acquire.gpu.global.u32 %0, [%1];" : "=r"(v) : "l"(c) : "memory"); }
        while (v < tgt);
    }
    __syncthreads();
}

// ----------------------------------------------------------------------------
// hgemm_nt (UNCHANGED from round 12 win): bf16-split mma GEMM.
// ----------------------------------------------------------------------------
template <int EPI>
__global__ void __launch_bounds__(256, 2) hgemm_nt(
    const float* __restrict__ A, const float* __restrict__ Bw,
    float* __restrict__ C, int M, int N, int K, const float* __restrict__ bias)
{
    extern __shared__ __align__(1024) char hsm[];
    uint32_t sb = smem_u32(hsm);
    uint32_t sAhi = sb, sAlo = sb + 16384, sBhi = sb + 32768, sBlo = sb + 49152;

    int tid = threadIdx.x, lane = tid & 31, wid = tid >> 5;
    int wm = wid & 3, wn = wid >> 2;
    const float* Ab = A + (size_t)blockIdx.y * 128 * K;
    const float* Bb = Bw + (size_t)blockIdx.x * 128 * K;

    float acc[2][8][4];
#pragma unroll
    for (int mt = 0; mt < 2; mt++)
#pragma unroll
        for (int nt = 0; nt < 8; nt++)
#pragma unroll
            for (int q = 0; q < 4; q++) acc[mt][nt][q] = 0.f;

    int aRowL = (lane & 7) + ((lane >> 3) & 1) * 8;
    int aK8 = (lane >> 4);
    int bRowL = ((lane >> 4) & 1) * 8 + (lane & 7);
    int bK8 = (lane >> 3) & 1;
    int rsub = tid >> 4, c4 = tid & 15;

    for (int kc = 0; kc < K; kc += 64) {
#pragma unroll
        for (int i = 0; i < 8; i++) {
            int row = rsub + i * 16;
            uint32_t off = (uint32_t)(row * 128 + ((c4 * 8) ^ ((row & 7) << 4)));
            float4 va = *(const float4*)(Ab + (size_t)row * K + kc + c4 * 4);
            uint2 hi, lo; bsplit(va, hi, lo);
            *(uint2*)(hsm + (sAhi - sb) + off) = hi;
            *(uint2*)(hsm + (sAlo - sb) + off) = lo;
            float4 vb = *(const float4*)(Bb + (size_t)row * K + kc + c4 * 4);
            bsplit(vb, hi, lo);
            *(uint2*)(hsm + (sBhi - sb) + off) = hi;
            *(uint2*)(hsm + (sBlo - sb) + off) = lo;
        }
        __syncthreads();
#pragma unroll
        for (int k16 = 0; k16 < 4; k16++) {
            int ku = k16 * 2;
            uint32_t ah[2][4], al[2][4];
#pragma unroll
            for (int mt = 0; mt < 2; mt++) {
                int row = wm * 32 + mt * 16 + aRowL;
                uint32_t off = (uint32_t)(row * 128 + (((ku + aK8) * 16) ^ ((row & 7) << 4)));
                ldsm4(ah[mt], sAhi + off);
                ldsm4(al[mt], sAlo + off);
            }
#pragma unroll
            for (int ntp = 0; ntp < 4; ntp++) {
                int row = wn * 64 + ntp * 16 + bRowL;
                uint32_t off = (uint32_t)(row * 128 + (((ku + bK8) * 16) ^ ((row & 7) << 4)));
                uint32_t bh[4], bl[4];
                ldsm4(bh, sBhi + off);
                ldsm4(bl, sBlo + off);
#pragma unroll
                for (int h = 0; h < 2; h++) {
                    int nt = ntp * 2 + h;
#pragma unroll
                    for (int mt = 0; mt < 2; mt++) {
                        mma16816(acc[mt][nt], ah[mt], bh + h * 2);
                        mma16816(acc[mt][nt], al[mt], bh + h * 2);
                        mma16816(acc[mt][nt], ah[mt], bl + h * 2);
                    }
                }
            }
        }
        __syncthreads();
    }

    int r0 = lane >> 2, c0 = (lane & 3) * 2;
#pragma unroll
    for (int mt = 0; mt < 2; mt++)
#pragma unroll
        for (int nt = 0; nt < 8; nt++) {
            int m = blockIdx.y * 128 + wm * 32 + mt * 16 + r0;
            int n = blockIdx.x * 128 + wn * 64 + nt * 8 + c0;
            float2 v0 = make_float2(acc[mt][nt][0], acc[mt][nt][1]);
            float2 v1 = make_float2(acc[mt][nt][2], acc[mt][nt][3]);
            if (EPI) {
                float b0 = bias[n], b1 = bias[n + 1];
                v0.x = tanhf(v0.x + b0); v0.y = tanhf(v0.y + b1);
                v1.x = tanhf(v1.x + b0); v1.y = tanhf(v1.y + b1);
            }
            *(float2*)(C + (size_t)m * N + n) = v0;
            *(float2*)(C + (size_t)(m + 8) * N + n) = v1;
        }
}

// ---------------- LN over vocab table + init ----------------
__global__ void ln_k(const float* __restrict__ gA, const float* __restrict__ beA,
                     const float* __restrict__ bA, const float* __restrict__ gB,
                     const float* __restrict__ beB, const float* __restrict__ bB)
{
    int row = blockIdx.x, tid = threadIdx.x;
    if (row < 512) {
        // zero g_hbf (4*2*16384 bf16 = 65536 floats = 512*128)
        ((float*)g_hbf)[row * 128 + tid] = 0.f;
    } else if (row == 512) {
        for (int q = 0; q < 12; q++) ((float*)g_stats)[q * 128 + tid] = 0.f;
        if (tid < 4) { g_ctrS[tid] = 0u; g_ctrH[tid] = 0u; }
    }
    int dir = row >= NV * 3;
    int rem = dir ? row - NV * 3 : row;
    int tok = rem / 3, gate = rem - tok * 3;
    float* p = (dir ? g_Wp1 : g_Wp0) + (size_t)tok * NH3 + gate * NH;
    const float* gg = (dir ? gB : gA) + gate * NH;
    const float* be = (dir ? beB : beA) + gate * NH;
    const float* bi = (dir ? bB : bA) + gate * NH;
    float4 v = ((float4*)p)[tid];
    if (tok == 0) { v.x = 0.f; v.y = 0.f; v.z = 0.f; v.w = 0.f; }
    float sum = v.x + v.y + v.z + v.w;
    float sq = v.x * v.x + v.y * v.y + v.z * v.z + v.w * v.w;
#pragma unroll
    for (int o = 16; o; o >>= 1) {
        sum += __shfl_xor_sync(0xffffffffu, sum, o);
        sq  += __shfl_xor_sync(0xffffffffu, sq, o);
    }
    __shared__ float ss[4], sc[4];
    int w = tid >> 5;
    if ((tid & 31) == 0) { ss[w] = sum; sc[w] = sq; }
    __syncthreads();
    sum = ss[0] + ss[1] + ss[2] + ss[3];
    sq  = sc[0] + sc[1] + sc[2] + sc[3];
    float mu = sum * (1.f / NH);
    float rs = rsqrtf(sq * (1.f / NH) - mu * mu + 1e-5f);
    int j = tid * 4;
    v.x = (v.x - mu) * rs * gg[j]     + be[j]     + bi[j];
    v.y = (v.y - mu) * rs * gg[j + 1] + be[j + 1] + bi[j + 1];
    v.z = (v.z - mu) * rs * gg[j + 2] + be[j + 2] + bi[j + 2];
    v.w = (v.w - mu) * rs * gg[j + 3] + be[j + 3] + bi[j + 3];
    ((float4*)p)[tid] = v;
}

// ----------------------------------------------------------------------------
// Persistent recurrence: h carried in registers; bf16 hi/lo planes published
// by phase 2 (producer-side conversion); staging is a pure swizzled copy.
// ----------------------------------------------------------------------------
__global__ void __launch_bounds__(REC_THREADS, 1) gru_rec(
    const int* __restrict__ src,
    const float* __restrict__ Whh_f, const float* __restrict__ Whh_b,
    const float* __restrict__ ghh_f, const float* __restrict__ behh_f,
    const float* __restrict__ bhh_f, const float* __restrict__ ghh_b,
    const float* __restrict__ behh_b, const float* __restrict__ bhh_b,
    float* __restrict__ dout)
{
    extern __shared__ __align__(16) char smraw[];
    uint32_t sb0 = smem_u32(smraw);
    uint32_t sb = (sb0 + 1023) & ~1023u;
    char* basep = smraw + (sb - sb0);
    float* Pbuf = (float*)(basep + OFF_P);
    float* hpsp = (float*)(basep + OFF_HPS);

    int grp = blockIdx.x >> 5, cid = blockIdx.x & 31;
    int dir = grp >> 1, bh = grp & 1;
    int tid = threadIdx.x, lane = tid & 31, wid = tid >> 5;
    int jbase = cid * JS;

    const float* Whh  = dir ? Whh_b  : Whh_f;
    const float* ghh  = dir ? ghh_b  : ghh_f;
    const float* behh = dir ? behh_b : behh_f;
    const float* bhh  = dir ? bhh_b  : bhh_f;
    const float* Wp   = dir ? g_Wp1  : g_Wp0;
    const uint4* hbhi = (const uint4*)g_hbf[grp][0];
    const uint4* hblo = (const uint4*)g_hbf[grp][1];
    unsigned* ctrS = &g_ctrS[grp];
    unsigned* ctrH = &g_ctrH[grp];

    // one-time: W -> bf16 hi/lo swizzled tiles
    for (int idx = tid; idx < NROW * 128; idx += REC_THREADS) {
        int r = idx >> 7, k4 = idx & 127;
        int grow = (r >> 4) * NH + jbase + (r & 15);
        float4 v = *(const float4*)(Whh + (size_t)grow * NH + k4 * 4);
        uint2 hi, lo; bsplit(v, hi, lo);
        uint32_t off = tile_off(r, k4);
        *(uint2*)(basep + OFF_WHI + off) = hi;
        *(uint2*)(basep + OFF_WLO + off) = lo;
    }

    int kh = wid / 6;
    int sp = wid % 6;
    bool t3 = sp >= 4;
    int mrowbase = t3 ? 0 : (sp >> 1) * 32;
    int ntb = t3 ? (sp - 4) * 24 : (sp & 1) * 24;
    int prow = t3 ? 64 : (sp >> 1) * 32;
    int khb = kh * 256;
    int aRow0 = mrowbase + (lane & 7) + ((lane >> 3) & 1) * 8;
    int aKoff = (lane >> 4) * 8;
    uint32_t swzl = (uint32_t)((lane & 7) << 4);
    uint32_t aBase0 = sb + OFF_A + aRow0 * 1024;
    uint32_t wTile = sb + (t3 ? OFF_WLO : OFF_WHI);
    int bKoff = ((lane >> 3) & 1) * 8;
    uint32_t bBase[3];
#pragma unroll
    for (int nt = 0; nt < 3; nt++)
        bBase[nt] = wTile + (ntb + nt * 8 + (lane & 7)) * 1024;

    int pb = tid >> 4, jl = tid & 15;
    float cg[3], cbe[3], cbb[3];
#pragma unroll
    for (int g = 0; g < 3; g++) {
        int j = g * NH + jbase + jl;
        cg[g] = ghh[j]; cbe[g] = behh[j]; cbb[g] = bhh[j];
    }
    float xv[3];
    {
        int s0 = dir ? (NS - 1) : 0;
        int tok = __ldg(src + s0 * NB + bh * NGB + pb);
        const float* xrow = Wp + (size_t)tok * NH3;
#pragma unroll
        for (int g = 0; g < 3; g++) xv[g] = __ldg(xrow + g * NH + jbase + jl);
    }
    float hprev = 0.f;   // register-carried h for (pb, jl)
    __syncthreads();

    for (int t = 0; t < NS; t++) {
        int s = dir ? (NS - 1 - t) : t;
        int par = t & 1;

        if (t > 0) bar_wait(ctrH, (unsigned)(NCG * t));

        // stage bf16 planes -> A tile (pure swizzled copy, 16B units)
#pragma unroll
        for (int i = 0; i < 8; i++) {
            int idx = tid + i * REC_THREADS;       // 0..4095
            int row = idx >> 6, u = idx & 63;
            const uint4* srcp = (row < 32) ? hbhi : hblo;
            uint4 v = srcp[(row & 31) * 64 + u];
            *(uint4*)(basep + OFF_A + row * 1024 + ((u * 16) ^ ((row & 7) << 4))) = v;
        }
        __syncthreads();

        if (wid < 12) {
            float acc[2][3][4];
#pragma unroll
            for (int mt = 0; mt < 2; mt++)
#pragma unroll
                for (int nt = 0; nt < 3; nt++)
#pragma unroll
                    for (int q = 0; q < 4; q++) acc[mt][nt][q] = 0.f;
#pragma unroll 2
            for (int kc = 0; kc < 16; kc++) {
                int kb = khb + kc * 16;
                uint32_t a0[4], a1[4];
                uint32_t ad = aBase0 + ((uint32_t)((kb + aKoff) * 2) ^ swzl);
                ldsm4(a0, ad);
                ldsm4(a1, ad + 16 * 1024);
                uint32_t bf[3][2];
                uint32_t bko = (uint32_t)((kb + bKoff) * 2) ^ swzl;
#pragma unroll
                for (int nt = 0; nt < 3; nt++) ldsm2(bf[nt], bBase[nt] + bko);
#pragma unroll
                for (int nt = 0; nt < 3; nt++) {
                    mma16816(acc[0][nt], a0, bf[nt]);
                    mma16816(acc[1][nt], a1, bf[nt]);
                }
            }
            float* P = Pbuf + kh * (96 * 50);
            int r0 = lane >> 2, c0 = (lane & 3) * 2;
#pragma unroll
            for (int mt = 0; mt < 2; mt++)
#pragma unroll
                for (int nt = 0; nt < 3; nt++) {
                    float* rp = P + (prow + mt * 16 + r0) * 50 + ntb + nt * 8 + c0;
                    *(float2*)rp = make_float2(acc[mt][nt][0], acc[mt][nt][1]);
                    *(float2*)(rp + 8 * 50) = make_float2(acc[mt][nt][2], acc[mt][nt][3]);
                }
        }
        __syncthreads();

#pragma unroll
        for (int i = 0; i < 3; i++) {
            int e = tid + i * REC_THREADS;
            int b = e / 48, r = e - b * 48;
            const float* P0 = Pbuf + b * 50 + r;
            const float* P1 = P0 + 96 * 50;
            float v = P0[0] + P0[32 * 50] + P0[64 * 50]
                    + P1[0] + P1[32 * 50] + P1[64 * 50];
            hpsp[b * 52 + r] = v;
        }
        __syncthreads();

        if (tid < 96) {
            int g = tid >> 5, b = tid & 31;
            float sv = 0.f, sq = 0.f;
#pragma unroll
            for (int q = 0; q < 16; q++) {
                float v = hpsp[b * 52 + g * 16 + q];
                sv += v; sq += v * v;
            }
            float* st = &g_stats[par][grp][b * 6 + g * 2];
            atomicAdd(st, sv);
            atomicAdd(st + 1, sq);
        }
        bar_arrive(ctrS);

        float xn[3];
        if (t + 1 < NS) {
            int sn = dir ? (NS - 2 - t) : (t + 1);
            int tok = __ldg(src + sn * NB + bh * NGB + pb);
            const float* xrow = Wp + (size_t)tok * NH3;
#pragma unroll
            for (int g = 0; g < 3; g++) xn[g] = __ldg(xrow + g * NH + jbase + jl);
        }

        bar_wait(ctrS, (unsigned)(NCG * (t + 1)));

        float hnew;
        {
            const float* st = &g_stats[par][grp][pb * 6];
            float mu0 = st[0] * (1.f / NH);
            float rs0 = rsqrtf(st[1] * (1.f / NH) - mu0 * mu0 + 1e-5f);
            float mu1 = st[2] * (1.f / NH);
            float rs1 = rsqrtf(st[3] * (1.f / NH) - mu1 * mu1 + 1e-5f);
            float mu2 = st[4] * (1.f / NH);
            float rs2 = rsqrtf(st[5] * (1.f / NH) - mu2 * mu2 + 1e-5f);
            float hr = (hpsp[pb * 52 + jl]      - mu0) * rs0 * cg[0] + cbe[0] + cbb[0];
            float hz = (hpsp[pb * 52 + 16 + jl] - mu1) * rs1 * cg[1] + cbe[1] + cbb[1];
            float hn = (hpsp[pb * 52 + 32 + jl] - mu2) * rs2 * cg[2] + cbe[2] + cbb[2];
            float r = 1.f / (1.f + __expf(-(xv[0] + hr)));
            float z = 1.f / (1.f + __expf(-(xv[1] + hz)));
            float n = tanhf(xv[2] + r * hn);
            hnew = (1.f - z) * n + z * hprev;
            hprev = hnew;
            // publish bf16 hi/lo (producer-side split; one conversion chip-wide)
            __nv_bfloat16 hi = __float2bfloat16_rn(hnew);
            __nv_bfloat16 lo = __float2bfloat16_rn(hnew - __bfloat162float(hi));
            g_hbf[grp][0][pb * NH + jbase + jl] = hi;
            g_hbf[grp][1][pb * NH + jbase + jl] = lo;
        }
        if (tid < 6) g_stats[par ^ 1][grp][cid * 6 + tid] = 0.f;
        bar_arrive(ctrH);

        {
            int j = jbase + jl;
            int bglob = bh * NGB + pb;
            g_gru[((size_t)s * NB + bglob) * (2 * NH) + dir * NH + j] = hnew;
            if (t == NS - 1)
                dout[(size_t)NS * NB * NH + (size_t)dir * NB * NH + bglob * NH + j] = hnew;
        }
        xv[0] = xn[0]; xv[1] = xn[1]; xv[2] = xn[2];
    }
}

// ---------------- launch ----------------
extern "C" void kernel_launch(void* const* d_in, const int* in_sizes, int n_in,
                              void* d_out, int out_size) {
    (void)in_sizes; (void)n_in; (void)out_size;
    const int*   src    = (const int*)  d_in[0];
    const float* emb    = (const float*)d_in[1];
    const float* W_ih_f = (const float*)d_in[2];
    const float* W_hh_f = (const float*)d_in[3];
    const float* b_ih_f = (const float*)d_in[4];
    const float* bhh_f  = (const float*)d_in[5];
    const float* gih_f  = (const float*)d_in[6];
    const float* beih_f = (const float*)d_in[7];
    const float* ghh_f  = (const float*)d_in[8];
    const float* behh_f = (const float*)d_in[9];
    const float* W_ih_b = (const float*)d_in[10];
    const float* W_hh_b = (const float*)d_in[11];
    const float* b_ih_b = (const float*)d_in[12];
    const float* bhh_b  = (const float*)d_in[13];
    const float* gih_b  = (const float*)d_in[14];
    const float* beih_b = (const float*)d_in[15];
    const float* ghh_b  = (const float*)d_in[16];
    const float* behh_b = (const float*)d_in[17];
    const float* W_out  = (const float*)d_in[18];
    const float* b_out  = (const float*)d_in[19];
    float* out = (float*)d_out;

    void *pWp0, *pWp1, *pGru;
    cudaGetSymbolAddress(&pWp0, g_Wp0);
    cudaGetSymbolAddress(&pWp1, g_Wp1);
    cudaGetSymbolAddress(&pGru, g_gru);
    cudaFuncSetAttribute(gru_rec, cudaFuncAttributeMaxDynamicSharedMemorySize,
                         REC_SMEM_BYTES);
    cudaFuncSetAttribute(hgemm_nt<0>, cudaFuncAttributeMaxDynamicSharedMemorySize,
                         HG_SMEM);
    cudaFuncSetAttribute(hgemm_nt<1>, cudaFuncAttributeMaxDynamicSharedMemorySize,
                         HG_SMEM);

    hgemm_nt<0><<<dim3(NH3 / 128, NV / 128), 256, HG_SMEM>>>(
        emb, W_ih_f, (float*)pWp0, NV, NH3, NE, nullptr);
    hgemm_nt<0><<<dim3(NH3 / 128, NV / 128), 256, HG_SMEM>>>(
        emb, W_ih_b, (float*)pWp1, NV, NH3, NE, nullptr);

    ln_k<<<2 * NV * 3, 128>>>(gih_f, beih_f, b_ih_f, gih_b, beih_b, b_ih_b);

    gru_rec<<<128, REC_THREADS, REC_SMEM_BYTES>>>(
        src, W_hh_f, W_hh_b, ghh_f, behh_f, bhh_f, ghh_b, behh_b, bhh_b, out);

    hgemm_nt<1><<<dim3(NH / 128, (NS * NB) / 128), 256, HG_SMEM>>>(
        (const float*)pGru, W_out, out, NS * NB, NH, 2 * NH, b_out);
}

// round 14
// speedup vs baseline: 3.1559x; 1.0068x over previous
#include <cuda_runtime.h>
#include <cuda_bf16.h>
#include <math.h>
#include <stdint.h>

constexpr int NS = 1024, NB = 64, NE = 512, NH = 512, NH3 = 1536, NV = 32000;
constexpr int NCG = 32, NGB = 32, JS = 16, NROW = 48, REC_THREADS = 512;

// gru_rec smem byte offsets (from 1024-aligned base)
constexpr int OFF_A   = 0;        // A tile: 64 x 512 bf16 (row stride 1024B)
constexpr int OFF_WHI = 65536;
constexpr int OFF_WLO = 114688;
constexpr int OFF_P   = 163840;   // partials [2][96][50] f32
constexpr int OFF_HPS = 202240;   // hp [32][52] f32 (6656B)
constexpr int OFF_SST = 208896;   // reduced stats [192] f32
constexpr int REC_SMEM_BYTES = 208896 + 768 + 1024;

// hgemm smem: 4 tiles of [128 rows][64 k] bf16 (16KB each)
constexpr int HG_SMEM = 65536;

// ---------------- warp mma / ldmatrix (base PTX, sm_80+) ----------------
__device__ __forceinline__ uint32_t smem_u32(const void* p) {
    uint32_t a;
    asm("{ .reg .u64 t; cvta.to.shared.u64 t, %1; cvt.u32.u64 %0, t; }" : "=r"(a) : "l"(p));
    return a;
}
__device__ __forceinline__ void ldsm4(uint32_t* r, uint32_t addr) {
    asm volatile("ldmatrix.sync.aligned.m8n8.x4.shared.b16 {%0,%1,%2,%3}, [%4];"
        : "=r"(r[0]), "=r"(r[1]), "=r"(r[2]), "=r"(r[3]) : "r"(addr));
}
__device__ __forceinline__ void ldsm2(uint32_t* r, uint32_t addr) {
    asm volatile("ldmatrix.sync.aligned.m8n8.x2.shared.b16 {%0,%1}, [%2];"
        : "=r"(r[0]), "=r"(r[1]) : "r"(addr));
}
__device__ __forceinline__ void mma16816(float* d, const uint32_t* a, const uint32_t* b) {
    asm volatile("mma.sync.aligned.m16n8k16.row.col.f32.bf16.bf16.f32 "
        "{%0,%1,%2,%3}, {%4,%5,%6,%7}, {%8,%9}, {%0,%1,%2,%3};"
        : "+f"(d[0]), "+f"(d[1]), "+f"(d[2]), "+f"(d[3])
        : "r"(a[0]), "r"(a[1]), "r"(a[2]), "r"(a[3]), "r"(b[0]), "r"(b[1]));
}
// swizzled byte offset, row stride 1024B (gru tiles), k4 = 8B unit
__device__ __forceinline__ uint32_t tile_off(int row, int k4) {
    return (uint32_t)(row * 1024 + ((k4 * 8) ^ ((row & 7) << 4)));
}
__device__ __forceinline__ void bsplit(float4 v, uint2& hi, uint2& lo) {
    __nv_bfloat16 a = __float2bfloat16_rn(v.x), b = __float2bfloat16_rn(v.y),
                  c = __float2bfloat16_rn(v.z), d = __float2bfloat16_rn(v.w);
    __nv_bfloat162 h0 = __halves2bfloat162(a, b), h1 = __halves2bfloat162(c, d);
    hi.x = *(uint32_t*)&h0; hi.y = *(uint32_t*)&h1;
    __nv_bfloat162 l0 = __floats2bfloat162_rn(v.x - __bfloat162float(a), v.y - __bfloat162float(b));
    __nv_bfloat162 l1 = __floats2bfloat162_rn(v.z - __bfloat162float(c), v.w - __bfloat162float(d));
    lo.x = *(uint32_t*)&l0; lo.y = *(uint32_t*)&l1;
}

// ---------------- device scratch ----------------
__device__ float g_Wp0[(size_t)NV * NH3];
__device__ float g_Wp1[(size_t)NV * NH3];
__device__ float g_gru[(size_t)NS * NB * 2 * NH];
__device__ __nv_bfloat16 g_hbf[4][2][NGB * NH];   // [group][hi/lo][b*512+k]
__device__ float g_pst[4][NCG][192];              // per-CTA LN stat partials
__device__ unsigned g_ctrS[4];
__device__ unsigned g_ctrH[4];

__device__ __forceinline__ void bar_arrive(unsigned* c) {
    __syncthreads();
    if (threadIdx.x == 0)
        asm volatile("red.release.gpu.global.add.u32 [%0], 1;" :: "l"(c) : "memory");
}
__device__ __forceinline__ void bar_wait(unsigned* c, unsigned tgt) {
    if (threadIdx.x == 0) {
        unsigned v;
        do { asm volatile("ld.acquire.gpu.global.u32 %0, [%1];" : "=r"(v) : "l"(c) : "memory"); }
        while (v < tgt);
    }
    __syncthreads();
}

// ----------------------------------------------------------------------------
// hgemm_nt (UNCHANGED): bf16-split mma GEMM.
// ----------------------------------------------------------------------------
template <int EPI>
__global__ void __launch_bounds__(256, 2) hgemm_nt(
    const float* __restrict__ A, const float* __restrict__ Bw,
    float* __restrict__ C, int M, int N, int K, const float* __restrict__ bias)
{
    extern __shared__ __align__(1024) char hsm[];
    uint32_t sb = smem_u32(hsm);
    uint32_t sAhi = sb, sAlo = sb + 16384, sBhi = sb + 32768, sBlo = sb + 49152;

    int tid = threadIdx.x, lane = tid & 31, wid = tid >> 5;
    int wm = wid & 3, wn = wid >> 2;
    const float* Ab = A + (size_t)blockIdx.y * 128 * K;
    const float* Bb = Bw + (size_t)blockIdx.x * 128 * K;

    float acc[2][8][4];
#pragma unroll
    for (int mt = 0; mt < 2; mt++)
#pragma unroll
        for (int nt = 0; nt < 8; nt++)
#pragma unroll
            for (int q = 0; q < 4; q++) acc[mt][nt][q] = 0.f;

    int aRowL = (lane & 7) + ((lane >> 3) & 1) * 8;
    int aK8 = (lane >> 4);
    int bRowL = ((lane >> 4) & 1) * 8 + (lane & 7);
    int bK8 = (lane >> 3) & 1;
    int rsub = tid >> 4, c4 = tid & 15;

    for (int kc = 0; kc < K; kc += 64) {
#pragma unroll
        for (int i = 0; i < 8; i++) {
            int row = rsub + i * 16;
            uint32_t off = (uint32_t)(row * 128 + ((c4 * 8) ^ ((row & 7) << 4)));
            float4 va = *(const float4*)(Ab + (size_t)row * K + kc + c4 * 4);
            uint2 hi, lo; bsplit(va, hi, lo);
            *(uint2*)(hsm + (sAhi - sb) + off) = hi;
            *(uint2*)(hsm + (sAlo - sb) + off) = lo;
            float4 vb = *(const float4*)(Bb + (size_t)row * K + kc + c4 * 4);
            bsplit(vb, hi, lo);
            *(uint2*)(hsm + (sBhi - sb) + off) = hi;
            *(uint2*)(hsm + (sBlo - sb) + off) = lo;
        }
        __syncthreads();
#pragma unroll
        for (int k16 = 0; k16 < 4; k16++) {
            int ku = k16 * 2;
            uint32_t ah[2][4], al[2][4];
#pragma unroll
            for (int mt = 0; mt < 2; mt++) {
                int row = wm * 32 + mt * 16 + aRowL;
                uint32_t off = (uint32_t)(row * 128 + (((ku + aK8) * 16) ^ ((row & 7) << 4)));
                ldsm4(ah[mt], sAhi + off);
                ldsm4(al[mt], sAlo + off);
            }
#pragma unroll
            for (int ntp = 0; ntp < 4; ntp++) {
                int row = wn * 64 + ntp * 16 + bRowL;
                uint32_t off = (uint32_t)(row * 128 + (((ku + bK8) * 16) ^ ((row & 7) << 4)));
                uint32_t bh[4], bl[4];
                ldsm4(bh, sBhi + off);
                ldsm4(bl, sBlo + off);
#pragma unroll
                for (int h = 0; h < 2; h++) {
                    int nt = ntp * 2 + h;
#pragma unroll
                    for (int mt = 0; mt < 2; mt++) {
                        mma16816(acc[mt][nt], ah[mt], bh + h * 2);
                        mma16816(acc[mt][nt], al[mt], bh + h * 2);
                        mma16816(acc[mt][nt], ah[mt], bl + h * 2);
                    }
                }
            }
        }
        __syncthreads();
    }

    int r0 = lane >> 2, c0 = (lane & 3) * 2;
#pragma unroll
    for (int mt = 0; mt < 2; mt++)
#pragma unroll
        for (int nt = 0; nt < 8; nt++) {
            int m = blockIdx.y * 128 + wm * 32 + mt * 16 + r0;
            int n = blockIdx.x * 128 + wn * 64 + nt * 8 + c0;
            float2 v0 = make_float2(acc[mt][nt][0], acc[mt][nt][1]);
            float2 v1 = make_float2(acc[mt][nt][2], acc[mt][nt][3]);
            if (EPI) {
                float b0 = bias[n], b1 = bias[n + 1];
                v0.x = tanhf(v0.x + b0); v0.y = tanhf(v0.y + b1);
                v1.x = tanhf(v1.x + b0); v1.y = tanhf(v1.y + b1);
            }
            *(float2*)(C + (size_t)m * N + n) = v0;
            *(float2*)(C + (size_t)(m + 8) * N + n) = v1;
        }
}

// ---------------- LN over vocab table + init ----------------
__global__ void ln_k(const float* __restrict__ gA, const float* __restrict__ beA,
                     const float* __restrict__ bA, const float* __restrict__ gB,
                     const float* __restrict__ beB, const float* __restrict__ bB)
{
    int row = blockIdx.x, tid = threadIdx.x;
    if (row < 512) {
        // zero g_hbf (4*2*16384 bf16 = 65536 floats = 512*128)
        ((float*)g_hbf)[row * 128 + tid] = 0.f;
    } else if (row == 512) {
        if (tid < 4) { g_ctrS[tid] = 0u; g_ctrH[tid] = 0u; }
    }
    int dir = row >= NV * 3;
    int rem = dir ? row - NV * 3 : row;
    int tok = rem / 3, gate = rem - tok * 3;
    float* p = (dir ? g_Wp1 : g_Wp0) + (size_t)tok * NH3 + gate * NH;
    const float* gg = (dir ? gB : gA) + gate * NH;
    const float* be = (dir ? beB : beA) + gate * NH;
    const float* bi = (dir ? bB : bA) + gate * NH;
    float4 v = ((float4*)p)[tid];
    if (tok == 0) { v.x = 0.f; v.y = 0.f; v.z = 0.f; v.w = 0.f; }
    float sum = v.x + v.y + v.z + v.w;
    float sq = v.x * v.x + v.y * v.y + v.z * v.z + v.w * v.w;
#pragma unroll
    for (int o = 16; o; o >>= 1) {
        sum += __shfl_xor_sync(0xffffffffu, sum, o);
        sq  += __shfl_xor_sync(0xffffffffu, sq, o);
    }
    __shared__ float ss[4], sc[4];
    int w = tid >> 5;
    if ((tid & 31) == 0) { ss[w] = sum; sc[w] = sq; }
    __syncthreads();
    sum = ss[0] + ss[1] + ss[2] + ss[3];
    sq  = sc[0] + sc[1] + sc[2] + sc[3];
    float mu = sum * (1.f / NH);
    float rs = rsqrtf(sq * (1.f / NH) - mu * mu + 1e-5f);
    int j = tid * 4;
    v.x = (v.x - mu) * rs * gg[j]     + be[j]     + bi[j];
    v.y = (v.y - mu) * rs * gg[j + 1] + be[j + 1] + bi[j + 1];
    v.z = (v.z - mu) * rs * gg[j + 2] + be[j + 2] + bi[j + 2];
    v.w = (v.w - mu) * rs * gg[j + 3] + be[j + 3] + bi[j + 3];
    ((float4*)p)[tid] = v;
}

// ----------------------------------------------------------------------------
// Persistent recurrence: register-carried h, producer-side bf16 publish,
// contention-free LN stats (per-CTA slots + reader-side reduce into smem),
// x(t+1) prefetched to L2 at step top.
// ----------------------------------------------------------------------------
__global__ void __launch_bounds__(REC_THREADS, 1) gru_rec(
    const int* __restrict__ src,
    const float* __restrict__ Whh_f, const float* __restrict__ Whh_b,
    const float* __restrict__ ghh_f, const float* __restrict__ behh_f,
    const float* __restrict__ bhh_f, const float* __restrict__ ghh_b,
    const float* __restrict__ behh_b, const float* __restrict__ bhh_b,
    float* __restrict__ dout)
{
    extern __shared__ __align__(16) char smraw[];
    uint32_t sb0 = smem_u32(smraw);
    uint32_t sb = (sb0 + 1023) & ~1023u;
    char* basep = smraw + (sb - sb0);
    float* Pbuf = (float*)(basep + OFF_P);
    float* hpsp = (float*)(basep + OFF_HPS);
    float* sstat = (float*)(basep + OFF_SST);

    int grp = blockIdx.x >> 5, cid = blockIdx.x & 31;
    int dir = grp >> 1, bh = grp & 1;
    int tid = threadIdx.x, lane = tid & 31, wid = tid >> 5;
    int jbase = cid * JS;

    const float* Whh  = dir ? Whh_b  : Whh_f;
    const float* ghh  = dir ? ghh_b  : ghh_f;
    const float* behh = dir ? behh_b : behh_f;
    const float* bhh  = dir ? bhh_b  : bhh_f;
    const float* Wp   = dir ? g_Wp1  : g_Wp0;
    const uint4* hbhi = (const uint4*)g_hbf[grp][0];
    const uint4* hblo = (const uint4*)g_hbf[grp][1];
    unsigned* ctrS = &g_ctrS[grp];
    unsigned* ctrH = &g_ctrH[grp];

    // one-time: W -> bf16 hi/lo swizzled tiles
    for (int idx = tid; idx < NROW * 128; idx += REC_THREADS) {
        int r = idx >> 7, k4 = idx & 127;
        int grow = (r >> 4) * NH + jbase + (r & 15);
        float4 v = *(const float4*)(Whh + (size_t)grow * NH + k4 * 4);
        uint2 hi, lo; bsplit(v, hi, lo);
        uint32_t off = tile_off(r, k4);
        *(uint2*)(basep + OFF_WHI + off) = hi;
        *(uint2*)(basep + OFF_WLO + off) = lo;
    }

    int kh = wid / 6;
    int sp = wid % 6;
    bool t3 = sp >= 4;
    int mrowbase = t3 ? 0 : (sp >> 1) * 32;
    int ntb = t3 ? (sp - 4) * 24 : (sp & 1) * 24;
    int prow = t3 ? 64 : (sp >> 1) * 32;
    int khb = kh * 256;
    int aRow0 = mrowbase + (lane & 7) + ((lane >> 3) & 1) * 8;
    int aKoff = (lane >> 4) * 8;
    uint32_t swzl = (uint32_t)((lane & 7) << 4);
    uint32_t aBase0 = sb + OFF_A + aRow0 * 1024;
    uint32_t wTile = sb + (t3 ? OFF_WLO : OFF_WHI);
    int bKoff = ((lane >> 3) & 1) * 8;
    uint32_t bBase[3];
#pragma unroll
    for (int nt = 0; nt < 3; nt++)
        bBase[nt] = wTile + (ntb + nt * 8 + (lane & 7)) * 1024;

    int pb = tid >> 4, jl = tid & 15;
    float cg[3], cbe[3], cbb[3];
#pragma unroll
    for (int g = 0; g < 3; g++) {
        int j = g * NH + jbase + jl;
        cg[g] = ghh[j]; cbe[g] = behh[j]; cbb[g] = bhh[j];
    }
    float xv[3];
    {
        int s0 = dir ? (NS - 1) : 0;
        int tok = __ldg(src + s0 * NB + bh * NGB + pb);
        const float* xrow = Wp + (size_t)tok * NH3;
#pragma unroll
        for (int g = 0; g < 3; g++) xv[g] = __ldg(xrow + g * NH + jbase + jl);
    }
    float hprev = 0.f;
    __syncthreads();

    for (int t = 0; t < NS; t++) {
        int s = dir ? (NS - 1 - t) : t;

        if (t > 0) bar_wait(ctrH, (unsigned)(NCG * t));

        // L2-prefetch x(t+1) rows (addresses statically known)
        if (t + 1 < NS && (jl & 7) == 0) {
            int sn = dir ? (NS - 2 - t) : (t + 1);
            int tokp = __ldg(src + sn * NB + bh * NGB + pb);
            const float* xrp = Wp + (size_t)tokp * NH3 + jbase + jl;
#pragma unroll
            for (int g = 0; g < 3; g++)
                asm volatile("prefetch.global.L2 [%0];" :: "l"(xrp + g * NH));
        }

        // stage bf16 planes -> A tile (pure swizzled copy, 16B units)
#pragma unroll
        for (int i = 0; i < 8; i++) {
            int idx = tid + i * REC_THREADS;       // 0..4095
            int row = idx >> 6, u = idx & 63;
            const uint4* srcp = (row < 32) ? hbhi : hblo;
            uint4 v = srcp[(row & 31) * 64 + u];
            *(uint4*)(basep + OFF_A + row * 1024 + ((u * 16) ^ ((row & 7) << 4))) = v;
        }
        __syncthreads();

        if (wid < 12) {
            float acc[2][3][4];
#pragma unroll
            for (int mt = 0; mt < 2; mt++)
#pragma unroll
                for (int nt = 0; nt < 3; nt++)
#pragma unroll
                    for (int q = 0; q < 4; q++) acc[mt][nt][q] = 0.f;
#pragma unroll 4
            for (int kc = 0; kc < 16; kc++) {
                int kb = khb + kc * 16;
                uint32_t a0[4], a1[4];
                uint32_t ad = aBase0 + ((uint32_t)((kb + aKoff) * 2) ^ swzl);
                ldsm4(a0, ad);
                ldsm4(a1, ad + 16 * 1024);
                uint32_t bf[3][2];
                uint32_t bko = (uint32_t)((kb + bKoff) * 2) ^ swzl;
#pragma unroll
                for (int nt = 0; nt < 3; nt++) ldsm2(bf[nt], bBase[nt] + bko);
#pragma unroll
                for (int nt = 0; nt < 3; nt++) {
                    mma16816(acc[0][nt], a0, bf[nt]);
                    mma16816(acc[1][nt], a1, bf[nt]);
                }
            }
            float* P = Pbuf + kh * (96 * 50);
            int r0 = lane >> 2, c0 = (lane & 3) * 2;
#pragma unroll
            for (int mt = 0; mt < 2; mt++)
#pragma unroll
                for (int nt = 0; nt < 3; nt++) {
                    float* rp = P + (prow + mt * 16 + r0) * 50 + ntb + nt * 8 + c0;
                    *(float2*)rp = make_float2(acc[mt][nt][0], acc[mt][nt][1]);
                    *(float2*)(rp + 8 * 50) = make_float2(acc[mt][nt][2], acc[mt][nt][3]);
                }
        }
        __syncthreads();

#pragma unroll
        for (int i = 0; i < 3; i++) {
            int e = tid + i * REC_THREADS;
            int b = e / 48, r = e - b * 48;
            const float* P0 = Pbuf + b * 50 + r;
            const float* P1 = P0 + 96 * 50;
            float v = P0[0] + P0[32 * 50] + P0[64 * 50]
                    + P1[0] + P1[32 * 50] + P1[64 * 50];
            hpsp[b * 52 + r] = v;
        }
        __syncthreads();

        // LN partial stats -> private per-CTA slot (no atomics, no contention)
        if (tid < 96) {
            int g = tid >> 5, b = tid & 31;
            float sv = 0.f, sq = 0.f;
#pragma unroll
            for (int q = 0; q < 16; q++) {
                float v = hpsp[b * 52 + g * 16 + q];
                sv += v; sq += v * v;
            }
            *(float2*)&g_pst[grp][cid][b * 6 + g * 2] = make_float2(sv, sq);
        }
        bar_arrive(ctrS);

        // x(t+1) loads (hit L2 thanks to the step-top prefetch)
        float xn[3];
        if (t + 1 < NS) {
            int sn = dir ? (NS - 2 - t) : (t + 1);
            int tok = __ldg(src + sn * NB + bh * NGB + pb);
            const float* xrow = Wp + (size_t)tok * NH3;
#pragma unroll
            for (int g = 0; g < 3; g++) xn[g] = __ldg(xrow + g * NH + jbase + jl);
        }

        bar_wait(ctrS, (unsigned)(NCG * (t + 1)));

        // reduce stats across CTAs (192 threads, MLP-32 loads) -> smem broadcast
        if (tid < 192) {
            float v = 0.f;
#pragma unroll 8
            for (int c = 0; c < NCG; c++) v += g_pst[grp][c][tid];
            sstat[tid] = v;
        }
        __syncthreads();

        float hnew;
        {
            const float* st = sstat + pb * 6;
            float mu0 = st[0] * (1.f / NH);
            float rs0 = rsqrtf(st[1] * (1.f / NH) - mu0 * mu0 + 1e-5f);
            float mu1 = st[2] * (1.f / NH);
            float rs1 = rsqrtf(st[3] * (1.f / NH) - mu1 * mu1 + 1e-5f);
            float mu2 = st[4] * (1.f / NH);
            float rs2 = rsqrtf(st[5] * (1.f / NH) - mu2 * mu2 + 1e-5f);
            float hr = (hpsp[pb * 52 + jl]      - mu0) * rs0 * cg[0] + cbe[0] + cbb[0];
            float hz = (hpsp[pb * 52 + 16 + jl] - mu1) * rs1 * cg[1] + cbe[1] + cbb[1];
            float hn = (hpsp[pb * 52 + 32 + jl] - mu2) * rs2 * cg[2] + cbe[2] + cbb[2];
            float r = 1.f / (1.f + __expf(-(xv[0] + hr)));
            float z = 1.f / (1.f + __expf(-(xv[1] + hz)));
            float n = tanhf(xv[2] + r * hn);
            hnew = (1.f - z) * n + z * hprev;
            hprev = hnew;
            __nv_bfloat16 hi = __float2bfloat16_rn(hnew);
            __nv_bfloat16 lo = __float2bfloat16_rn(hnew - __bfloat162float(hi));
            g_hbf[grp][0][pb * NH + jbase + jl] = hi;
            g_hbf[grp][1][pb * NH + jbase + jl] = lo;
        }
        bar_arrive(ctrH);

        {
            int j = jbase + jl;
            int bglob = bh * NGB + pb;
            g_gru[((size_t)s * NB + bglob) * (2 * NH) + dir * NH + j] = hnew;
            if (t == NS - 1)
                dout[(size_t)NS * NB * NH + (size_t)dir * NB * NH + bglob * NH + j] = hnew;
        }
        xv[0] = xn[0]; xv[1] = xn[1]; xv[2] = xn[2];
    }
}

// ---------------- launch ----------------
extern "C" void kernel_launch(void* const* d_in, const int* in_sizes, int n_in,
                              void* d_out, int out_size) {
    (void)in_sizes; (void)n_in; (void)out_size;
    const int*   src    = (const int*)  d_in[0];
    const float* emb    = (const float*)d_in[1];
    const float* W_ih_f = (const float*)d_in[2];
    const float* W_hh_f = (const float*)d_in[3];
    const float* b_ih_f = (const float*)d_in[4];
    const float* bhh_f  = (const float*)d_in[5];
    const float* gih_f  = (const float*)d_in[6];
    const float* beih_f = (const float*)d_in[7];
    const float* ghh_f  = (const float*)d_in[8];
    const float* behh_f = (const float*)d_in[9];
    const float* W_ih_b = (const float*)d_in[10];
    const float* W_hh_b = (const float*)d_in[11];
    const float* b_ih_b = (const float*)d_in[12];
    const float* bhh_b  = (const float*)d_in[13];
    const float* gih_b  = (const float*)d_in[14];
    const float* beih_b = (const float*)d_in[15];
    const float* ghh_b  = (const float*)d_in[16];
    const float* behh_b = (const float*)d_in[17];
    const float* W_out  = (const float*)d_in[18];
    const float* b_out  = (const float*)d_in[19];
    float* out = (float*)d_out;

    void *pWp0, *pWp1, *pGru;
    cudaGetSymbolAddress(&pWp0, g_Wp0);
    cudaGetSymbolAddress(&pWp1, g_Wp1);
    cudaGetSymbolAddress(&pGru, g_gru);
    cudaFuncSetAttribute(gru_rec, cudaFuncAttributeMaxDynamicSharedMemorySize,
                         REC_SMEM_BYTES);
    cudaFuncSetAttribute(hgemm_nt<0>, cudaFuncAttributeMaxDynamicSharedMemorySize,
                         HG_SMEM);
    cudaFuncSetAttribute(hgemm_nt<1>, cudaFuncAttributeMaxDynamicSharedMemorySize,
                         HG_SMEM);

    hgemm_nt<0><<<dim3(NH3 / 128, NV / 128), 256, HG_SMEM>>>(
        emb, W_ih_f, (float*)pWp0, NV, NH3, NE, nullptr);
    hgemm_nt<0><<<dim3(NH3 / 128, NV / 128), 256, HG_SMEM>>>(
        emb, W_ih_b, (float*)pWp1, NV, NH3, NE, nullptr);

    ln_k<<<2 * NV * 3, 128>>>(gih_f, beih_f, b_ih_f, gih_b, beih_b, b_ih_b);

    gru_rec<<<128, REC_THREADS, REC_SMEM_BYTES>>>(
        src, W_hh_f, W_hh_b, ghh_f, behh_f, bhh_f, ghh_b, behh_b, bhh_b, out);

    hgemm_nt<1><<<dim3(NH / 128, (NS * NB) / 128), 256, HG_SMEM>>>(
        (const float*)pGru, W_out, out, NS * NB, NH, 2 * NH, b_out);
}